// round 1
// baseline (speedup 1.0000x reference)
#include <cuda_runtime.h>
#include <cuda_bf16.h>
#include <cstdint>

// Problem constants
#define BATCH 64
#define CH    64
#define HH    64
#define WW    64
#define NPOS  1024        // 32*32
#define KPIN  1134        // 42*27
#define KPOUT 1024
#define UP_ELEMS (BATCH*CH*HH*WW)          // 16777216
#define ATTN_ELEMS (BATCH*NPOS*NPOS)       // 67108864

// Scratch (device globals; no allocation)
__device__ float g_pv[BATCH * CH * NPOS];     // [b][c][n]
__device__ float g_out[BATCH * CH * NPOS];    // [b][c][m]
__device__ float g_q[BATCH * NPOS];
__device__ float g_k[BATCH * NPOS];
__device__ float g_kc[BATCH * KPIN];
__device__ float g_kmax[BATCH];
__device__ float g_kmin[BATCH];

__device__ __forceinline__ float ex2f(float x) {
    float y;
    asm("ex2.approx.ftz.f32 %0, %1;" : "=f"(y) : "f"(x));
    return y;
}
__device__ __forceinline__ unsigned long long pack2(float lo, float hi) {
    unsigned long long r;
    asm("mov.b64 %0, {%1, %2};" : "=l"(r) : "f"(lo), "f"(hi));
    return r;
}
__device__ __forceinline__ unsigned long long fma2(unsigned long long a,
                                                   unsigned long long b,
                                                   unsigned long long c) {
    unsigned long long d;
    asm("fma.rn.f32x2 %0, %1, %2, %3;" : "=l"(d) : "l"(a), "l"(b), "l"(c));
    return d;
}
__device__ __forceinline__ void unpack2(unsigned long long r, float& lo, float& hi) {
    asm("mov.b64 {%0, %1}, %2;" : "=f"(lo), "=f"(hi) : "l"(r));
}

// ---------------------------------------------------------------------------
// Kernel 1: conv2x2(v, wk) -> g_kc[b][ii*27+jj]
// grid (42, 64), 256 threads
// ---------------------------------------------------------------------------
__global__ __launch_bounds__(256) void conv_v_kernel(const float* __restrict__ v,
                                                     const float* __restrict__ wk,
                                                     const float* __restrict__ bk) {
    __shared__ float vs[64 * 2 * 54];   // 27648 B
    __shared__ float wks[256];
    int ii = blockIdx.x;
    int b  = blockIdx.y;
    int t  = threadIdx.x;

    wks[t] = wk[t];
    for (int idx = t; idx < 64 * 2 * 54; idx += 256) {
        int c   = idx / 108;
        int rem = idx - c * 108;
        int a   = rem / 54;
        int col = rem - a * 54;
        vs[idx] = v[((b * 64 + c) * 84 + (2 * ii + a)) * 54 + col];
    }
    __syncthreads();

    if (t < 27) {
        int jj = t;
        float acc = 0.f;
        for (int c = 0; c < 64; c++) {
            #pragma unroll
            for (int a = 0; a < 2; a++) {
                float x0 = vs[(c * 2 + a) * 54 + 2 * jj + 0];
                float x1 = vs[(c * 2 + a) * 54 + 2 * jj + 1];
                acc += x0 * wks[c * 4 + a * 2 + 0] + x1 * wks[c * 4 + a * 2 + 1];
            }
        }
        g_kc[b * KPIN + ii * 27 + jj] = acc + bk[0];
    }
}

// ---------------------------------------------------------------------------
// Kernel 2: k[b][m] = sum_j g_kc[b][j] * wproj[m][j] + bproj[m]
// grid 16 (m-tiles of 64), 256 threads
// ---------------------------------------------------------------------------
__global__ __launch_bounds__(256) void kproj_kernel(const float* __restrict__ wproj,
                                                    const float* __restrict__ bproj) {
    __shared__ float kcs[64 * 65];
    __shared__ float ws[64 * 65];
    int m0 = blockIdx.x * 64;
    int t  = threadIdx.x;
    int r  = t >> 4;       // 0..15 -> b group
    int cc = t & 15;       // 0..15 -> m group
    int b0 = r * 4;
    int mm0 = cc * 4;

    float acc[4][4];
    #pragma unroll
    for (int i = 0; i < 4; i++)
        #pragma unroll
        for (int j = 0; j < 4; j++) acc[i][j] = 0.f;

    for (int j0 = 0; j0 < KPIN; j0 += 64) {
        __syncthreads();
        for (int idx = t; idx < 4096; idx += 256) {
            int row = idx >> 6, jj = idx & 63;
            int j = j0 + jj;
            kcs[row * 65 + jj] = (j < KPIN) ? g_kc[row * KPIN + j] : 0.f;
            ws[row * 65 + jj]  = (j < KPIN) ? wproj[(m0 + row) * KPIN + j] : 0.f;
        }
        __syncthreads();
        #pragma unroll 4
        for (int jj = 0; jj < 64; jj++) {
            float kv[4], wv_[4];
            #pragma unroll
            for (int v_ = 0; v_ < 4; v_++) kv[v_] = kcs[(b0 + v_) * 65 + jj];
            #pragma unroll
            for (int u = 0; u < 4; u++) wv_[u] = ws[(mm0 + u) * 65 + jj];
            #pragma unroll
            for (int v_ = 0; v_ < 4; v_++)
                #pragma unroll
                for (int u = 0; u < 4; u++) acc[v_][u] += kv[v_] * wv_[u];
        }
    }
    #pragma unroll
    for (int v_ = 0; v_ < 4; v_++)
        #pragma unroll
        for (int u = 0; u < 4; u++) {
            int m = m0 + mm0 + u;
            g_k[(b0 + v_) * KPOUT + m] = acc[v_][u] + bproj[m];
        }
}

// ---------------------------------------------------------------------------
// Kernel 3: per-b max/min of k
// ---------------------------------------------------------------------------
__global__ __launch_bounds__(256) void kstats_kernel() {
    __shared__ float smax[256], smin[256];
    int b = blockIdx.x, t = threadIdx.x;
    float mx = -1e30f, mn = 1e30f;
    for (int n = t; n < NPOS; n += 256) {
        float kv = g_k[b * NPOS + n];
        mx = fmaxf(mx, kv);
        mn = fminf(mn, kv);
    }
    smax[t] = mx; smin[t] = mn;
    __syncthreads();
    for (int s = 128; s > 0; s >>= 1) {
        if (t < s) {
            smax[t] = fmaxf(smax[t], smax[t + s]);
            smin[t] = fminf(smin[t], smin[t + s]);
        }
        __syncthreads();
    }
    if (t == 0) { g_kmax[b] = smax[0]; g_kmin[b] = smin[0]; }
}

// ---------------------------------------------------------------------------
// Kernel 4: fused conv2x2 of x with wq (-> g_q) and wv (-> g_pv)
// grid (32, 64) = (i, b), 256 threads, dyn smem = 99840 B
// ---------------------------------------------------------------------------
__global__ __launch_bounds__(256) void conv_x_kernel(const float* __restrict__ x,
                                                     const float* __restrict__ wq,
                                                     const float* __restrict__ bq,
                                                     const float* __restrict__ wv,
                                                     const float* __restrict__ bv) {
    extern __shared__ float sm[];
    float* xs  = sm;            // [c*2+a][64] : 8192
    float* wvs = xs + 8192;     // [co][258 pad] : 16512
    float* wqs = wvs + 16512;   // 256

    int i = blockIdx.x;
    int b = blockIdx.y;
    int t = threadIdx.x;

    wqs[t] = wq[t];
    for (int idx = t; idx < 16384; idx += 256)
        wvs[(idx >> 8) * 258 + (idx & 255)] = wv[idx];
    for (int idx = t; idx < 8192; idx += 256) {
        int c = idx >> 7;
        int rem = idx & 127;          // a*64 + col
        xs[idx] = x[((b * 64 + c) * 64 + (2 * i + (rem >> 6))) * 64 + (rem & 63)];
    }
    __syncthreads();

    int co   = t >> 2;
    int quad = t & 3;
    int j0   = quad * 8;

    float acc[8];
    #pragma unroll
    for (int u = 0; u < 8; u++) acc[u] = 0.f;

    for (int ci = 0; ci < 64; ci++) {
        #pragma unroll
        for (int a = 0; a < 2; a++) {
            const float* xr = &xs[(ci * 2 + a) * 64 + quad * 16];
            float w0 = wvs[co * 258 + ci * 4 + a * 2 + 0];
            float w1 = wvs[co * 258 + ci * 4 + a * 2 + 1];
            #pragma unroll
            for (int jj = 0; jj < 4; jj++) {
                float4 xv = *reinterpret_cast<const float4*>(&xr[jj * 4]);
                acc[2 * jj + 0] += xv.x * w0 + xv.y * w1;
                acc[2 * jj + 1] += xv.z * w0 + xv.w * w1;
            }
        }
    }
    float bvv = bv[co];
    float* dst = &g_pv[(b * 64 + co) * NPOS + i * 32 + j0];
    float4 s0 = make_float4(acc[0] + bvv, acc[1] + bvv, acc[2] + bvv, acc[3] + bvv);
    float4 s1 = make_float4(acc[4] + bvv, acc[5] + bvv, acc[6] + bvv, acc[7] + bvv);
    *reinterpret_cast<float4*>(dst)     = s0;
    *reinterpret_cast<float4*>(dst + 4) = s1;

    if (t < 32) {
        int j = t;
        float aq = 0.f;
        for (int ci = 0; ci < 64; ci++) {
            #pragma unroll
            for (int a = 0; a < 2; a++) {
                aq += wqs[ci * 4 + a * 2 + 0] * xs[(ci * 2 + a) * 64 + 2 * j + 0];
                aq += wqs[ci * 4 + a * 2 + 1] * xs[(ci * 2 + a) * 64 + 2 * j + 1];
            }
        }
        g_q[b * NPOS + i * 32 + j] = aq + bq[0];
    }
}

// ---------------------------------------------------------------------------
// Kernel 5: fused softmax (rank-1) + attn write + GEMM out = pv @ attn^T
// grid (8, 64) = (m-tile, b), 256 threads, dyn smem = 56576 B
// ---------------------------------------------------------------------------
__global__ __launch_bounds__(256, 2) void attn_kernel(float* __restrict__ attn_out,
                                                      int has_attn) {
    extern __shared__ float sm[];
    float* ks   = sm;            // 1024
    float* sarr = ks + 1024;     // 128
    float* rm   = sarr + 128;    // 128
    float* invZ = rm + 128;      // 128
    float* zp   = invZ + 128;    // 256
    float* pvs  = zp + 256;      // 64*65 = 4160
    float* es   = pvs + 4160;    // 64*130 = 8320

    const float L2E = 1.4426950408889634f;
    int mt = blockIdx.x;
    int b  = blockIdx.y;
    int m0 = mt * 128;
    int t  = threadIdx.x;
    int w  = t >> 5;
    int l  = t & 31;

    for (int n = t; n < NPOS; n += 256) ks[n] = g_k[b * NPOS + n];
    if (t < 128) {
        float s = g_q[b * NPOS + m0 + t] * 0.03125f;   // 1/sqrt(1024)
        sarr[t] = s;
        rm[t] = (s >= 0.f) ? s * g_kmax[b] : s * g_kmin[b];
    }
    __syncthreads();

    // Pass 1: Z
    {
        int m = t & 127;
        int h = t >> 7;
        float s = sarr[m], rmm = rm[m];
        const float* kp = ks + h * 512;
        float p0 = 0.f, p1 = 0.f, p2 = 0.f, p3 = 0.f;
        #pragma unroll 4
        for (int n = 0; n < 512; n += 4) {
            p0 += ex2f((s * kp[n + 0] - rmm) * L2E);
            p1 += ex2f((s * kp[n + 1] - rmm) * L2E);
            p2 += ex2f((s * kp[n + 2] - rmm) * L2E);
            p3 += ex2f((s * kp[n + 3] - rmm) * L2E);
        }
        zp[h * 128 + m] = (p0 + p1) + (p2 + p3);
    }
    __syncthreads();
    if (t < 128) invZ[t] = 1.f / (zp[t] + zp[128 + t]);

    // register tile: 4 c x 4 m-pairs
    int r  = t >> 4;       // 0..15
    int cc = t & 15;       // 0..15
    int c0 = r * 4;

    unsigned long long acc[4][4];
    #pragma unroll
    for (int v_ = 0; v_ < 4; v_++)
        #pragma unroll
        for (int u = 0; u < 4; u++) acc[v_][u] = 0ull;

    for (int ch = 0; ch < 16; ch++) {
        int nn0 = ch * 64;
        __syncthreads();
        // load pv chunk
        for (int idx = t; idx < 4096; idx += 256) {
            int c = idx >> 6, nn = idx & 63;
            pvs[c * 65 + nn] = g_pv[(b * 64 + c) * NPOS + nn0 + nn];
        }
        // compute normalized attn chunk, write to gmem + smem
        for (int m = w; m < 128; m += 8) {
            float s = sarr[m], rmm = rm[m], iz = invZ[m];
            #pragma unroll
            for (int seg = 0; seg < 2; seg++) {
                int nn = seg * 32 + l;
                float val = ex2f((s * ks[nn0 + nn] - rmm) * L2E) * iz;
                es[nn * 130 + m] = val;
                if (has_attn)
                    attn_out[(size_t)(b * 1024 + m0 + m) * 1024 + nn0 + nn] = val;
            }
        }
        __syncthreads();
        // GEMM accumulate (f32x2 packed)
        #pragma unroll 4
        for (int nn = 0; nn < 64; nn++) {
            unsigned long long p[4], e[4];
            #pragma unroll
            for (int v_ = 0; v_ < 4; v_++) {
                float pvv = pvs[(c0 + v_) * 65 + nn];
                p[v_] = pack2(pvv, pvv);
            }
            #pragma unroll
            for (int u = 0; u < 4; u++)
                e[u] = *reinterpret_cast<const unsigned long long*>(
                          &es[nn * 130 + 2 * (cc + 16 * u)]);
            #pragma unroll
            for (int v_ = 0; v_ < 4; v_++)
                #pragma unroll
                for (int u = 0; u < 4; u++)
                    acc[v_][u] = fma2(p[v_], e[u], acc[v_][u]);
        }
    }

    #pragma unroll
    for (int v_ = 0; v_ < 4; v_++)
        #pragma unroll
        for (int u = 0; u < 4; u++) {
            float lo, hi;
            unpack2(acc[v_][u], lo, hi);
            int m = m0 + 2 * (cc + 16 * u);
            *reinterpret_cast<float2*>(&g_out[(b * 64 + c0 + v_) * NPOS + m]) =
                make_float2(lo, hi);
        }
}

// ---------------------------------------------------------------------------
// Kernel 6: ConvTranspose2d(k=2,s=2): up from g_out
// grid (32, 64) = (i, b), 256 threads, dyn smem = 73984 B
// ---------------------------------------------------------------------------
__global__ __launch_bounds__(256) void upsample_kernel(const float* __restrict__ wu,
                                                       const float* __restrict__ bu,
                                                       float* __restrict__ up) {
    extern __shared__ float sm[];
    float* wus  = sm;             // 16384
    float* outs = wus + 16384;    // 64*32 = 2048
    float* bus  = outs + 2048;    // 64

    int i = blockIdx.x;
    int b = blockIdx.y;
    int t = threadIdx.x;

    for (int idx = t; idx < 16384; idx += 256) wus[idx] = wu[idx];
    for (int idx = t; idx < 2048; idx += 256)
        outs[idx] = g_out[(b * 64 + (idx >> 5)) * NPOS + i * 32 + (idx & 31)];
    if (t < 64) bus[t] = bu[t];
    __syncthreads();

    int d    = t >> 2;
    int quad = t & 3;
    int j0   = quad * 8;

    float acc[4][8];
    #pragma unroll
    for (int p = 0; p < 4; p++)
        #pragma unroll
        for (int u = 0; u < 8; u++) acc[p][u] = 0.f;

    for (int c = 0; c < 64; c++) {
        float4 w4 = *reinterpret_cast<const float4*>(&wus[c * 256 + d * 4]);
        float4 o0 = *reinterpret_cast<const float4*>(&outs[c * 32 + j0]);
        float4 o1 = *reinterpret_cast<const float4*>(&outs[c * 32 + j0 + 4]);
        float ov[8] = {o0.x, o0.y, o0.z, o0.w, o1.x, o1.y, o1.z, o1.w};
        #pragma unroll
        for (int u = 0; u < 8; u++) {
            acc[0][u] += ov[u] * w4.x;   // a=0,b=0
            acc[1][u] += ov[u] * w4.y;   // a=0,b=1
            acc[2][u] += ov[u] * w4.z;   // a=1,b=0
            acc[3][u] += ov[u] * w4.w;   // a=1,b=1
        }
    }

    float bud = bus[d];
    #pragma unroll
    for (int a = 0; a < 2; a++) {
        float* row = &up[((size_t)(b * 64 + d) * 64 + (2 * i + a)) * 64 + 2 * j0];
        #pragma unroll
        for (int g = 0; g < 4; g++) {
            float4 v4 = make_float4(acc[a * 2 + 0][2 * g]     + bud,
                                    acc[a * 2 + 1][2 * g]     + bud,
                                    acc[a * 2 + 0][2 * g + 1] + bud,
                                    acc[a * 2 + 1][2 * g + 1] + bud);
            *reinterpret_cast<float4*>(&row[4 * g]) = v4;
        }
    }
}

// ---------------------------------------------------------------------------
extern "C" void kernel_launch(void* const* d_in, const int* in_sizes, int n_in,
                              void* d_out, int out_size) {
    const float* x     = (const float*)d_in[0];
    const float* v     = (const float*)d_in[1];
    const float* wq    = (const float*)d_in[2];
    const float* bq    = (const float*)d_in[3];
    const float* wk    = (const float*)d_in[4];
    const float* bk    = (const float*)d_in[5];
    const float* wv    = (const float*)d_in[6];
    const float* bv    = (const float*)d_in[7];
    const float* wu    = (const float*)d_in[8];
    const float* bu    = (const float*)d_in[9];
    const float* wproj = (const float*)d_in[10];
    const float* bproj = (const float*)d_in[11];

    float* up_out   = (float*)d_out;
    int has_attn    = (out_size > UP_ELEMS) ? 1 : 0;
    float* attn_out = up_out + UP_ELEMS;

    static int attr_done = 0;
    // (setting attributes every call is idempotent + cheap; not a work guard)
    cudaFuncSetAttribute(conv_x_kernel, cudaFuncAttributeMaxDynamicSharedMemorySize, 99840);
    cudaFuncSetAttribute(attn_kernel,   cudaFuncAttributeMaxDynamicSharedMemorySize, 56576);
    cudaFuncSetAttribute(upsample_kernel, cudaFuncAttributeMaxDynamicSharedMemorySize, 73984);
    (void)attr_done;

    conv_v_kernel<<<dim3(42, 64), 256>>>(v, wk, bk);
    kproj_kernel<<<16, 256>>>(wproj, bproj);
    kstats_kernel<<<64, 256>>>();
    conv_x_kernel<<<dim3(32, 64), 256, 99840>>>(x, wq, bq, wv, bv);
    attn_kernel<<<dim3(8, 64), 256, 56576>>>(attn_out, has_attn);
    upsample_kernel<<<dim3(32, 64), 256, 73984>>>(wu, bu, up_out);
}

// round 2
// speedup vs baseline: 1.3720x; 1.3720x over previous
#include <cuda_runtime.h>
#include <cuda_bf16.h>
#include <cstdint>

// Problem constants
#define BATCH 64
#define CH    64
#define HH    64
#define WW    64
#define NPOS  1024        // 32*32
#define KPIN  1134        // 42*27
#define KPOUT 1024
#define UP_ELEMS (BATCH*CH*HH*WW)          // 16777216
#define ATTN_ELEMS (BATCH*NPOS*NPOS)       // 67108864

// Scratch (device globals; no allocation)
__device__ float g_pv[BATCH * CH * NPOS];     // [b][c][n]
__device__ float g_out[BATCH * CH * NPOS];    // [b][c][m]
__device__ float g_q[BATCH * NPOS];
__device__ float g_k[BATCH * NPOS];
__device__ float g_kc[BATCH * KPIN];
__device__ float g_kmax[BATCH];
__device__ float g_kmin[BATCH];

typedef unsigned long long ull;

__device__ __forceinline__ float ex2f(float x) {
    float y;
    asm("ex2.approx.ftz.f32 %0, %1;" : "=f"(y) : "f"(x));
    return y;
}
__device__ __forceinline__ ull pack2(float lo, float hi) {
    ull r;
    asm("mov.b64 %0, {%1, %2};" : "=l"(r) : "f"(lo), "f"(hi));
    return r;
}
__device__ __forceinline__ ull fma2(ull a, ull b, ull c) {
    ull d;
    asm("fma.rn.f32x2 %0, %1, %2, %3;" : "=l"(d) : "l"(a), "l"(b), "l"(c));
    return d;
}
__device__ __forceinline__ void unpack2(ull r, float& lo, float& hi) {
    asm("mov.b64 {%0, %1}, %2;" : "=f"(lo), "=f"(hi) : "l"(r));
}

// ---------------------------------------------------------------------------
// Kernel 1: conv2x2(v, wk) -> g_kc[b][ii*27+jj]
// grid (42, 64), 256 threads
// ---------------------------------------------------------------------------
__global__ __launch_bounds__(256) void conv_v_kernel(const float* __restrict__ v,
                                                     const float* __restrict__ wk,
                                                     const float* __restrict__ bk) {
    __shared__ float vs[64 * 2 * 54];   // 27648 B
    __shared__ float wks[256];
    int ii = blockIdx.x;
    int b  = blockIdx.y;
    int t  = threadIdx.x;

    wks[t] = wk[t];
    for (int idx = t; idx < 64 * 2 * 54; idx += 256) {
        int c   = idx / 108;
        int rem = idx - c * 108;
        int a   = rem / 54;
        int col = rem - a * 54;
        vs[idx] = v[((b * 64 + c) * 84 + (2 * ii + a)) * 54 + col];
    }
    __syncthreads();

    if (t < 27) {
        int jj = t;
        float acc = 0.f;
        for (int c = 0; c < 64; c++) {
            #pragma unroll
            for (int a = 0; a < 2; a++) {
                float x0 = vs[(c * 2 + a) * 54 + 2 * jj + 0];
                float x1 = vs[(c * 2 + a) * 54 + 2 * jj + 1];
                acc += x0 * wks[c * 4 + a * 2 + 0] + x1 * wks[c * 4 + a * 2 + 1];
            }
        }
        g_kc[b * KPIN + ii * 27 + jj] = acc + bk[0];
    }
}

// ---------------------------------------------------------------------------
// Kernel 2: k[b][m] = sum_j g_kc[b][j] * wproj[m][j] + bproj[m]
// grid 16 (m-tiles of 64), 256 threads
// ---------------------------------------------------------------------------
__global__ __launch_bounds__(256) void kproj_kernel(const float* __restrict__ wproj,
                                                    const float* __restrict__ bproj) {
    __shared__ float kcs[64 * 65];
    __shared__ float ws[64 * 65];
    int m0 = blockIdx.x * 64;
    int t  = threadIdx.x;
    int r  = t >> 4;       // 0..15 -> b group
    int cc = t & 15;       // 0..15 -> m group
    int b0 = r * 4;
    int mm0 = cc * 4;

    float acc[4][4];
    #pragma unroll
    for (int i = 0; i < 4; i++)
        #pragma unroll
        for (int j = 0; j < 4; j++) acc[i][j] = 0.f;

    for (int j0 = 0; j0 < KPIN; j0 += 64) {
        __syncthreads();
        for (int idx = t; idx < 4096; idx += 256) {
            int row = idx >> 6, jj = idx & 63;
            int j = j0 + jj;
            kcs[row * 65 + jj] = (j < KPIN) ? g_kc[row * KPIN + j] : 0.f;
            ws[row * 65 + jj]  = (j < KPIN) ? wproj[(m0 + row) * KPIN + j] : 0.f;
        }
        __syncthreads();
        #pragma unroll 4
        for (int jj = 0; jj < 64; jj++) {
            float kv[4], wv_[4];
            #pragma unroll
            for (int v_ = 0; v_ < 4; v_++) kv[v_] = kcs[(b0 + v_) * 65 + jj];
            #pragma unroll
            for (int u = 0; u < 4; u++) wv_[u] = ws[(mm0 + u) * 65 + jj];
            #pragma unroll
            for (int v_ = 0; v_ < 4; v_++)
                #pragma unroll
                for (int u = 0; u < 4; u++) acc[v_][u] += kv[v_] * wv_[u];
        }
    }
    #pragma unroll
    for (int v_ = 0; v_ < 4; v_++)
        #pragma unroll
        for (int u = 0; u < 4; u++) {
            int m = m0 + mm0 + u;
            g_k[(b0 + v_) * KPOUT + m] = acc[v_][u] + bproj[m];
        }
}

// ---------------------------------------------------------------------------
// Kernel 3: per-b max/min of k
// ---------------------------------------------------------------------------
__global__ __launch_bounds__(256) void kstats_kernel() {
    __shared__ float smax[256], smin[256];
    int b = blockIdx.x, t = threadIdx.x;
    float mx = -1e30f, mn = 1e30f;
    for (int n = t; n < NPOS; n += 256) {
        float kv = g_k[b * NPOS + n];
        mx = fmaxf(mx, kv);
        mn = fminf(mn, kv);
    }
    smax[t] = mx; smin[t] = mn;
    __syncthreads();
    for (int s = 128; s > 0; s >>= 1) {
        if (t < s) {
            smax[t] = fmaxf(smax[t], smax[t + s]);
            smin[t] = fminf(smin[t], smin[t + s]);
        }
        __syncthreads();
    }
    if (t == 0) { g_kmax[b] = smax[0]; g_kmin[b] = smin[0]; }
}

// ---------------------------------------------------------------------------
// Kernel 4: conv2x2 of x with wv -> g_pv and wq -> g_q, as a register-tiled
// GEMM with packed f32x2 FMA.
// Per batch b: pv[co][n] = sum_{k=0..255} wv[co][k] * P[k][n],
//   k = ci*4 + a*2 + bb, P[k][n] = x[b,ci,2i+a,2j+bb], n = i*32+j.
// grid (4 ntile, 64 b), 256 threads = 8 cog x 32 g.
// Thread computes co = cog*8..+7, n = ntile*256 + (g>>2)*32 + (g&3)*8 ..+7.
// ---------------------------------------------------------------------------
__global__ __launch_bounds__(256, 2) void conv_x_kernel(const float* __restrict__ x,
                                                        const float* __restrict__ wq,
                                                        const float* __restrict__ bq,
                                                        const float* __restrict__ wv,
                                                        const float* __restrict__ bv) {
    __shared__ float As[64 * 34];       // [co][kl] kl<32, pad 34
    __shared__ float xs[8 * 16 * 68];   // [ci_l][row16][col64 pad 68]
    __shared__ float wqs[256];

    int ntile = blockIdx.x;
    int b     = blockIdx.y;
    int t     = threadIdx.x;
    int g     = t & 31;
    int cog   = t >> 5;
    int il    = g >> 2;       // 0..7 local i row
    int quad  = g & 3;        // 0..3

    wqs[t] = wq[t];

    ull acc[8][4];
    #pragma unroll
    for (int co = 0; co < 8; co++)
        #pragma unroll
        for (int p = 0; p < 4; p++) acc[co][p] = 0ull;
    ull qacc[4] = {0ull, 0ull, 0ull, 0ull};

    for (int chunk = 0; chunk < 8; chunk++) {
        int k0  = chunk * 32;
        int ci0 = chunk * 8;
        __syncthreads();
        #pragma unroll
        for (int s = 0; s < 8; s++) {
            int idx = t + s * 256;
            int co = idx >> 5, kl = idx & 31;
            As[co * 34 + kl] = wv[co * 256 + k0 + kl];
        }
        #pragma unroll
        for (int s = 0; s < 32; s++) {
            int idx = t + s * 256;
            int cl = idx >> 10;
            int rem = idx & 1023;
            int r = rem >> 6, col = rem & 63;
            xs[cl * 1088 + r * 68 + col] =
                x[(((size_t)b * 64 + ci0 + cl) * 64 + ntile * 16 + r) * 64 + col];
        }
        __syncthreads();

        #pragma unroll
        for (int cl = 0; cl < 8; cl++) {
            #pragma unroll
            for (int a = 0; a < 2; a++) {
                const float* xp = &xs[cl * 1088 + (2 * il + a) * 68 + quad * 16];
                float4 f0 = *reinterpret_cast<const float4*>(xp);
                float4 f1 = *reinterpret_cast<const float4*>(xp + 4);
                float4 f2 = *reinterpret_cast<const float4*>(xp + 8);
                float4 f3 = *reinterpret_cast<const float4*>(xp + 12);
                ull B0[4], B1[4];
                B0[0] = pack2(f0.x, f0.z); B1[0] = pack2(f0.y, f0.w);
                B0[1] = pack2(f1.x, f1.z); B1[1] = pack2(f1.y, f1.w);
                B0[2] = pack2(f2.x, f2.z); B1[2] = pack2(f2.y, f2.w);
                B0[3] = pack2(f3.x, f3.z); B1[3] = pack2(f3.y, f3.w);
                int kl0 = cl * 4 + a * 2;
                #pragma unroll
                for (int co = 0; co < 8; co++) {
                    float2 aa = *reinterpret_cast<const float2*>(
                        &As[(cog * 8 + co) * 34 + kl0]);
                    ull s0 = pack2(aa.x, aa.x);
                    ull s1 = pack2(aa.y, aa.y);
                    #pragma unroll
                    for (int p = 0; p < 4; p++) {
                        acc[co][p] = fma2(s0, B0[p], acc[co][p]);
                        acc[co][p] = fma2(s1, B1[p], acc[co][p]);
                    }
                }
                if (cog == 0) {
                    float w0 = wqs[k0 + kl0], w1 = wqs[k0 + kl0 + 1];
                    ull s0 = pack2(w0, w0), s1 = pack2(w1, w1);
                    #pragma unroll
                    for (int p = 0; p < 4; p++) {
                        qacc[p] = fma2(s0, B0[p], qacc[p]);
                        qacc[p] = fma2(s1, B1[p], qacc[p]);
                    }
                }
            }
        }
    }

    int nbase = ntile * 256 + il * 32 + quad * 8;
    #pragma unroll
    for (int co = 0; co < 8; co++) {
        int c = cog * 8 + co;
        float bvv = bv[c];
        float lo0, hi0, lo1, hi1, lo2, hi2, lo3, hi3;
        unpack2(acc[co][0], lo0, hi0);
        unpack2(acc[co][1], lo1, hi1);
        unpack2(acc[co][2], lo2, hi2);
        unpack2(acc[co][3], lo3, hi3);
        float* dst = &g_pv[((size_t)b * 64 + c) * NPOS + nbase];
        *reinterpret_cast<float4*>(dst) =
            make_float4(lo0 + bvv, hi0 + bvv, lo1 + bvv, hi1 + bvv);
        *reinterpret_cast<float4*>(dst + 4) =
            make_float4(lo2 + bvv, hi2 + bvv, lo3 + bvv, hi3 + bvv);
    }
    if (cog == 0) {
        float bqq = bq[0];
        float lo0, hi0, lo1, hi1, lo2, hi2, lo3, hi3;
        unpack2(qacc[0], lo0, hi0);
        unpack2(qacc[1], lo1, hi1);
        unpack2(qacc[2], lo2, hi2);
        unpack2(qacc[3], lo3, hi3);
        float* dst = &g_q[b * NPOS + nbase];
        *reinterpret_cast<float4*>(dst) =
            make_float4(lo0 + bqq, hi0 + bqq, lo1 + bqq, hi1 + bqq);
        *reinterpret_cast<float4*>(dst + 4) =
            make_float4(lo2 + bqq, hi2 + bqq, lo3 + bqq, hi3 + bqq);
    }
}

// ---------------------------------------------------------------------------
// Kernel 5: fused softmax (rank-1) + attn write + GEMM out = pv @ attn^T
// grid (8, 64) = (m-tile, b), 256 threads, dyn smem = 56576 B
// ---------------------------------------------------------------------------
__global__ __launch_bounds__(256, 2) void attn_kernel(float* __restrict__ attn_out,
                                                      int has_attn) {
    extern __shared__ float sm[];
    float* ks   = sm;            // 1024
    float* sarr = ks + 1024;     // 128
    float* rm   = sarr + 128;    // 128
    float* invZ = rm + 128;      // 128
    float* zp   = invZ + 128;    // 256
    float* pvs  = zp + 256;      // 64*65 = 4160
    float* es   = pvs + 4160;    // 64*130 = 8320

    const float L2E = 1.4426950408889634f;
    int mt = blockIdx.x;
    int b  = blockIdx.y;
    int m0 = mt * 128;
    int t  = threadIdx.x;
    int w  = t >> 5;
    int l  = t & 31;

    for (int n = t; n < NPOS; n += 256) ks[n] = g_k[b * NPOS + n];
    if (t < 128) {
        float s = g_q[b * NPOS + m0 + t] * 0.03125f;   // 1/sqrt(1024)
        sarr[t] = s;
        rm[t] = (s >= 0.f) ? s * g_kmax[b] : s * g_kmin[b];
    }
    __syncthreads();

    // Pass 1: Z
    {
        int m = t & 127;
        int h = t >> 7;
        float s = sarr[m], rmm = rm[m];
        const float* kp = ks + h * 512;
        float p0 = 0.f, p1 = 0.f, p2 = 0.f, p3 = 0.f;
        #pragma unroll 4
        for (int n = 0; n < 512; n += 4) {
            p0 += ex2f((s * kp[n + 0] - rmm) * L2E);
            p1 += ex2f((s * kp[n + 1] - rmm) * L2E);
            p2 += ex2f((s * kp[n + 2] - rmm) * L2E);
            p3 += ex2f((s * kp[n + 3] - rmm) * L2E);
        }
        zp[h * 128 + m] = (p0 + p1) + (p2 + p3);
    }
    __syncthreads();
    if (t < 128) invZ[t] = 1.f / (zp[t] + zp[128 + t]);

    // register tile: 4 c x 4 m-pairs
    int r  = t >> 4;       // 0..15
    int cc = t & 15;       // 0..15
    int c0 = r * 4;

    ull acc[4][4];
    #pragma unroll
    for (int v_ = 0; v_ < 4; v_++)
        #pragma unroll
        for (int u = 0; u < 4; u++) acc[v_][u] = 0ull;

    for (int ch = 0; ch < 16; ch++) {
        int nn0 = ch * 64;
        __syncthreads();
        // load pv chunk
        for (int idx = t; idx < 4096; idx += 256) {
            int c = idx >> 6, nn = idx & 63;
            pvs[c * 65 + nn] = g_pv[(b * 64 + c) * NPOS + nn0 + nn];
        }
        // compute normalized attn chunk, write to gmem + smem
        for (int m = w; m < 128; m += 8) {
            float s = sarr[m], rmm = rm[m], iz = invZ[m];
            #pragma unroll
            for (int seg = 0; seg < 2; seg++) {
                int nn = seg * 32 + l;
                float val = ex2f((s * ks[nn0 + nn] - rmm) * L2E) * iz;
                es[nn * 130 + m] = val;
                if (has_attn)
                    attn_out[(size_t)(b * 1024 + m0 + m) * 1024 + nn0 + nn] = val;
            }
        }
        __syncthreads();
        // GEMM accumulate (f32x2 packed)
        #pragma unroll 4
        for (int nn = 0; nn < 64; nn++) {
            ull p[4], e[4];
            #pragma unroll
            for (int v_ = 0; v_ < 4; v_++) {
                float pvv = pvs[(c0 + v_) * 65 + nn];
                p[v_] = pack2(pvv, pvv);
            }
            #pragma unroll
            for (int u = 0; u < 4; u++)
                e[u] = *reinterpret_cast<const ull*>(
                          &es[nn * 130 + 2 * (cc + 16 * u)]);
            #pragma unroll
            for (int v_ = 0; v_ < 4; v_++)
                #pragma unroll
                for (int u = 0; u < 4; u++)
                    acc[v_][u] = fma2(p[v_], e[u], acc[v_][u]);
        }
    }

    #pragma unroll
    for (int v_ = 0; v_ < 4; v_++)
        #pragma unroll
        for (int u = 0; u < 4; u++) {
            float lo, hi;
            unpack2(acc[v_][u], lo, hi);
            int m = m0 + 2 * (cc + 16 * u);
            *reinterpret_cast<float2*>(&g_out[(b * 64 + c0 + v_) * NPOS + m]) =
                make_float2(lo, hi);
        }
}

// ---------------------------------------------------------------------------
// Kernel 6: ConvTranspose2d(k=2,s=2): up from g_out. 4 i-rows per block,
// packed f32x2 FMA. grid (8, 64), 256 threads, dyn smem = 99584 B
// ---------------------------------------------------------------------------
__global__ __launch_bounds__(256, 2) void upsample_kernel(const float* __restrict__ wu,
                                                          const float* __restrict__ bu,
                                                          float* __restrict__ up) {
    extern __shared__ float sm[];
    float* wus  = sm;                 // 16384
    float* outs = wus + 16384;        // 64 * 132 = 8448
    float* bus  = outs + 8448;        // 64

    int ib = blockIdx.x;              // i-block: i0 = ib*4
    int b  = blockIdx.y;
    int t  = threadIdx.x;
    int d    = t >> 2;
    int quad = t & 3;
    int j0   = quad * 8;

    #pragma unroll
    for (int s = 0; s < 64; s++) wus[t + s * 256] = wu[t + s * 256];
    #pragma unroll
    for (int s = 0; s < 32; s++) {
        int idx = t + s * 256;
        int c = idx >> 7, nn = idx & 127;
        outs[c * 132 + nn] = g_out[((size_t)b * 64 + c) * NPOS + ib * 128 + nn];
    }
    if (t < 64) bus[t] = bu[t];
    __syncthreads();

    float bud = bus[d];

    #pragma unroll
    for (int il = 0; il < 4; il++) {
        ull accp[4][4];
        #pragma unroll
        for (int p = 0; p < 4; p++)
            #pragma unroll
            for (int ab = 0; ab < 4; ab++) accp[p][ab] = 0ull;

        for (int c = 0; c < 64; c++) {
            float4 w4 = *reinterpret_cast<const float4*>(&wus[c * 256 + d * 4]);
            float4 o0 = *reinterpret_cast<const float4*>(&outs[c * 132 + il * 32 + j0]);
            float4 o1 = *reinterpret_cast<const float4*>(&outs[c * 132 + il * 32 + j0 + 4]);
            ull oP[4];
            oP[0] = pack2(o0.x, o0.y);
            oP[1] = pack2(o0.z, o0.w);
            oP[2] = pack2(o1.x, o1.y);
            oP[3] = pack2(o1.z, o1.w);
            ull ws[4];
            ws[0] = pack2(w4.x, w4.x);
            ws[1] = pack2(w4.y, w4.y);
            ws[2] = pack2(w4.z, w4.z);
            ws[3] = pack2(w4.w, w4.w);
            #pragma unroll
            for (int p = 0; p < 4; p++)
                #pragma unroll
                for (int ab = 0; ab < 4; ab++)
                    accp[p][ab] = fma2(oP[p], ws[ab], accp[p][ab]);
        }

        #pragma unroll
        for (int a = 0; a < 2; a++) {
            float* row = &up[(((size_t)b * 64 + d) * 64 + 2 * (ib * 4 + il) + a) * 64 + 2 * j0];
            #pragma unroll
            for (int p = 0; p < 4; p++) {
                float lo0, hi0, lo1, hi1;
                unpack2(accp[p][a * 2 + 0], lo0, hi0);
                unpack2(accp[p][a * 2 + 1], lo1, hi1);
                *reinterpret_cast<float4*>(&row[4 * p]) =
                    make_float4(lo0 + bud, lo1 + bud, hi0 + bud, hi1 + bud);
            }
        }
    }
}

// ---------------------------------------------------------------------------
extern "C" void kernel_launch(void* const* d_in, const int* in_sizes, int n_in,
                              void* d_out, int out_size) {
    const float* x     = (const float*)d_in[0];
    const float* v     = (const float*)d_in[1];
    const float* wq    = (const float*)d_in[2];
    const float* bq    = (const float*)d_in[3];
    const float* wk    = (const float*)d_in[4];
    const float* bk    = (const float*)d_in[5];
    const float* wv    = (const float*)d_in[6];
    const float* bv    = (const float*)d_in[7];
    const float* wu    = (const float*)d_in[8];
    const float* bu    = (const float*)d_in[9];
    const float* wproj = (const float*)d_in[10];
    const float* bproj = (const float*)d_in[11];

    float* up_out   = (float*)d_out;
    int has_attn    = (out_size > UP_ELEMS) ? 1 : 0;
    float* attn_out = up_out + UP_ELEMS;

    cudaFuncSetAttribute(attn_kernel,     cudaFuncAttributeMaxDynamicSharedMemorySize, 56576);
    cudaFuncSetAttribute(upsample_kernel, cudaFuncAttributeMaxDynamicSharedMemorySize, 99584);

    conv_v_kernel<<<dim3(42, 64), 256>>>(v, wk, bk);
    kproj_kernel<<<16, 256>>>(wproj, bproj);
    kstats_kernel<<<64, 256>>>();
    conv_x_kernel<<<dim3(4, 64), 256>>>(x, wq, bq, wv, bv);
    attn_kernel<<<dim3(8, 64), 256, 56576>>>(attn_out, has_attn);
    upsample_kernel<<<dim3(8, 64), 256, 99584>>>(wu, bu, up_out);
}

// round 3
// speedup vs baseline: 1.7775x; 1.2956x over previous
#include <cuda_runtime.h>
#include <cuda_bf16.h>
#include <cstdint>

// Problem constants
#define BATCH 64
#define CH    64
#define HH    64
#define WW    64
#define NPOS  1024        // 32*32
#define KPIN  1134        // 42*27
#define KPOUT 1024
#define UP_ELEMS (BATCH*CH*HH*WW)          // 16777216
#define ATTN_ELEMS (BATCH*NPOS*NPOS)       // 67108864

// Scratch (device globals; no allocation)
__device__ float g_pv[BATCH * CH * NPOS];     // [b][c][n]
__device__ float g_out[BATCH * CH * NPOS];    // [b][c][m]
__device__ float g_q[BATCH * NPOS];
__device__ float g_k[BATCH * NPOS];
__device__ float g_kc[BATCH * KPIN];
__device__ float g_kmax[BATCH];
__device__ float g_kmin[BATCH];

typedef unsigned long long ull;

__device__ __forceinline__ float ex2f(float x) {
    float y;
    asm("ex2.approx.ftz.f32 %0, %1;" : "=f"(y) : "f"(x));
    return y;
}
__device__ __forceinline__ ull pack2(float lo, float hi) {
    ull r;
    asm("mov.b64 %0, {%1, %2};" : "=l"(r) : "f"(lo), "f"(hi));
    return r;
}
__device__ __forceinline__ ull fma2(ull a, ull b, ull c) {
    ull d;
    asm("fma.rn.f32x2 %0, %1, %2, %3;" : "=l"(d) : "l"(a), "l"(b), "l"(c));
    return d;
}
__device__ __forceinline__ void unpack2(ull r, float& lo, float& hi) {
    asm("mov.b64 {%0, %1}, %2;" : "=f"(lo), "=f"(hi) : "l"(r));
}
__device__ __forceinline__ uint32_t tf32r(float x) {
    uint32_t r;
    asm("cvt.rna.tf32.f32 %0, %1;" : "=r"(r) : "f"(x));
    return r;
}
__device__ __forceinline__ void mma_tf32(float& d0, float& d1, float& d2, float& d3,
                                         uint32_t a0, uint32_t a1, uint32_t a2, uint32_t a3,
                                         uint32_t b0, uint32_t b1) {
    asm("mma.sync.aligned.m16n8k8.row.col.f32.tf32.tf32.f32 "
        "{%0,%1,%2,%3}, {%4,%5,%6,%7}, {%8,%9}, {%0,%1,%2,%3};"
        : "+f"(d0), "+f"(d1), "+f"(d2), "+f"(d3)
        : "r"(a0), "r"(a1), "r"(a2), "r"(a3), "r"(b0), "r"(b1));
}

// ---------------------------------------------------------------------------
// Kernel 1: conv2x2(v, wk) -> g_kc[b][ii*27+jj]
// ---------------------------------------------------------------------------
__global__ __launch_bounds__(256) void conv_v_kernel(const float* __restrict__ v,
                                                     const float* __restrict__ wk,
                                                     const float* __restrict__ bk) {
    __shared__ float vs[64 * 2 * 54];
    __shared__ float wks[256];
    int ii = blockIdx.x;
    int b  = blockIdx.y;
    int t  = threadIdx.x;

    wks[t] = wk[t];
    for (int idx = t; idx < 64 * 2 * 54; idx += 256) {
        int c   = idx / 108;
        int rem = idx - c * 108;
        int a   = rem / 54;
        int col = rem - a * 54;
        vs[idx] = v[((b * 64 + c) * 84 + (2 * ii + a)) * 54 + col];
    }
    __syncthreads();

    if (t < 27) {
        int jj = t;
        float acc = 0.f;
        for (int c = 0; c < 64; c++) {
            #pragma unroll
            for (int a = 0; a < 2; a++) {
                float x0 = vs[(c * 2 + a) * 54 + 2 * jj + 0];
                float x1 = vs[(c * 2 + a) * 54 + 2 * jj + 1];
                acc += x0 * wks[c * 4 + a * 2 + 0] + x1 * wks[c * 4 + a * 2 + 1];
            }
        }
        g_kc[b * KPIN + ii * 27 + jj] = acc + bk[0];
    }
}

// ---------------------------------------------------------------------------
// Kernel 2: k[b][m] = sum_j g_kc[b][j] * wproj[m][j] + bproj[m]
// ---------------------------------------------------------------------------
__global__ __launch_bounds__(256) void kproj_kernel(const float* __restrict__ wproj,
                                                    const float* __restrict__ bproj) {
    __shared__ float kcs[64 * 65];
    __shared__ float ws[64 * 65];
    int m0 = blockIdx.x * 64;
    int t  = threadIdx.x;
    int r  = t >> 4;
    int cc = t & 15;
    int b0 = r * 4;
    int mm0 = cc * 4;

    float acc[4][4];
    #pragma unroll
    for (int i = 0; i < 4; i++)
        #pragma unroll
        for (int j = 0; j < 4; j++) acc[i][j] = 0.f;

    for (int j0 = 0; j0 < KPIN; j0 += 64) {
        __syncthreads();
        for (int idx = t; idx < 4096; idx += 256) {
            int row = idx >> 6, jj = idx & 63;
            int j = j0 + jj;
            kcs[row * 65 + jj] = (j < KPIN) ? g_kc[row * KPIN + j] : 0.f;
            ws[row * 65 + jj]  = (j < KPIN) ? wproj[(m0 + row) * KPIN + j] : 0.f;
        }
        __syncthreads();
        #pragma unroll 4
        for (int jj = 0; jj < 64; jj++) {
            float kv[4], wv_[4];
            #pragma unroll
            for (int v_ = 0; v_ < 4; v_++) kv[v_] = kcs[(b0 + v_) * 65 + jj];
            #pragma unroll
            for (int u = 0; u < 4; u++) wv_[u] = ws[(mm0 + u) * 65 + jj];
            #pragma unroll
            for (int v_ = 0; v_ < 4; v_++)
                #pragma unroll
                for (int u = 0; u < 4; u++) acc[v_][u] += kv[v_] * wv_[u];
        }
    }
    #pragma unroll
    for (int v_ = 0; v_ < 4; v_++)
        #pragma unroll
        for (int u = 0; u < 4; u++) {
            int m = m0 + mm0 + u;
            g_k[(b0 + v_) * KPOUT + m] = acc[v_][u] + bproj[m];
        }
}

// ---------------------------------------------------------------------------
// Kernel 3: per-b max/min of k
// ---------------------------------------------------------------------------
__global__ __launch_bounds__(256) void kstats_kernel() {
    __shared__ float smax[256], smin[256];
    int b = blockIdx.x, t = threadIdx.x;
    float mx = -1e30f, mn = 1e30f;
    for (int n = t; n < NPOS; n += 256) {
        float kv = g_k[b * NPOS + n];
        mx = fmaxf(mx, kv);
        mn = fminf(mn, kv);
    }
    smax[t] = mx; smin[t] = mn;
    __syncthreads();
    for (int s = 128; s > 0; s >>= 1) {
        if (t < s) {
            smax[t] = fmaxf(smax[t], smax[t + s]);
            smin[t] = fminf(smin[t], smin[t + s]);
        }
        __syncthreads();
    }
    if (t == 0) { g_kmax[b] = smax[0]; g_kmin[b] = smin[0]; }
}

// ---------------------------------------------------------------------------
// Kernel 4: conv2x2 of x with wv -> g_pv and wq -> g_q (f32x2 GEMM)
// ---------------------------------------------------------------------------
__global__ __launch_bounds__(256, 2) void conv_x_kernel(const float* __restrict__ x,
                                                        const float* __restrict__ wq,
                                                        const float* __restrict__ bq,
                                                        const float* __restrict__ wv,
                                                        const float* __restrict__ bv) {
    __shared__ float As[64 * 34];
    __shared__ float xs[8 * 16 * 68];
    __shared__ float wqs[256];

    int ntile = blockIdx.x;
    int b     = blockIdx.y;
    int t     = threadIdx.x;
    int g     = t & 31;
    int cog   = t >> 5;
    int il    = g >> 2;
    int quad  = g & 3;

    wqs[t] = wq[t];

    ull acc[8][4];
    #pragma unroll
    for (int co = 0; co < 8; co++)
        #pragma unroll
        for (int p = 0; p < 4; p++) acc[co][p] = 0ull;
    ull qacc[4] = {0ull, 0ull, 0ull, 0ull};

    for (int chunk = 0; chunk < 8; chunk++) {
        int k0  = chunk * 32;
        int ci0 = chunk * 8;
        __syncthreads();
        #pragma unroll
        for (int s = 0; s < 8; s++) {
            int idx = t + s * 256;
            int co = idx >> 5, kl = idx & 31;
            As[co * 34 + kl] = wv[co * 256 + k0 + kl];
        }
        #pragma unroll
        for (int s = 0; s < 32; s++) {
            int idx = t + s * 256;
            int cl = idx >> 10;
            int rem = idx & 1023;
            int r = rem >> 6, col = rem & 63;
            xs[cl * 1088 + r * 68 + col] =
                x[(((size_t)b * 64 + ci0 + cl) * 64 + ntile * 16 + r) * 64 + col];
        }
        __syncthreads();

        #pragma unroll
        for (int cl = 0; cl < 8; cl++) {
            #pragma unroll
            for (int a = 0; a < 2; a++) {
                const float* xp = &xs[cl * 1088 + (2 * il + a) * 68 + quad * 16];
                float4 f0 = *reinterpret_cast<const float4*>(xp);
                float4 f1 = *reinterpret_cast<const float4*>(xp + 4);
                float4 f2 = *reinterpret_cast<const float4*>(xp + 8);
                float4 f3 = *reinterpret_cast<const float4*>(xp + 12);
                ull B0[4], B1[4];
                B0[0] = pack2(f0.x, f0.z); B1[0] = pack2(f0.y, f0.w);
                B0[1] = pack2(f1.x, f1.z); B1[1] = pack2(f1.y, f1.w);
                B0[2] = pack2(f2.x, f2.z); B1[2] = pack2(f2.y, f2.w);
                B0[3] = pack2(f3.x, f3.z); B1[3] = pack2(f3.y, f3.w);
                int kl0 = cl * 4 + a * 2;
                #pragma unroll
                for (int co = 0; co < 8; co++) {
                    float2 aa = *reinterpret_cast<const float2*>(
                        &As[(cog * 8 + co) * 34 + kl0]);
                    ull s0 = pack2(aa.x, aa.x);
                    ull s1 = pack2(aa.y, aa.y);
                    #pragma unroll
                    for (int p = 0; p < 4; p++) {
                        acc[co][p] = fma2(s0, B0[p], acc[co][p]);
                        acc[co][p] = fma2(s1, B1[p], acc[co][p]);
                    }
                }
                if (cog == 0) {
                    float w0 = wqs[k0 + kl0], w1 = wqs[k0 + kl0 + 1];
                    ull s0 = pack2(w0, w0), s1 = pack2(w1, w1);
                    #pragma unroll
                    for (int p = 0; p < 4; p++) {
                        qacc[p] = fma2(s0, B0[p], qacc[p]);
                        qacc[p] = fma2(s1, B1[p], qacc[p]);
                    }
                }
            }
        }
    }

    int nbase = ntile * 256 + il * 32 + quad * 8;
    #pragma unroll
    for (int co = 0; co < 8; co++) {
        int c = cog * 8 + co;
        float bvv = bv[c];
        float lo0, hi0, lo1, hi1, lo2, hi2, lo3, hi3;
        unpack2(acc[co][0], lo0, hi0);
        unpack2(acc[co][1], lo1, hi1);
        unpack2(acc[co][2], lo2, hi2);
        unpack2(acc[co][3], lo3, hi3);
        float* dst = &g_pv[((size_t)b * 64 + c) * NPOS + nbase];
        *reinterpret_cast<float4*>(dst) =
            make_float4(lo0 + bvv, hi0 + bvv, lo1 + bvv, hi1 + bvv);
        *reinterpret_cast<float4*>(dst + 4) =
            make_float4(lo2 + bvv, hi2 + bvv, lo3 + bvv, hi3 + bvv);
    }
    if (cog == 0) {
        float bqq = bq[0];
        float lo0, hi0, lo1, hi1, lo2, hi2, lo3, hi3;
        unpack2(qacc[0], lo0, hi0);
        unpack2(qacc[1], lo1, hi1);
        unpack2(qacc[2], lo2, hi2);
        unpack2(qacc[3], lo3, hi3);
        float* dst = &g_q[b * NPOS + nbase];
        *reinterpret_cast<float4*>(dst) =
            make_float4(lo0 + bqq, hi0 + bqq, lo1 + bqq, hi1 + bqq);
        *reinterpret_cast<float4*>(dst + 4) =
            make_float4(lo2 + bqq, hi2 + bqq, lo3 + bqq, hi3 + bqq);
    }
}

// ---------------------------------------------------------------------------
// Kernel 5: fused softmax (rank-1) + attn write + tf32 MMA GEMM out = pv@attn^T
// grid (8, 64) = (m-tile, b), 256 threads = 8 warps, dyn smem = 58880 B
//
// smem layout (floats/u32):
//   ks[1024], sarr[128], rm[128], invZ[128], zp[256],
//   pvs[64][68] (tf32 bits), es[128][68] (tf32 bits)
//
// MMA: per warp, m-slice of 16 (2 n-tiles of 8), 4 c-tiles of 16.
// A = pvs (c x k), B = es (m x k), D[c][m] accumulated in 32 fp32 regs.
// ---------------------------------------------------------------------------
__global__ __launch_bounds__(256, 2) void attn_kernel(float* __restrict__ attn_out,
                                                      int has_attn) {
    extern __shared__ float sm[];
    float*    ks   = sm;              // 1024
    float*    sarr = ks + 1024;       // 128
    float*    rm   = sarr + 128;      // 128
    float*    invZ = rm + 128;        // 128
    float*    zp   = invZ + 128;      // 256
    uint32_t* pvs  = reinterpret_cast<uint32_t*>(zp + 256);   // 64*68 = 4352
    uint32_t* es   = pvs + 4352;      // 128*68 = 8704

    const float L2E = 1.4426950408889634f;
    int mt = blockIdx.x;
    int b  = blockIdx.y;
    int m0 = mt * 128;
    int t  = threadIdx.x;
    int wid = t >> 5;
    int l   = t & 31;
    int g   = l >> 2;      // 0..7
    int tg  = l & 3;       // 0..3

    for (int n = t; n < NPOS; n += 256) ks[n] = g_k[b * NPOS + n];
    if (t < 128) {
        float s = g_q[b * NPOS + m0 + t] * 0.03125f;   // 1/sqrt(1024)
        sarr[t] = s;
        rm[t] = (s >= 0.f) ? s * g_kmax[b] : s * g_kmin[b];
    }
    __syncthreads();

    // Pass 1: Z
    {
        int m = t & 127;
        int h = t >> 7;
        float s = sarr[m], rmm = rm[m];
        const float* kp = ks + h * 512;
        float p0 = 0.f, p1 = 0.f, p2 = 0.f, p3 = 0.f;
        #pragma unroll 4
        for (int n = 0; n < 512; n += 4) {
            p0 += ex2f((s * kp[n + 0] - rmm) * L2E);
            p1 += ex2f((s * kp[n + 1] - rmm) * L2E);
            p2 += ex2f((s * kp[n + 2] - rmm) * L2E);
            p3 += ex2f((s * kp[n + 3] - rmm) * L2E);
        }
        zp[h * 128 + m] = (p0 + p1) + (p2 + p3);
    }
    __syncthreads();
    if (t < 128) invZ[t] = 1.f / (zp[t] + zp[128 + t]);

    // accumulators: 4 c-tiles x 2 m-tiles x 4 regs
    float acc[4][2][4];
    #pragma unroll
    for (int ct = 0; ct < 4; ct++)
        #pragma unroll
        for (int nt = 0; nt < 2; nt++)
            #pragma unroll
            for (int u = 0; u < 4; u++) acc[ct][nt][u] = 0.f;

    int mbase = wid * 16;

    for (int ch = 0; ch < 16; ch++) {
        int nn0 = ch * 64;
        __syncthreads();
        // stage pv chunk as tf32 bits
        #pragma unroll
        for (int s = 0; s < 16; s++) {
            int idx = t + s * 256;
            int c = idx >> 6, nn = idx & 63;
            pvs[c * 68 + nn] = tf32r(g_pv[((size_t)b * 64 + c) * NPOS + nn0 + nn]);
        }
        // compute normalized attn chunk: exact fp32 to gmem, tf32 bits to smem
        for (int m = wid; m < 128; m += 8) {
            float s = sarr[m], rmm = rm[m], iz = invZ[m];
            #pragma unroll
            for (int seg = 0; seg < 2; seg++) {
                int nn = seg * 32 + l;
                float val = ex2f((s * ks[nn0 + nn] - rmm) * L2E) * iz;
                es[m * 68 + nn] = tf32r(val);
                if (has_attn)
                    attn_out[(size_t)(b * 1024 + m0 + m) * 1024 + nn0 + nn] = val;
            }
        }
        __syncthreads();

        // MMA over 8 k-steps
        #pragma unroll
        for (int ks8 = 0; ks8 < 8; ks8++) {
            int kk = ks8 * 8 + tg;
            uint32_t afr[4][4];
            #pragma unroll
            for (int ct = 0; ct < 4; ct++) {
                const uint32_t* ap = &pvs[(ct * 16 + g) * 68 + kk];
                afr[ct][0] = ap[0];
                afr[ct][1] = ap[8 * 68];
                afr[ct][2] = ap[4];
                afr[ct][3] = ap[8 * 68 + 4];
            }
            uint32_t bfr[2][2];
            #pragma unroll
            for (int nt = 0; nt < 2; nt++) {
                const uint32_t* bp = &es[(mbase + nt * 8 + g) * 68 + kk];
                bfr[nt][0] = bp[0];
                bfr[nt][1] = bp[4];
            }
            #pragma unroll
            for (int ct = 0; ct < 4; ct++)
                #pragma unroll
                for (int nt = 0; nt < 2; nt++)
                    mma_tf32(acc[ct][nt][0], acc[ct][nt][1], acc[ct][nt][2], acc[ct][nt][3],
                             afr[ct][0], afr[ct][1], afr[ct][2], afr[ct][3],
                             bfr[nt][0], bfr[nt][1]);
        }
    }

    // write g_out: D[c][m], c = ct*16 + g (+8), m = m0 + mbase + nt*8 + 2*tg (+1)
    #pragma unroll
    for (int ct = 0; ct < 4; ct++) {
        #pragma unroll
        for (int nt = 0; nt < 2; nt++) {
            int m = m0 + mbase + nt * 8 + 2 * tg;
            int c_lo = ct * 16 + g;
            *reinterpret_cast<float2*>(&g_out[((size_t)b * 64 + c_lo) * NPOS + m]) =
                make_float2(acc[ct][nt][0], acc[ct][nt][1]);
            *reinterpret_cast<float2*>(&g_out[((size_t)b * 64 + c_lo + 8) * NPOS + m]) =
                make_float2(acc[ct][nt][2], acc[ct][nt][3]);
        }
    }
}

// ---------------------------------------------------------------------------
// Kernel 6: ConvTranspose2d(k=2,s=2): up from g_out. 4 i-rows per block,
// packed f32x2 FMA. grid (8, 64), 256 threads, dyn smem = 99584 B
// ---------------------------------------------------------------------------
__global__ __launch_bounds__(256, 2) void upsample_kernel(const float* __restrict__ wu,
                                                          const float* __restrict__ bu,
                                                          float* __restrict__ up) {
    extern __shared__ float sm[];
    float* wus  = sm;                 // 16384
    float* outs = wus + 16384;        // 64 * 132 = 8448
    float* bus  = outs + 8448;        // 64

    int ib = blockIdx.x;
    int b  = blockIdx.y;
    int t  = threadIdx.x;
    int d    = t >> 2;
    int quad = t & 3;
    int j0   = quad * 8;

    #pragma unroll
    for (int s = 0; s < 64; s++) wus[t + s * 256] = wu[t + s * 256];
    #pragma unroll
    for (int s = 0; s < 32; s++) {
        int idx = t + s * 256;
        int c = idx >> 7, nn = idx & 127;
        outs[c * 132 + nn] = g_out[((size_t)b * 64 + c) * NPOS + ib * 128 + nn];
    }
    if (t < 64) bus[t] = bu[t];
    __syncthreads();

    float bud = bus[d];

    #pragma unroll
    for (int il = 0; il < 4; il++) {
        ull accp[4][4];
        #pragma unroll
        for (int p = 0; p < 4; p++)
            #pragma unroll
            for (int ab = 0; ab < 4; ab++) accp[p][ab] = 0ull;

        for (int c = 0; c < 64; c++) {
            float4 w4 = *reinterpret_cast<const float4*>(&wus[c * 256 + d * 4]);
            float4 o0 = *reinterpret_cast<const float4*>(&outs[c * 132 + il * 32 + j0]);
            float4 o1 = *reinterpret_cast<const float4*>(&outs[c * 132 + il * 32 + j0 + 4]);
            ull oP[4];
            oP[0] = pack2(o0.x, o0.y);
            oP[1] = pack2(o0.z, o0.w);
            oP[2] = pack2(o1.x, o1.y);
            oP[3] = pack2(o1.z, o1.w);
            ull ws[4];
            ws[0] = pack2(w4.x, w4.x);
            ws[1] = pack2(w4.y, w4.y);
            ws[2] = pack2(w4.z, w4.z);
            ws[3] = pack2(w4.w, w4.w);
            #pragma unroll
            for (int p = 0; p < 4; p++)
                #pragma unroll
                for (int ab = 0; ab < 4; ab++)
                    accp[p][ab] = fma2(oP[p], ws[ab], accp[p][ab]);
        }

        #pragma unroll
        for (int a = 0; a < 2; a++) {
            float* row = &up[(((size_t)b * 64 + d) * 64 + 2 * (ib * 4 + il) + a) * 64 + 2 * j0];
            #pragma unroll
            for (int p = 0; p < 4; p++) {
                float lo0, hi0, lo1, hi1;
                unpack2(accp[p][a * 2 + 0], lo0, hi0);
                unpack2(accp[p][a * 2 + 1], lo1, hi1);
                *reinterpret_cast<float4*>(&row[4 * p]) =
                    make_float4(lo0 + bud, lo1 + bud, hi0 + bud, hi1 + bud);
            }
        }
    }
}

// ---------------------------------------------------------------------------
extern "C" void kernel_launch(void* const* d_in, const int* in_sizes, int n_in,
                              void* d_out, int out_size) {
    const float* x     = (const float*)d_in[0];
    const float* v     = (const float*)d_in[1];
    const float* wq    = (const float*)d_in[2];
    const float* bq    = (const float*)d_in[3];
    const float* wk    = (const float*)d_in[4];
    const float* bk    = (const float*)d_in[5];
    const float* wv    = (const float*)d_in[6];
    const float* bv    = (const float*)d_in[7];
    const float* wu    = (const float*)d_in[8];
    const float* bu    = (const float*)d_in[9];
    const float* wproj = (const float*)d_in[10];
    const float* bproj = (const float*)d_in[11];

    float* up_out   = (float*)d_out;
    int has_attn    = (out_size > UP_ELEMS) ? 1 : 0;
    float* attn_out = up_out + UP_ELEMS;

    cudaFuncSetAttribute(attn_kernel,     cudaFuncAttributeMaxDynamicSharedMemorySize, 58880);
    cudaFuncSetAttribute(upsample_kernel, cudaFuncAttributeMaxDynamicSharedMemorySize, 99584);

    conv_v_kernel<<<dim3(42, 64), 256>>>(v, wk, bk);
    kproj_kernel<<<16, 256>>>(wproj, bproj);
    kstats_kernel<<<64, 256>>>();
    conv_x_kernel<<<dim3(4, 64), 256>>>(x, wq, bq, wv, bv);
    attn_kernel<<<dim3(8, 64), 256, 58880>>>(attn_out, has_attn);
    upsample_kernel<<<dim3(8, 64), 256, 99584>>>(wu, bu, up_out);
}

// round 4
// speedup vs baseline: 1.9582x; 1.1017x over previous
#include <cuda_runtime.h>
#include <cuda_bf16.h>
#include <cstdint>

// Problem constants
#define BATCH 64
#define CH    64
#define HH    64
#define WW    64
#define NPOS  1024        // 32*32
#define KPIN  1134        // 42*27
#define KPOUT 1024
#define UP_ELEMS (BATCH*CH*HH*WW)          // 16777216
#define ATTN_ELEMS (BATCH*NPOS*NPOS)       // 67108864

// Scratch (device globals; no allocation)
__device__ float g_pv[BATCH * CH * NPOS];     // [b][c][n]
__device__ float g_outT[BATCH * NPOS * CH];   // [b][m][c]  (transposed!)
__device__ float g_q[BATCH * NPOS];
__device__ float g_k[BATCH * NPOS];
__device__ float g_kc[BATCH * KPIN];
__device__ float g_kmax[BATCH];
__device__ float g_kmin[BATCH];

typedef unsigned long long ull;

__device__ __forceinline__ float ex2f(float x) {
    float y;
    asm("ex2.approx.ftz.f32 %0, %1;" : "=f"(y) : "f"(x));
    return y;
}
__device__ __forceinline__ ull pack2(float lo, float hi) {
    ull r;
    asm("mov.b64 %0, {%1, %2};" : "=l"(r) : "f"(lo), "f"(hi));
    return r;
}
__device__ __forceinline__ ull fma2(ull a, ull b, ull c) {
    ull d;
    asm("fma.rn.f32x2 %0, %1, %2, %3;" : "=l"(d) : "l"(a), "l"(b), "l"(c));
    return d;
}
__device__ __forceinline__ void unpack2(ull r, float& lo, float& hi) {
    asm("mov.b64 {%0, %1}, %2;" : "=f"(lo), "=f"(hi) : "l"(r));
}
__device__ __forceinline__ uint32_t tf32r(float x) {
    uint32_t r;
    asm("cvt.rna.tf32.f32 %0, %1;" : "=r"(r) : "f"(x));
    return r;
}
__device__ __forceinline__ void mma_tf32(float& d0, float& d1, float& d2, float& d3,
                                         uint32_t a0, uint32_t a1, uint32_t a2, uint32_t a3,
                                         uint32_t b0, uint32_t b1) {
    asm("mma.sync.aligned.m16n8k8.row.col.f32.tf32.tf32.f32 "
        "{%0,%1,%2,%3}, {%4,%5,%6,%7}, {%8,%9}, {%0,%1,%2,%3};"
        : "+f"(d0), "+f"(d1), "+f"(d2), "+f"(d3)
        : "r"(a0), "r"(a1), "r"(a2), "r"(a3), "r"(b0), "r"(b1));
}

// ---------------------------------------------------------------------------
// Kernel 1: conv2x2(v, wk) -> g_kc[b][ii*27+jj]
// ---------------------------------------------------------------------------
__global__ __launch_bounds__(256) void conv_v_kernel(const float* __restrict__ v,
                                                     const float* __restrict__ wk,
                                                     const float* __restrict__ bk) {
    __shared__ float vs[64 * 2 * 54];
    __shared__ float wks[256];
    int ii = blockIdx.x;
    int b  = blockIdx.y;
    int t  = threadIdx.x;

    wks[t] = wk[t];
    for (int idx = t; idx < 64 * 2 * 54; idx += 256) {
        int c   = idx / 108;
        int rem = idx - c * 108;
        int a   = rem / 54;
        int col = rem - a * 54;
        vs[idx] = v[((b * 64 + c) * 84 + (2 * ii + a)) * 54 + col];
    }
    __syncthreads();

    if (t < 27) {
        int jj = t;
        float acc = 0.f;
        for (int c = 0; c < 64; c++) {
            #pragma unroll
            for (int a = 0; a < 2; a++) {
                float x0 = vs[(c * 2 + a) * 54 + 2 * jj + 0];
                float x1 = vs[(c * 2 + a) * 54 + 2 * jj + 1];
                acc += x0 * wks[c * 4 + a * 2 + 0] + x1 * wks[c * 4 + a * 2 + 1];
            }
        }
        g_kc[b * KPIN + ii * 27 + jj] = acc + bk[0];
    }
}

// ---------------------------------------------------------------------------
// Kernel 2: k[b][m] = sum_j g_kc[b][j] * wproj[m][j] + bproj[m]
// ---------------------------------------------------------------------------
__global__ __launch_bounds__(256) void kproj_kernel(const float* __restrict__ wproj,
                                                    const float* __restrict__ bproj) {
    __shared__ float kcs[64 * 65];
    __shared__ float ws[64 * 65];
    int m0 = blockIdx.x * 64;
    int t  = threadIdx.x;
    int r  = t >> 4;
    int cc = t & 15;
    int b0 = r * 4;
    int mm0 = cc * 4;

    float acc[4][4];
    #pragma unroll
    for (int i = 0; i < 4; i++)
        #pragma unroll
        for (int j = 0; j < 4; j++) acc[i][j] = 0.f;

    for (int j0 = 0; j0 < KPIN; j0 += 64) {
        __syncthreads();
        for (int idx = t; idx < 4096; idx += 256) {
            int row = idx >> 6, jj = idx & 63;
            int j = j0 + jj;
            kcs[row * 65 + jj] = (j < KPIN) ? g_kc[row * KPIN + j] : 0.f;
            ws[row * 65 + jj]  = (j < KPIN) ? wproj[(m0 + row) * KPIN + j] : 0.f;
        }
        __syncthreads();
        #pragma unroll 4
        for (int jj = 0; jj < 64; jj++) {
            float kv[4], wv_[4];
            #pragma unroll
            for (int v_ = 0; v_ < 4; v_++) kv[v_] = kcs[(b0 + v_) * 65 + jj];
            #pragma unroll
            for (int u = 0; u < 4; u++) wv_[u] = ws[(mm0 + u) * 65 + jj];
            #pragma unroll
            for (int v_ = 0; v_ < 4; v_++)
                #pragma unroll
                for (int u = 0; u < 4; u++) acc[v_][u] += kv[v_] * wv_[u];
        }
    }
    #pragma unroll
    for (int v_ = 0; v_ < 4; v_++)
        #pragma unroll
        for (int u = 0; u < 4; u++) {
            int m = m0 + mm0 + u;
            g_k[(b0 + v_) * KPOUT + m] = acc[v_][u] + bproj[m];
        }
}

// ---------------------------------------------------------------------------
// Kernel 3: per-b max/min of k
// ---------------------------------------------------------------------------
__global__ __launch_bounds__(256) void kstats_kernel() {
    __shared__ float smax[256], smin[256];
    int b = blockIdx.x, t = threadIdx.x;
    float mx = -1e30f, mn = 1e30f;
    for (int n = t; n < NPOS; n += 256) {
        float kv = g_k[b * NPOS + n];
        mx = fmaxf(mx, kv);
        mn = fminf(mn, kv);
    }
    smax[t] = mx; smin[t] = mn;
    __syncthreads();
    for (int s = 128; s > 0; s >>= 1) {
        if (t < s) {
            smax[t] = fmaxf(smax[t], smax[t + s]);
            smin[t] = fminf(smin[t], smin[t + s]);
        }
        __syncthreads();
    }
    if (t == 0) { g_kmax[b] = smax[0]; g_kmin[b] = smin[0]; }
}

// ---------------------------------------------------------------------------
// Kernel 4: conv2x2 of x with wv -> g_pv and wq -> g_q (f32x2 GEMM).
// De-interleaved x staging + pre-duplicated weight pairs: zero pack2 in the
// hot loop. Dyn smem = 56320 B.
// Layout: As2 ull[64][34] | xs_e f[8][16][36] | xs_o f[8][16][36] | wq2 ull[256]
// ---------------------------------------------------------------------------
__global__ __launch_bounds__(256, 2) void conv_x_kernel(const float* __restrict__ x,
                                                        const float* __restrict__ wq,
                                                        const float* __restrict__ bq,
                                                        const float* __restrict__ wv,
                                                        const float* __restrict__ bv) {
    extern __shared__ char cxsm[];
    ull*   As2  = reinterpret_cast<ull*>(cxsm);          // 2176 ull  (17408 B)
    float* xs_e = reinterpret_cast<float*>(As2 + 2176);  // 4608 f    (18432 B)
    float* xs_o = xs_e + 4608;                           // 4608 f    (18432 B)
    ull*   wq2  = reinterpret_cast<ull*>(xs_o + 4608);   // 256 ull   (2048 B)

    int ntile = blockIdx.x;
    int b     = blockIdx.y;
    int t     = threadIdx.x;
    int g     = t & 31;
    int cog   = t >> 5;
    int il    = g >> 2;
    int quad  = g & 3;

    {
        float w = wq[t];
        wq2[t] = pack2(w, w);
    }

    ull acc[8][4];
    #pragma unroll
    for (int co = 0; co < 8; co++)
        #pragma unroll
        for (int p = 0; p < 4; p++) acc[co][p] = 0ull;
    ull qacc[4] = {0ull, 0ull, 0ull, 0ull};

    for (int chunk = 0; chunk < 8; chunk++) {
        int k0  = chunk * 32;
        int ci0 = chunk * 8;
        __syncthreads();
        #pragma unroll
        for (int s = 0; s < 8; s++) {
            int idx = t + s * 256;
            int co = idx >> 5, kl = idx & 31;
            float w = wv[co * 256 + k0 + kl];
            As2[co * 34 + kl] = pack2(w, w);
        }
        #pragma unroll
        for (int s = 0; s < 32; s++) {
            int idx = t + s * 256;
            int cl = idx >> 10;
            int rem = idx & 1023;
            int r = rem >> 6, col = rem & 63;
            float val = x[(((size_t)b * 64 + ci0 + cl) * 64 + ntile * 16 + r) * 64 + col];
            float* dst = (col & 1) ? xs_o : xs_e;
            dst[cl * 576 + r * 36 + (col >> 1)] = val;
        }
        __syncthreads();

        #pragma unroll
        for (int cl = 0; cl < 8; cl++) {
            #pragma unroll
            for (int a = 0; a < 2; a++) {
                int base = cl * 576 + (2 * il + a) * 36 + quad * 8;
                ulonglong2 e01 = *reinterpret_cast<const ulonglong2*>(&xs_e[base]);
                ulonglong2 e23 = *reinterpret_cast<const ulonglong2*>(&xs_e[base + 4]);
                ulonglong2 o01 = *reinterpret_cast<const ulonglong2*>(&xs_o[base]);
                ulonglong2 o23 = *reinterpret_cast<const ulonglong2*>(&xs_o[base + 4]);
                ull B0[4] = {e01.x, e01.y, e23.x, e23.y};
                ull B1[4] = {o01.x, o01.y, o23.x, o23.y};
                int kl0 = cl * 4 + a * 2;
                #pragma unroll
                for (int co = 0; co < 8; co++) {
                    ulonglong2 wp = *reinterpret_cast<const ulonglong2*>(
                        &As2[(cog * 8 + co) * 34 + kl0]);
                    #pragma unroll
                    for (int p = 0; p < 4; p++) {
                        acc[co][p] = fma2(wp.x, B0[p], acc[co][p]);
                        acc[co][p] = fma2(wp.y, B1[p], acc[co][p]);
                    }
                }
                if (cog == 0) {
                    ulonglong2 wqp = *reinterpret_cast<const ulonglong2*>(&wq2[k0 + kl0]);
                    #pragma unroll
                    for (int p = 0; p < 4; p++) {
                        qacc[p] = fma2(wqp.x, B0[p], qacc[p]);
                        qacc[p] = fma2(wqp.y, B1[p], qacc[p]);
                    }
                }
            }
        }
    }

    int nbase = ntile * 256 + il * 32 + quad * 8;
    #pragma unroll
    for (int co = 0; co < 8; co++) {
        int c = cog * 8 + co;
        float bvv = bv[c];
        float lo0, hi0, lo1, hi1, lo2, hi2, lo3, hi3;
        unpack2(acc[co][0], lo0, hi0);
        unpack2(acc[co][1], lo1, hi1);
        unpack2(acc[co][2], lo2, hi2);
        unpack2(acc[co][3], lo3, hi3);
        float* dst = &g_pv[((size_t)b * 64 + c) * NPOS + nbase];
        *reinterpret_cast<float4*>(dst) =
            make_float4(lo0 + bvv, hi0 + bvv, lo1 + bvv, hi1 + bvv);
        *reinterpret_cast<float4*>(dst + 4) =
            make_float4(lo2 + bvv, hi2 + bvv, lo3 + bvv, hi3 + bvv);
    }
    if (cog == 0) {
        float bqq = bq[0];
        float lo0, hi0, lo1, hi1, lo2, hi2, lo3, hi3;
        unpack2(qacc[0], lo0, hi0);
        unpack2(qacc[1], lo1, hi1);
        unpack2(qacc[2], lo2, hi2);
        unpack2(qacc[3], lo3, hi3);
        float* dst = &g_q[b * NPOS + nbase];
        *reinterpret_cast<float4*>(dst) =
            make_float4(lo0 + bqq, hi0 + bqq, lo1 + bqq, hi1 + bqq);
        *reinterpret_cast<float4*>(dst + 4) =
            make_float4(lo2 + bqq, hi2 + bqq, lo3 + bqq, hi3 + bqq);
    }
}

// ---------------------------------------------------------------------------
// Kernel 5: fused softmax (rank-1) + attn write + tf32 MMA GEMM.
// Writes g_outT[b][m][c] (transposed) for the upsample MMA consumer.
// grid (8, 64), 256 threads, dyn smem = 58880 B
// ---------------------------------------------------------------------------
__global__ __launch_bounds__(256, 2) void attn_kernel(float* __restrict__ attn_out,
                                                      int has_attn) {
    extern __shared__ float sm[];
    float*    ks   = sm;              // 1024
    float*    sarr = ks + 1024;       // 128
    float*    rm   = sarr + 128;      // 128
    float*    invZ = rm + 128;        // 128
    float*    zp   = invZ + 128;      // 256
    uint32_t* pvs  = reinterpret_cast<uint32_t*>(zp + 256);   // 64*68
    uint32_t* es   = pvs + 4352;      // 128*68

    const float L2E = 1.4426950408889634f;
    int mt = blockIdx.x;
    int b  = blockIdx.y;
    int m0 = mt * 128;
    int t  = threadIdx.x;
    int wid = t >> 5;
    int l   = t & 31;
    int g   = l >> 2;
    int tg  = l & 3;

    for (int n = t; n < NPOS; n += 256) ks[n] = g_k[b * NPOS + n];
    if (t < 128) {
        float s = g_q[b * NPOS + m0 + t] * 0.03125f;   // 1/sqrt(1024)
        sarr[t] = s;
        rm[t] = (s >= 0.f) ? s * g_kmax[b] : s * g_kmin[b];
    }
    __syncthreads();

    // Pass 1: Z
    {
        int m = t & 127;
        int h = t >> 7;
        float s = sarr[m], rmm = rm[m];
        const float* kp = ks + h * 512;
        float p0 = 0.f, p1 = 0.f, p2 = 0.f, p3 = 0.f;
        #pragma unroll 4
        for (int n = 0; n < 512; n += 4) {
            p0 += ex2f((s * kp[n + 0] - rmm) * L2E);
            p1 += ex2f((s * kp[n + 1] - rmm) * L2E);
            p2 += ex2f((s * kp[n + 2] - rmm) * L2E);
            p3 += ex2f((s * kp[n + 3] - rmm) * L2E);
        }
        zp[h * 128 + m] = (p0 + p1) + (p2 + p3);
    }
    __syncthreads();
    if (t < 128) invZ[t] = 1.f / (zp[t] + zp[128 + t]);

    float acc[4][2][4];
    #pragma unroll
    for (int ct = 0; ct < 4; ct++)
        #pragma unroll
        for (int nt = 0; nt < 2; nt++)
            #pragma unroll
            for (int u = 0; u < 4; u++) acc[ct][nt][u] = 0.f;

    int mbase = wid * 16;

    for (int ch = 0; ch < 16; ch++) {
        int nn0 = ch * 64;
        __syncthreads();
        #pragma unroll
        for (int s = 0; s < 16; s++) {
            int idx = t + s * 256;
            int c = idx >> 6, nn = idx & 63;
            pvs[c * 68 + nn] = tf32r(g_pv[((size_t)b * 64 + c) * NPOS + nn0 + nn]);
        }
        for (int m = wid; m < 128; m += 8) {
            float s = sarr[m], rmm = rm[m], iz = invZ[m];
            #pragma unroll
            for (int seg = 0; seg < 2; seg++) {
                int nn = seg * 32 + l;
                float val = ex2f((s * ks[nn0 + nn] - rmm) * L2E) * iz;
                es[m * 68 + nn] = tf32r(val);
                if (has_attn)
                    attn_out[(size_t)(b * 1024 + m0 + m) * 1024 + nn0 + nn] = val;
            }
        }
        __syncthreads();

        #pragma unroll
        for (int ks8 = 0; ks8 < 8; ks8++) {
            int kk = ks8 * 8 + tg;
            uint32_t afr[4][4];
            #pragma unroll
            for (int ct = 0; ct < 4; ct++) {
                const uint32_t* ap = &pvs[(ct * 16 + g) * 68 + kk];
                afr[ct][0] = ap[0];
                afr[ct][1] = ap[8 * 68];
                afr[ct][2] = ap[4];
                afr[ct][3] = ap[8 * 68 + 4];
            }
            uint32_t bfr[2][2];
            #pragma unroll
            for (int nt = 0; nt < 2; nt++) {
                const uint32_t* bp = &es[(mbase + nt * 8 + g) * 68 + kk];
                bfr[nt][0] = bp[0];
                bfr[nt][1] = bp[4];
            }
            #pragma unroll
            for (int ct = 0; ct < 4; ct++)
                #pragma unroll
                for (int nt = 0; nt < 2; nt++)
                    mma_tf32(acc[ct][nt][0], acc[ct][nt][1], acc[ct][nt][2], acc[ct][nt][3],
                             afr[ct][0], afr[ct][1], afr[ct][2], afr[ct][3],
                             bfr[nt][0], bfr[nt][1]);
        }
    }

    // write transposed: g_outT[b][m][c]
    #pragma unroll
    for (int ct = 0; ct < 4; ct++) {
        #pragma unroll
        for (int nt = 0; nt < 2; nt++) {
            int m = m0 + mbase + nt * 8 + 2 * tg;
            int c_lo = ct * 16 + g;
            size_t r0 = ((size_t)b * 1024 + m) * 64;
            size_t r1 = r0 + 64;
            g_outT[r0 + c_lo]     = acc[ct][nt][0];
            g_outT[r1 + c_lo]     = acc[ct][nt][1];
            g_outT[r0 + c_lo + 8] = acc[ct][nt][2];
            g_outT[r1 + c_lo + 8] = acc[ct][nt][3];
        }
    }
}

// ---------------------------------------------------------------------------
// Kernel 6: ConvTranspose2d via tf32 MMA.
// up[b,d,2i+a,2j+bb] = sum_c outT[n=(i,j)][c] * wu[c][d*4+a*2+bb] + bu[d]
// A = outT chunk [128 n x 64 c], B = wuT [256 m x 64 c], m = d*4+ab.
// D-frag thread pair (2tg,2tg+1) = same d, same a, bb={0,1} -> float2 STG.
// grid (8, 64), 256 threads, dyn smem = 105472 B.
// ---------------------------------------------------------------------------
__global__ __launch_bounds__(256, 2) void upsample_kernel(const float* __restrict__ wu,
                                                          const float* __restrict__ bu,
                                                          float* __restrict__ up) {
    extern __shared__ uint32_t usm[];
    uint32_t* As = usm;            // 128*68 = 8704  (34816 B)
    uint32_t* Ws = As + 8704;      // 256*69 = 17664 (70656 B)

    int ib = blockIdx.x;           // n0 = ib*128 -> i rows ib*4..ib*4+3
    int b  = blockIdx.y;
    int n0 = ib * 128;
    int t  = threadIdx.x;
    int w  = t >> 5;
    int l  = t & 31;
    int g  = l >> 2;
    int tg = l & 3;

    // stage A (outT -> tf32)
    #pragma unroll
    for (int s = 0; s < 32; s++) {
        int idx = t + s * 256;
        int n = idx >> 6, c = idx & 63;
        As[n * 68 + c] = tf32r(g_outT[((size_t)b * 1024 + n0 + n) * 64 + c]);
    }
    // stage Ws (wu transposed -> tf32)
    #pragma unroll
    for (int s = 0; s < 64; s++) {
        int idx = t + s * 256;
        int m = idx & 255, c = idx >> 8;
        Ws[m * 69 + c] = tf32r(wu[c * 256 + m]);
    }
    __syncthreads();

    // preload A frags for this warp's 16 n-rows
    uint32_t af[8][4];
    #pragma unroll
    for (int k8 = 0; k8 < 8; k8++) {
        const uint32_t* ap = &As[(w * 16 + g) * 68 + k8 * 8 + tg];
        af[k8][0] = ap[0];
        af[k8][1] = ap[8 * 68];
        af[k8][2] = ap[4];
        af[k8][3] = ap[8 * 68 + 4];
    }

    int n1 = n0 + w * 16 + g;
    int i1 = n1 >> 5, j1 = n1 & 31;
    int n2 = n1 + 8;
    int i2 = n2 >> 5, j2 = n2 & 31;

    for (int mtile = 0; mtile < 32; mtile++) {
        float d0 = 0.f, d1 = 0.f, d2 = 0.f, d3 = 0.f;
        #pragma unroll
        for (int k8 = 0; k8 < 8; k8++) {
            const uint32_t* bp = &Ws[(mtile * 8 + g) * 69 + k8 * 8 + tg];
            mma_tf32(d0, d1, d2, d3,
                     af[k8][0], af[k8][1], af[k8][2], af[k8][3],
                     bp[0], bp[4]);
        }
        int mm = mtile * 8 + 2 * tg;       // (and mm+1)
        int dd = mm >> 2;
        int a  = (mm >> 1) & 1;
        float bud = __ldg(&bu[dd]);
        size_t base = ((size_t)(b * 64 + dd) * 64);
        float* r1p = &up[(base + 2 * i1 + a) * 64 + 2 * j1];
        float* r2p = &up[(base + 2 * i2 + a) * 64 + 2 * j2];
        *reinterpret_cast<float2*>(r1p) = make_float2(d0 + bud, d1 + bud);
        *reinterpret_cast<float2*>(r2p) = make_float2(d2 + bud, d3 + bud);
    }
}

// ---------------------------------------------------------------------------
extern "C" void kernel_launch(void* const* d_in, const int* in_sizes, int n_in,
                              void* d_out, int out_size) {
    const float* x     = (const float*)d_in[0];
    const float* v     = (const float*)d_in[1];
    const float* wq    = (const float*)d_in[2];
    const float* bq    = (const float*)d_in[3];
    const float* wk    = (const float*)d_in[4];
    const float* bk    = (const float*)d_in[5];
    const float* wv    = (const float*)d_in[6];
    const float* bv    = (const float*)d_in[7];
    const float* wu    = (const float*)d_in[8];
    const float* bu    = (const float*)d_in[9];
    const float* wproj = (const float*)d_in[10];
    const float* bproj = (const float*)d_in[11];

    float* up_out   = (float*)d_out;
    int has_attn    = (out_size > UP_ELEMS) ? 1 : 0;
    float* attn_out = up_out + UP_ELEMS;

    cudaFuncSetAttribute(conv_x_kernel,   cudaFuncAttributeMaxDynamicSharedMemorySize, 56320);
    cudaFuncSetAttribute(attn_kernel,     cudaFuncAttributeMaxDynamicSharedMemorySize, 58880);
    cudaFuncSetAttribute(upsample_kernel, cudaFuncAttributeMaxDynamicSharedMemorySize, 105472);

    conv_v_kernel<<<dim3(42, 64), 256>>>(v, wk, bk);
    kproj_kernel<<<16, 256>>>(wproj, bproj);
    kstats_kernel<<<64, 256>>>();
    conv_x_kernel<<<dim3(4, 64), 256, 56320>>>(x, wq, bq, wv, bv);
    attn_kernel<<<dim3(8, 64), 256, 58880>>>(attn_out, has_attn);
    upsample_kernel<<<dim3(8, 64), 256, 105472>>>(wu, bu, up_out);
}

// round 5
// speedup vs baseline: 2.0830x; 1.0637x over previous
#include <cuda_runtime.h>
#include <cuda_bf16.h>
#include <cstdint>

// Problem constants
#define BATCH 64
#define CH    64
#define HH    64
#define WW    64
#define NPOS  1024        // 32*32
#define KPIN  1134        // 42*27
#define KPOUT 1024
#define UP_ELEMS (BATCH*CH*HH*WW)          // 16777216
#define ATTN_ELEMS (BATCH*NPOS*NPOS)       // 67108864

// Scratch (device globals; no allocation)
__device__ float g_pv[BATCH * CH * NPOS];     // [b][c][n]
__device__ float g_outT[BATCH * NPOS * CH];   // [b][m][c]  (transposed!)
__device__ float g_q[BATCH * NPOS];
__device__ float g_k[BATCH * NPOS];
__device__ float g_kc[BATCH * KPIN];
__device__ float g_kmax[BATCH];
__device__ float g_kmin[BATCH];

typedef unsigned long long ull;

__device__ __forceinline__ float ex2f(float x) {
    float y;
    asm("ex2.approx.ftz.f32 %0, %1;" : "=f"(y) : "f"(x));
    return y;
}
__device__ __forceinline__ float lg2f(float x) {
    float y;
    asm("lg2.approx.ftz.f32 %0, %1;" : "=f"(y) : "f"(x));
    return y;
}
__device__ __forceinline__ ull pack2(float lo, float hi) {
    ull r;
    asm("mov.b64 %0, {%1, %2};" : "=l"(r) : "f"(lo), "f"(hi));
    return r;
}
__device__ __forceinline__ ull fma2(ull a, ull b, ull c) {
    ull d;
    asm("fma.rn.f32x2 %0, %1, %2, %3;" : "=l"(d) : "l"(a), "l"(b), "l"(c));
    return d;
}
__device__ __forceinline__ void unpack2(ull r, float& lo, float& hi) {
    asm("mov.b64 {%0, %1}, %2;" : "=f"(lo), "=f"(hi) : "l"(r));
}
__device__ __forceinline__ uint32_t tf32r(float x) {
    uint32_t r;
    asm("cvt.rna.tf32.f32 %0, %1;" : "=r"(r) : "f"(x));
    return r;
}
__device__ __forceinline__ void mma_tf32(float& d0, float& d1, float& d2, float& d3,
                                         uint32_t a0, uint32_t a1, uint32_t a2, uint32_t a3,
                                         uint32_t b0, uint32_t b1) {
    asm("mma.sync.aligned.m16n8k8.row.col.f32.tf32.tf32.f32 "
        "{%0,%1,%2,%3}, {%4,%5,%6,%7}, {%8,%9}, {%0,%1,%2,%3};"
        : "+f"(d0), "+f"(d1), "+f"(d2), "+f"(d3)
        : "r"(a0), "r"(a1), "r"(a2), "r"(a3), "r"(b0), "r"(b1));
}

// ---------------------------------------------------------------------------
// Kernel 1: conv2x2(v, wk) -> g_kc[b][ii*27+jj]
// 216 active compute threads (27 jj x 8 c-groups) + tree reduce.
// ---------------------------------------------------------------------------
__global__ __launch_bounds__(256) void conv_v_kernel(const float* __restrict__ v,
                                                     const float* __restrict__ wk,
                                                     const float* __restrict__ bk) {
    __shared__ float vs[64 * 2 * 54];
    __shared__ float wks[256];
    __shared__ float part[8][28];
    int ii = blockIdx.x;
    int b  = blockIdx.y;
    int t  = threadIdx.x;

    wks[t] = wk[t];
    for (int idx = t; idx < 64 * 2 * 54; idx += 256) {
        int c   = idx / 108;
        int rem = idx - c * 108;
        int a   = rem / 54;
        int col = rem - a * 54;
        vs[idx] = v[((b * 64 + c) * 84 + (2 * ii + a)) * 54 + col];
    }
    __syncthreads();

    if (t < 216) {
        int jj = t % 27;
        int cg = t / 27;
        float acc = 0.f;
        #pragma unroll
        for (int cc = 0; cc < 8; cc++) {
            int c = cg * 8 + cc;
            #pragma unroll
            for (int a = 0; a < 2; a++) {
                float x0 = vs[(c * 2 + a) * 54 + 2 * jj + 0];
                float x1 = vs[(c * 2 + a) * 54 + 2 * jj + 1];
                acc += x0 * wks[c * 4 + a * 2 + 0] + x1 * wks[c * 4 + a * 2 + 1];
            }
        }
        part[cg][jj] = acc;
    }
    __syncthreads();
    if (t < 27) {
        float s = bk[0];
        #pragma unroll
        for (int cg = 0; cg < 8; cg++) s += part[cg][t];
        g_kc[b * KPIN + ii * 27 + t] = s;
    }
}

// ---------------------------------------------------------------------------
// Kernel 2: k[b][m] = sum_j g_kc[b][j] * wproj[m][j] + bproj[m]
// ---------------------------------------------------------------------------
__global__ __launch_bounds__(256) void kproj_kernel(const float* __restrict__ wproj,
                                                    const float* __restrict__ bproj) {
    __shared__ float kcs[64 * 65];
    __shared__ float ws[64 * 65];
    int m0 = blockIdx.x * 64;
    int t  = threadIdx.x;
    int r  = t >> 4;
    int cc = t & 15;
    int b0 = r * 4;
    int mm0 = cc * 4;

    float acc[4][4];
    #pragma unroll
    for (int i = 0; i < 4; i++)
        #pragma unroll
        for (int j = 0; j < 4; j++) acc[i][j] = 0.f;

    for (int j0 = 0; j0 < KPIN; j0 += 64) {
        __syncthreads();
        for (int idx = t; idx < 4096; idx += 256) {
            int row = idx >> 6, jj = idx & 63;
            int j = j0 + jj;
            kcs[row * 65 + jj] = (j < KPIN) ? g_kc[row * KPIN + j] : 0.f;
            ws[row * 65 + jj]  = (j < KPIN) ? wproj[(m0 + row) * KPIN + j] : 0.f;
        }
        __syncthreads();
        #pragma unroll 4
        for (int jj = 0; jj < 64; jj++) {
            float kv[4], wv_[4];
            #pragma unroll
            for (int v_ = 0; v_ < 4; v_++) kv[v_] = kcs[(b0 + v_) * 65 + jj];
            #pragma unroll
            for (int u = 0; u < 4; u++) wv_[u] = ws[(mm0 + u) * 65 + jj];
            #pragma unroll
            for (int v_ = 0; v_ < 4; v_++)
                #pragma unroll
                for (int u = 0; u < 4; u++) acc[v_][u] += kv[v_] * wv_[u];
        }
    }
    #pragma unroll
    for (int v_ = 0; v_ < 4; v_++)
        #pragma unroll
        for (int u = 0; u < 4; u++) {
            int m = m0 + mm0 + u;
            g_k[(b0 + v_) * KPOUT + m] = acc[v_][u] + bproj[m];
        }
}

// ---------------------------------------------------------------------------
// Kernel 3: per-b max/min of k
// ---------------------------------------------------------------------------
__global__ __launch_bounds__(256) void kstats_kernel() {
    __shared__ float smax[256], smin[256];
    int b = blockIdx.x, t = threadIdx.x;
    float mx = -1e30f, mn = 1e30f;
    for (int n = t; n < NPOS; n += 256) {
        float kv = g_k[b * NPOS + n];
        mx = fmaxf(mx, kv);
        mn = fminf(mn, kv);
    }
    smax[t] = mx; smin[t] = mn;
    __syncthreads();
    for (int s = 128; s > 0; s >>= 1) {
        if (t < s) {
            smax[t] = fmaxf(smax[t], smax[t + s]);
            smin[t] = fminf(smin[t], smin[t + s]);
        }
        __syncthreads();
    }
    if (t == 0) { g_kmax[b] = smax[0]; g_kmin[b] = smin[0]; }
}

// ---------------------------------------------------------------------------
// Kernel 4: conv2x2 of x with wv -> g_pv and wq -> g_q (f32x2 GEMM).
// ---------------------------------------------------------------------------
__global__ __launch_bounds__(256, 2) void conv_x_kernel(const float* __restrict__ x,
                                                        const float* __restrict__ wq,
                                                        const float* __restrict__ bq,
                                                        const float* __restrict__ wv,
                                                        const float* __restrict__ bv) {
    extern __shared__ char cxsm[];
    ull*   As2  = reinterpret_cast<ull*>(cxsm);          // 2176 ull
    float* xs_e = reinterpret_cast<float*>(As2 + 2176);  // 4608 f
    float* xs_o = xs_e + 4608;                           // 4608 f
    ull*   wq2  = reinterpret_cast<ull*>(xs_o + 4608);   // 256 ull

    int ntile = blockIdx.x;
    int b     = blockIdx.y;
    int t     = threadIdx.x;
    int g     = t & 31;
    int cog   = t >> 5;
    int il    = g >> 2;
    int quad  = g & 3;

    {
        float w = wq[t];
        wq2[t] = pack2(w, w);
    }

    ull acc[8][4];
    #pragma unroll
    for (int co = 0; co < 8; co++)
        #pragma unroll
        for (int p = 0; p < 4; p++) acc[co][p] = 0ull;
    ull qacc[4] = {0ull, 0ull, 0ull, 0ull};

    for (int chunk = 0; chunk < 8; chunk++) {
        int k0  = chunk * 32;
        int ci0 = chunk * 8;
        __syncthreads();
        #pragma unroll
        for (int s = 0; s < 8; s++) {
            int idx = t + s * 256;
            int co = idx >> 5, kl = idx & 31;
            float w = wv[co * 256 + k0 + kl];
            As2[co * 34 + kl] = pack2(w, w);
        }
        #pragma unroll
        for (int s = 0; s < 32; s++) {
            int idx = t + s * 256;
            int cl = idx >> 10;
            int rem = idx & 1023;
            int r = rem >> 6, col = rem & 63;
            float val = x[(((size_t)b * 64 + ci0 + cl) * 64 + ntile * 16 + r) * 64 + col];
            float* dst = (col & 1) ? xs_o : xs_e;
            dst[cl * 576 + r * 36 + (col >> 1)] = val;
        }
        __syncthreads();

        #pragma unroll
        for (int cl = 0; cl < 8; cl++) {
            #pragma unroll
            for (int a = 0; a < 2; a++) {
                int base = cl * 576 + (2 * il + a) * 36 + quad * 8;
                ulonglong2 e01 = *reinterpret_cast<const ulonglong2*>(&xs_e[base]);
                ulonglong2 e23 = *reinterpret_cast<const ulonglong2*>(&xs_e[base + 4]);
                ulonglong2 o01 = *reinterpret_cast<const ulonglong2*>(&xs_o[base]);
                ulonglong2 o23 = *reinterpret_cast<const ulonglong2*>(&xs_o[base + 4]);
                ull B0[4] = {e01.x, e01.y, e23.x, e23.y};
                ull B1[4] = {o01.x, o01.y, o23.x, o23.y};
                int kl0 = cl * 4 + a * 2;
                #pragma unroll
                for (int co = 0; co < 8; co++) {
                    ulonglong2 wp = *reinterpret_cast<const ulonglong2*>(
                        &As2[(cog * 8 + co) * 34 + kl0]);
                    #pragma unroll
                    for (int p = 0; p < 4; p++) {
                        acc[co][p] = fma2(wp.x, B0[p], acc[co][p]);
                        acc[co][p] = fma2(wp.y, B1[p], acc[co][p]);
                    }
                }
                if (cog == 0) {
                    ulonglong2 wqp = *reinterpret_cast<const ulonglong2*>(&wq2[k0 + kl0]);
                    #pragma unroll
                    for (int p = 0; p < 4; p++) {
                        qacc[p] = fma2(wqp.x, B0[p], qacc[p]);
                        qacc[p] = fma2(wqp.y, B1[p], qacc[p]);
                    }
                }
            }
        }
    }

    int nbase = ntile * 256 + il * 32 + quad * 8;
    #pragma unroll
    for (int co = 0; co < 8; co++) {
        int c = cog * 8 + co;
        float bvv = bv[c];
        float lo0, hi0, lo1, hi1, lo2, hi2, lo3, hi3;
        unpack2(acc[co][0], lo0, hi0);
        unpack2(acc[co][1], lo1, hi1);
        unpack2(acc[co][2], lo2, hi2);
        unpack2(acc[co][3], lo3, hi3);
        float* dst = &g_pv[((size_t)b * 64 + c) * NPOS + nbase];
        *reinterpret_cast<float4*>(dst) =
            make_float4(lo0 + bvv, hi0 + bvv, lo1 + bvv, hi1 + bvv);
        *reinterpret_cast<float4*>(dst + 4) =
            make_float4(lo2 + bvv, hi2 + bvv, lo3 + bvv, hi3 + bvv);
    }
    if (cog == 0) {
        float bqq = bq[0];
        float lo0, hi0, lo1, hi1, lo2, hi2, lo3, hi3;
        unpack2(qacc[0], lo0, hi0);
        unpack2(qacc[1], lo1, hi1);
        unpack2(qacc[2], lo2, hi2);
        unpack2(qacc[3], lo3, hi3);
        float* dst = &g_q[b * NPOS + nbase];
        *reinterpret_cast<float4*>(dst) =
            make_float4(lo0 + bqq, hi0 + bqq, lo1 + bqq, hi1 + bqq);
        *reinterpret_cast<float4*>(dst + 4) =
            make_float4(lo2 + bqq, hi2 + bqq, lo3 + bqq, hi3 + bqq);
    }
}

// ---------------------------------------------------------------------------
// Kernel 5: fused softmax (rank-1) + attn write + tf32 MMA GEMM.
// 256 m-rows/block, grid (4, 64). B-fragments (exp values) computed directly
// in registers in the m16n8k8 B layout: no es smem, attn STG from regs,
// normalization folded into the exponent. Writes g_outT[b][m][c].
// Warp tile: 32 m x 64 c. Static smem = 23552 B.
// ---------------------------------------------------------------------------
__global__ __launch_bounds__(256, 2) void attn_kernel(float* __restrict__ attn_out,
                                                      int has_attn) {
    __shared__ float ks[1024];
    __shared__ float sLs[256];
    __shared__ float offs[256];
    __shared__ uint32_t pvs[64 * 68];

    const float L2E = 1.4426950408889634f;
    int mt = blockIdx.x;               // 0..3
    int b  = blockIdx.y;
    int m0 = mt * 256;
    int t  = threadIdx.x;
    int w  = t >> 5;
    int l  = t & 31;
    int g  = l >> 2;
    int tg = l & 3;

    for (int n = t; n < NPOS; n += 256) ks[n] = g_k[b * NPOS + n];
    __syncthreads();

    // Pass 1: per-thread m = m0 + t, compute Z and fold everything into
    // (sL, off):   attn = exp2( sL*k + off )
    {
        float s   = g_q[b * NPOS + m0 + t] * 0.03125f;   // 1/sqrt(1024)
        float rm  = (s >= 0.f) ? s * g_kmax[b] : s * g_kmin[b];
        float sL  = s * L2E;
        float rmL = rm * L2E;
        float p0 = 0.f, p1 = 0.f, p2 = 0.f, p3 = 0.f;
        #pragma unroll 4
        for (int n = 0; n < 1024; n += 4) {
            p0 += ex2f(fmaf(sL, ks[n + 0], -rmL));
            p1 += ex2f(fmaf(sL, ks[n + 1], -rmL));
            p2 += ex2f(fmaf(sL, ks[n + 2], -rmL));
            p3 += ex2f(fmaf(sL, ks[n + 3], -rmL));
        }
        float Z = (p0 + p1) + (p2 + p3);
        sLs[t]  = sL;
        offs[t] = -rmL - lg2f(Z);
    }
    __syncthreads();

    // per-thread softmax params for its 4 B-frag m-rows
    int mbase = w * 32;
    float sl[4], of[4];
    #pragma unroll
    for (int nt = 0; nt < 4; nt++) {
        int mm = mbase + nt * 8 + g;
        sl[nt] = sLs[mm];
        of[nt] = offs[mm];
    }

    float acc[4][4][4];   // [ct][nt][reg]
    #pragma unroll
    for (int ct = 0; ct < 4; ct++)
        #pragma unroll
        for (int nt = 0; nt < 4; nt++)
            #pragma unroll
            for (int u = 0; u < 4; u++) acc[ct][nt][u] = 0.f;

    for (int ch = 0; ch < 16; ch++) {
        int nn0 = ch * 64;
        __syncthreads();
        // stage pv chunk as tf32 bits
        #pragma unroll
        for (int s = 0; s < 16; s++) {
            int idx = t + s * 256;
            int c = idx >> 6, nn = idx & 63;
            pvs[c * 68 + nn] = tf32r(g_pv[((size_t)b * 64 + c) * NPOS + nn0 + nn]);
        }
        __syncthreads();

        #pragma unroll
        for (int ks8 = 0; ks8 < 8; ks8++) {
            int kk = ks8 * 8 + tg;
            float k0v = ks[nn0 + kk];
            float k4v = ks[nn0 + kk + 4];

            uint32_t afr[4][4];
            #pragma unroll
            for (int ct = 0; ct < 4; ct++) {
                const uint32_t* ap = &pvs[(ct * 16 + g) * 68 + kk];
                afr[ct][0] = ap[0];
                afr[ct][1] = ap[8 * 68];
                afr[ct][2] = ap[4];
                afr[ct][3] = ap[8 * 68 + 4];
            }

            #pragma unroll
            for (int nt = 0; nt < 4; nt++) {
                float e0 = ex2f(fmaf(sl[nt], k0v, of[nt]));
                float e4 = ex2f(fmaf(sl[nt], k4v, of[nt]));
                if (has_attn) {
                    int mrow = m0 + mbase + nt * 8 + g;
                    size_t base = ((size_t)(b * 1024 + mrow)) * 1024 + nn0;
                    attn_out[base + kk]     = e0;
                    attn_out[base + kk + 4] = e4;
                }
                uint32_t b0 = tf32r(e0);
                uint32_t b1 = tf32r(e4);
                #pragma unroll
                for (int ct = 0; ct < 4; ct++)
                    mma_tf32(acc[ct][nt][0], acc[ct][nt][1], acc[ct][nt][2], acc[ct][nt][3],
                             afr[ct][0], afr[ct][1], afr[ct][2], afr[ct][3],
                             b0, b1);
            }
        }
    }

    // write transposed: g_outT[b][m][c]
    #pragma unroll
    for (int ct = 0; ct < 4; ct++) {
        #pragma unroll
        for (int nt = 0; nt < 4; nt++) {
            int m = m0 + mbase + nt * 8 + 2 * tg;
            int c_lo = ct * 16 + g;
            size_t r0 = ((size_t)b * 1024 + m) * 64;
            size_t r1 = r0 + 64;
            g_outT[r0 + c_lo]     = acc[ct][nt][0];
            g_outT[r1 + c_lo]     = acc[ct][nt][1];
            g_outT[r0 + c_lo + 8] = acc[ct][nt][2];
            g_outT[r1 + c_lo + 8] = acc[ct][nt][3];
        }
    }
}

// ---------------------------------------------------------------------------
// Kernel 6: ConvTranspose2d via tf32 MMA.
// grid (8, 64), 256 threads, dyn smem = 105472 B.
// ---------------------------------------------------------------------------
__global__ __launch_bounds__(256, 2) void upsample_kernel(const float* __restrict__ wu,
                                                          const float* __restrict__ bu,
                                                          float* __restrict__ up) {
    extern __shared__ uint32_t usm[];
    uint32_t* As = usm;            // 128*68
    uint32_t* Ws = As + 8704;      // 256*69

    int ib = blockIdx.x;
    int b  = blockIdx.y;
    int n0 = ib * 128;
    int t  = threadIdx.x;
    int w  = t >> 5;
    int l  = t & 31;
    int g  = l >> 2;
    int tg = l & 3;

    #pragma unroll
    for (int s = 0; s < 32; s++) {
        int idx = t + s * 256;
        int n = idx >> 6, c = idx & 63;
        As[n * 68 + c] = tf32r(g_outT[((size_t)b * 1024 + n0 + n) * 64 + c]);
    }
    #pragma unroll
    for (int s = 0; s < 64; s++) {
        int idx = t + s * 256;
        int m = idx & 255, c = idx >> 8;
        Ws[m * 69 + c] = tf32r(wu[c * 256 + m]);
    }
    __syncthreads();

    uint32_t af[8][4];
    #pragma unroll
    for (int k8 = 0; k8 < 8; k8++) {
        const uint32_t* ap = &As[(w * 16 + g) * 68 + k8 * 8 + tg];
        af[k8][0] = ap[0];
        af[k8][1] = ap[8 * 68];
        af[k8][2] = ap[4];
        af[k8][3] = ap[8 * 68 + 4];
    }

    int n1 = n0 + w * 16 + g;
    int i1 = n1 >> 5, j1 = n1 & 31;
    int n2 = n1 + 8;
    int i2 = n2 >> 5, j2 = n2 & 31;

    for (int mtile = 0; mtile < 32; mtile++) {
        float d0 = 0.f, d1 = 0.f, d2 = 0.f, d3 = 0.f;
        #pragma unroll
        for (int k8 = 0; k8 < 8; k8++) {
            const uint32_t* bp = &Ws[(mtile * 8 + g) * 69 + k8 * 8 + tg];
            mma_tf32(d0, d1, d2, d3,
                     af[k8][0], af[k8][1], af[k8][2], af[k8][3],
                     bp[0], bp[4]);
        }
        int mm = mtile * 8 + 2 * tg;
        int dd = mm >> 2;
        int a  = (mm >> 1) & 1;
        float bud = __ldg(&bu[dd]);
        size_t base = ((size_t)(b * 64 + dd) * 64);
        float* r1p = &up[(base + 2 * i1 + a) * 64 + 2 * j1];
        float* r2p = &up[(base + 2 * i2 + a) * 64 + 2 * j2];
        *reinterpret_cast<float2*>(r1p) = make_float2(d0 + bud, d1 + bud);
        *reinterpret_cast<float2*>(r2p) = make_float2(d2 + bud, d3 + bud);
    }
}

// ---------------------------------------------------------------------------
extern "C" void kernel_launch(void* const* d_in, const int* in_sizes, int n_in,
                              void* d_out, int out_size) {
    const float* x     = (const float*)d_in[0];
    const float* v     = (const float*)d_in[1];
    const float* wq    = (const float*)d_in[2];
    const float* bq    = (const float*)d_in[3];
    const float* wk    = (const float*)d_in[4];
    const float* bk    = (const float*)d_in[5];
    const float* wv    = (const float*)d_in[6];
    const float* bv    = (const float*)d_in[7];
    const float* wu    = (const float*)d_in[8];
    const float* bu    = (const float*)d_in[9];
    const float* wproj = (const float*)d_in[10];
    const float* bproj = (const float*)d_in[11];

    float* up_out   = (float*)d_out;
    int has_attn    = (out_size > UP_ELEMS) ? 1 : 0;
    float* attn_out = up_out + UP_ELEMS;

    cudaFuncSetAttribute(conv_x_kernel,   cudaFuncAttributeMaxDynamicSharedMemorySize, 56320);
    cudaFuncSetAttribute(upsample_kernel, cudaFuncAttributeMaxDynamicSharedMemorySize, 105472);

    conv_v_kernel<<<dim3(42, 64), 256>>>(v, wk, bk);
    kproj_kernel<<<16, 256>>>(wproj, bproj);
    kstats_kernel<<<64, 256>>>();
    conv_x_kernel<<<dim3(4, 64), 256, 56320>>>(x, wq, bq, wv, bv);
    attn_kernel<<<dim3(4, 64), 256>>>(attn_out, has_attn);
    upsample_kernel<<<dim3(8, 64), 256, 105472>>>(wu, bu, up_out);
}

// round 6
// speedup vs baseline: 2.2880x; 1.0984x over previous
#include <cuda_runtime.h>
#include <cuda_bf16.h>
#include <cstdint>

// Problem constants
#define BATCH 64
#define CH    64
#define HH    64
#define WW    64
#define NPOS  1024        // 32*32
#define KPIN  1134        // 42*27
#define KPOUT 1024
#define UP_ELEMS (BATCH*CH*HH*WW)          // 16777216
#define ATTN_ELEMS (BATCH*NPOS*NPOS)       // 67108864

// Scratch (device globals; no allocation)
__device__ float g_pv[BATCH * CH * NPOS];     // [b][c][n]
__device__ float g_outT[BATCH * NPOS * CH];   // [b][m][c]  (transposed!)
__device__ float g_q[BATCH * NPOS];
__device__ float g_k[BATCH * NPOS];
__device__ float g_kc[BATCH * KPIN];
__device__ float g_kmax[BATCH];
__device__ float g_kmin[BATCH];

typedef unsigned long long ull;

__device__ __forceinline__ float ex2f(float x) {
    float y;
    asm("ex2.approx.ftz.f32 %0, %1;" : "=f"(y) : "f"(x));
    return y;
}
__device__ __forceinline__ float lg2f(float x) {
    float y;
    asm("lg2.approx.ftz.f32 %0, %1;" : "=f"(y) : "f"(x));
    return y;
}
__device__ __forceinline__ uint32_t tf32r(float x) {
    uint32_t r;
    asm("cvt.rna.tf32.f32 %0, %1;" : "=r"(r) : "f"(x));
    return r;
}
__device__ __forceinline__ void mma_tf32(float& d0, float& d1, float& d2, float& d3,
                                         uint32_t a0, uint32_t a1, uint32_t a2, uint32_t a3,
                                         uint32_t b0, uint32_t b1) {
    asm("mma.sync.aligned.m16n8k8.row.col.f32.tf32.tf32.f32 "
        "{%0,%1,%2,%3}, {%4,%5,%6,%7}, {%8,%9}, {%0,%1,%2,%3};"
        : "+f"(d0), "+f"(d1), "+f"(d2), "+f"(d3)
        : "r"(a0), "r"(a1), "r"(a2), "r"(a3), "r"(b0), "r"(b1));
}

// ---------------------------------------------------------------------------
// Kernel 1: conv2x2(v, wk) -> g_kc[b][ii*27+jj]
// ---------------------------------------------------------------------------
__global__ __launch_bounds__(256) void conv_v_kernel(const float* __restrict__ v,
                                                     const float* __restrict__ wk,
                                                     const float* __restrict__ bk) {
    __shared__ float vs[64 * 2 * 54];
    __shared__ float wks[256];
    __shared__ float part[8][28];
    int ii = blockIdx.x;
    int b  = blockIdx.y;
    int t  = threadIdx.x;

    wks[t] = wk[t];
    for (int idx = t; idx < 64 * 2 * 54; idx += 256) {
        int c   = idx / 108;
        int rem = idx - c * 108;
        int a   = rem / 54;
        int col = rem - a * 54;
        vs[idx] = v[((b * 64 + c) * 84 + (2 * ii + a)) * 54 + col];
    }
    __syncthreads();

    if (t < 216) {
        int jj = t % 27;
        int cg = t / 27;
        float acc = 0.f;
        #pragma unroll
        for (int cc = 0; cc < 8; cc++) {
            int c = cg * 8 + cc;
            #pragma unroll
            for (int a = 0; a < 2; a++) {
                float x0 = vs[(c * 2 + a) * 54 + 2 * jj + 0];
                float x1 = vs[(c * 2 + a) * 54 + 2 * jj + 1];
                acc += x0 * wks[c * 4 + a * 2 + 0] + x1 * wks[c * 4 + a * 2 + 1];
            }
        }
        part[cg][jj] = acc;
    }
    __syncthreads();
    if (t < 27) {
        float s = bk[0];
        #pragma unroll
        for (int cg = 0; cg < 8; cg++) s += part[cg][t];
        g_kc[b * KPIN + ii * 27 + t] = s;
    }
}

// ---------------------------------------------------------------------------
// Kernel 2: k[b][m] = sum_j g_kc[b][j] * wproj[m][j] + bproj[m]
// ---------------------------------------------------------------------------
__global__ __launch_bounds__(256) void kproj_kernel(const float* __restrict__ wproj,
                                                    const float* __restrict__ bproj) {
    __shared__ float kcs[64 * 65];
    __shared__ float ws[64 * 65];
    int m0 = blockIdx.x * 64;
    int t  = threadIdx.x;
    int r  = t >> 4;
    int cc = t & 15;
    int b0 = r * 4;
    int mm0 = cc * 4;

    float acc[4][4];
    #pragma unroll
    for (int i = 0; i < 4; i++)
        #pragma unroll
        for (int j = 0; j < 4; j++) acc[i][j] = 0.f;

    for (int j0 = 0; j0 < KPIN; j0 += 64) {
        __syncthreads();
        for (int idx = t; idx < 4096; idx += 256) {
            int row = idx >> 6, jj = idx & 63;
            int j = j0 + jj;
            kcs[row * 65 + jj] = (j < KPIN) ? g_kc[row * KPIN + j] : 0.f;
            ws[row * 65 + jj]  = (j < KPIN) ? wproj[(m0 + row) * KPIN + j] : 0.f;
        }
        __syncthreads();
        #pragma unroll 4
        for (int jj = 0; jj < 64; jj++) {
            float kv[4], wv_[4];
            #pragma unroll
            for (int v_ = 0; v_ < 4; v_++) kv[v_] = kcs[(b0 + v_) * 65 + jj];
            #pragma unroll
            for (int u = 0; u < 4; u++) wv_[u] = ws[(mm0 + u) * 65 + jj];
            #pragma unroll
            for (int v_ = 0; v_ < 4; v_++)
                #pragma unroll
                for (int u = 0; u < 4; u++) acc[v_][u] += kv[v_] * wv_[u];
        }
    }
    #pragma unroll
    for (int v_ = 0; v_ < 4; v_++)
        #pragma unroll
        for (int u = 0; u < 4; u++) {
            int m = m0 + mm0 + u;
            g_k[(b0 + v_) * KPOUT + m] = acc[v_][u] + bproj[m];
        }
}

// ---------------------------------------------------------------------------
// Kernel 3: per-b max/min of k
// ---------------------------------------------------------------------------
__global__ __launch_bounds__(256) void kstats_kernel() {
    __shared__ float smax[256], smin[256];
    int b = blockIdx.x, t = threadIdx.x;
    float mx = -1e30f, mn = 1e30f;
    for (int n = t; n < NPOS; n += 256) {
        float kv = g_k[b * NPOS + n];
        mx = fmaxf(mx, kv);
        mn = fminf(mn, kv);
    }
    smax[t] = mx; smin[t] = mn;
    __syncthreads();
    for (int s = 128; s > 0; s >>= 1) {
        if (t < s) {
            smax[t] = fmaxf(smax[t], smax[t + s]);
            smin[t] = fminf(smin[t], smin[t + s]);
        }
        __syncthreads();
    }
    if (t == 0) { g_kmax[b] = smax[0]; g_kmin[b] = smin[0]; }
}

// ---------------------------------------------------------------------------
// Kernel 4: conv2x2 of x as tf32 MMA GEMM (im2col at staging):
//   pv[b][co][n] = sum_k wv[co][k] * P[k][n],  k=(ci,a,bb), n=(i,j)
//   q[b][n] = sum_k wq[k] * P[k][n]  (scalar FMA from staged slab)
// grid (4 ntile of 256 n, 64 b), 256 threads = 8 warps.
// Warp w: co-tile mt=w&3 (16 rows), n-half = w>>2 (128 cols), 16 n-tiles of 8.
// smem: Pn u32[256][38] (tf32 bits) + wvs u32[64][36] + wqc f[32]
// dyn smem = 48384 B, 2 blocks/SM.
// ---------------------------------------------------------------------------
__global__ __launch_bounds__(256, 2) void conv_x_kernel(const float* __restrict__ x,
                                                        const float* __restrict__ wq,
                                                        const float* __restrict__ bq,
                                                        const float* __restrict__ wv,
                                                        const float* __restrict__ bv) {
    extern __shared__ uint32_t cxs[];
    uint32_t* Pn  = cxs;                 // 256*38 = 9728 u32
    uint32_t* wvs = Pn + 9728;           // 64*36  = 2304 u32
    float*    wqc = reinterpret_cast<float*>(wvs + 2304);   // 32 f

    int ntile = blockIdx.x;
    int b     = blockIdx.y;
    int t     = threadIdx.x;
    int w     = t >> 5;
    int l     = t & 31;
    int g     = l >> 2;
    int tg    = l & 3;
    int mt    = w & 3;
    int half  = w >> 2;

    float acc[16][4];
    #pragma unroll
    for (int nt = 0; nt < 16; nt++)
        #pragma unroll
        for (int u = 0; u < 4; u++) acc[nt][u] = 0.f;
    float qacc = 0.f;

    for (int chunk = 0; chunk < 8; chunk++) {
        int k0  = chunk * 32;
        int ci0 = chunk * 8;
        __syncthreads();
        // stage wv tile [64 co x 32 k] as tf32
        #pragma unroll
        for (int s = 0; s < 8; s++) {
            int idx = t + s * 256;
            int co = idx >> 5, kl = idx & 31;
            wvs[co * 36 + kl] = tf32r(wv[co * 256 + k0 + kl]);
        }
        if (t < 32) wqc[t] = wq[k0 + t];
        // stage x slab -> Pn[n][k] (im2col permutation), float4 loads
        #pragma unroll
        for (int s = 0; s < 8; s++) {
            int idx = t + s * 256;          // 0..2047 vec4 index
            int cl  = idx >> 8;             // 0..7
            int rem = idx & 255;
            int r   = rem >> 4;             // 0..15
            int c4  = rem & 15;             // 0..15
            float4 xv = *reinterpret_cast<const float4*>(
                &x[(((size_t)b * 64 + ci0 + cl) * 64 + ntile * 16 + r) * 64 + c4 * 4]);
            int n2 = (r >> 1) * 32 + c4 * 2;
            int kb = cl * 4 + (r & 1) * 2;
            uint2 p0 = make_uint2(tf32r(xv.x), tf32r(xv.y));
            uint2 p1 = make_uint2(tf32r(xv.z), tf32r(xv.w));
            *reinterpret_cast<uint2*>(&Pn[n2 * 38 + kb])       = p0;
            *reinterpret_cast<uint2*>(&Pn[(n2 + 1) * 38 + kb]) = p1;
        }
        __syncthreads();

        // q partial: thread t handles n = t
        {
            const uint32_t* pr = &Pn[t * 38];
            #pragma unroll 8
            for (int k = 0; k < 32; k++)
                qacc = fmaf(wqc[k], __uint_as_float(pr[k]), qacc);
        }

        // MMA over 4 k8-steps
        #pragma unroll
        for (int k8 = 0; k8 < 4; k8++) {
            int kk = k8 * 8 + tg;
            const uint32_t* ap = &wvs[(mt * 16 + g) * 36 + kk];
            uint32_t a0 = ap[0];
            uint32_t a1 = ap[8 * 36];
            uint32_t a2 = ap[4];
            uint32_t a3 = ap[8 * 36 + 4];
            #pragma unroll
            for (int nt = 0; nt < 16; nt++) {
                const uint32_t* bp = &Pn[(half * 128 + nt * 8 + g) * 38 + kk];
                mma_tf32(acc[nt][0], acc[nt][1], acc[nt][2], acc[nt][3],
                         a0, a1, a2, a3, bp[0], bp[4]);
            }
        }
    }

    // epilogue
    int c0 = mt * 16 + g;
    float bv0 = bv[c0];
    float bv8 = bv[c0 + 8];
    int nb = ntile * 256 + half * 128;
    #pragma unroll
    for (int nt = 0; nt < 16; nt++) {
        int n = nb + nt * 8 + 2 * tg;
        *reinterpret_cast<float2*>(&g_pv[((size_t)b * 64 + c0) * NPOS + n]) =
            make_float2(acc[nt][0] + bv0, acc[nt][1] + bv0);
        *reinterpret_cast<float2*>(&g_pv[((size_t)b * 64 + c0 + 8) * NPOS + n]) =
            make_float2(acc[nt][2] + bv8, acc[nt][3] + bv8);
    }
    g_q[b * NPOS + ntile * 256 + t] = qacc + bq[0];
}

// ---------------------------------------------------------------------------
// Kernel 5: fused softmax (rank-1) + attn write + tf32 MMA GEMM.
// 256 m-rows/block, grid (4, 64). B-fragments computed in registers.
// ---------------------------------------------------------------------------
__global__ __launch_bounds__(256, 2) void attn_kernel(float* __restrict__ attn_out,
                                                      int has_attn) {
    __shared__ float ks[1024];
    __shared__ float sLs[256];
    __shared__ float offs[256];
    __shared__ uint32_t pvs[64 * 68];

    const float L2E = 1.4426950408889634f;
    int mt = blockIdx.x;
    int b  = blockIdx.y;
    int m0 = mt * 256;
    int t  = threadIdx.x;
    int w  = t >> 5;
    int l  = t & 31;
    int g  = l >> 2;
    int tg = l & 3;

    for (int n = t; n < NPOS; n += 256) ks[n] = g_k[b * NPOS + n];
    __syncthreads();

    {
        float s   = g_q[b * NPOS + m0 + t] * 0.03125f;   // 1/sqrt(1024)
        float rm  = (s >= 0.f) ? s * g_kmax[b] : s * g_kmin[b];
        float sL  = s * L2E;
        float rmL = rm * L2E;
        float p0 = 0.f, p1 = 0.f, p2 = 0.f, p3 = 0.f;
        #pragma unroll 4
        for (int n = 0; n < 1024; n += 4) {
            p0 += ex2f(fmaf(sL, ks[n + 0], -rmL));
            p1 += ex2f(fmaf(sL, ks[n + 1], -rmL));
            p2 += ex2f(fmaf(sL, ks[n + 2], -rmL));
            p3 += ex2f(fmaf(sL, ks[n + 3], -rmL));
        }
        float Z = (p0 + p1) + (p2 + p3);
        sLs[t]  = sL;
        offs[t] = -rmL - lg2f(Z);
    }
    __syncthreads();

    int mbase = w * 32;
    float sl[4], of[4];
    #pragma unroll
    for (int nt = 0; nt < 4; nt++) {
        int mm = mbase + nt * 8 + g;
        sl[nt] = sLs[mm];
        of[nt] = offs[mm];
    }

    float acc[4][4][4];
    #pragma unroll
    for (int ct = 0; ct < 4; ct++)
        #pragma unroll
        for (int nt = 0; nt < 4; nt++)
            #pragma unroll
            for (int u = 0; u < 4; u++) acc[ct][nt][u] = 0.f;

    for (int ch = 0; ch < 16; ch++) {
        int nn0 = ch * 64;
        __syncthreads();
        #pragma unroll
        for (int s = 0; s < 16; s++) {
            int idx = t + s * 256;
            int c = idx >> 6, nn = idx & 63;
            pvs[c * 68 + nn] = tf32r(g_pv[((size_t)b * 64 + c) * NPOS + nn0 + nn]);
        }
        __syncthreads();

        #pragma unroll
        for (int ks8 = 0; ks8 < 8; ks8++) {
            int kk = ks8 * 8 + tg;
            float k0v = ks[nn0 + kk];
            float k4v = ks[nn0 + kk + 4];

            uint32_t afr[4][4];
            #pragma unroll
            for (int ct = 0; ct < 4; ct++) {
                const uint32_t* ap = &pvs[(ct * 16 + g) * 68 + kk];
                afr[ct][0] = ap[0];
                afr[ct][1] = ap[8 * 68];
                afr[ct][2] = ap[4];
                afr[ct][3] = ap[8 * 68 + 4];
            }

            #pragma unroll
            for (int nt = 0; nt < 4; nt++) {
                float e0 = ex2f(fmaf(sl[nt], k0v, of[nt]));
                float e4 = ex2f(fmaf(sl[nt], k4v, of[nt]));
                if (has_attn) {
                    int mrow = m0 + mbase + nt * 8 + g;
                    size_t base = ((size_t)(b * 1024 + mrow)) * 1024 + nn0;
                    attn_out[base + kk]     = e0;
                    attn_out[base + kk + 4] = e4;
                }
                uint32_t b0 = tf32r(e0);
                uint32_t b1 = tf32r(e4);
                #pragma unroll
                for (int ct = 0; ct < 4; ct++)
                    mma_tf32(acc[ct][nt][0], acc[ct][nt][1], acc[ct][nt][2], acc[ct][nt][3],
                             afr[ct][0], afr[ct][1], afr[ct][2], afr[ct][3],
                             b0, b1);
            }
        }
    }

    #pragma unroll
    for (int ct = 0; ct < 4; ct++) {
        #pragma unroll
        for (int nt = 0; nt < 4; nt++) {
            int m = m0 + mbase + nt * 8 + 2 * tg;
            int c_lo = ct * 16 + g;
            size_t r0 = ((size_t)b * 1024 + m) * 64;
            size_t r1 = r0 + 64;
            g_outT[r0 + c_lo]     = acc[ct][nt][0];
            g_outT[r1 + c_lo]     = acc[ct][nt][1];
            g_outT[r0 + c_lo + 8] = acc[ct][nt][2];
            g_outT[r1 + c_lo + 8] = acc[ct][nt][3];
        }
    }
}

// ---------------------------------------------------------------------------
// Kernel 6: ConvTranspose2d via tf32 MMA.
// grid (8, 64), 256 threads, dyn smem = 105472 B.
// ---------------------------------------------------------------------------
__global__ __launch_bounds__(256, 2) void upsample_kernel(const float* __restrict__ wu,
                                                          const float* __restrict__ bu,
                                                          float* __restrict__ up) {
    extern __shared__ uint32_t usm[];
    uint32_t* As = usm;            // 128*68
    uint32_t* Ws = As + 8704;      // 256*69

    int ib = blockIdx.x;
    int b  = blockIdx.y;
    int n0 = ib * 128;
    int t  = threadIdx.x;
    int w  = t >> 5;
    int l  = t & 31;
    int g  = l >> 2;
    int tg = l & 3;

    #pragma unroll
    for (int s = 0; s < 32; s++) {
        int idx = t + s * 256;
        int n = idx >> 6, c = idx & 63;
        As[n * 68 + c] = tf32r(g_outT[((size_t)b * 1024 + n0 + n) * 64 + c]);
    }
    #pragma unroll
    for (int s = 0; s < 64; s++) {
        int idx = t + s * 256;
        int m = idx & 255, c = idx >> 8;
        Ws[m * 69 + c] = tf32r(wu[c * 256 + m]);
    }
    __syncthreads();

    uint32_t af[8][4];
    #pragma unroll
    for (int k8 = 0; k8 < 8; k8++) {
        const uint32_t* ap = &As[(w * 16 + g) * 68 + k8 * 8 + tg];
        af[k8][0] = ap[0];
        af[k8][1] = ap[8 * 68];
        af[k8][2] = ap[4];
        af[k8][3] = ap[8 * 68 + 4];
    }

    int n1 = n0 + w * 16 + g;
    int i1 = n1 >> 5, j1 = n1 & 31;
    int n2 = n1 + 8;
    int i2 = n2 >> 5, j2 = n2 & 31;

    for (int mtile = 0; mtile < 32; mtile++) {
        float d0 = 0.f, d1 = 0.f, d2 = 0.f, d3 = 0.f;
        #pragma unroll
        for (int k8 = 0; k8 < 8; k8++) {
            const uint32_t* bp = &Ws[(mtile * 8 + g) * 69 + k8 * 8 + tg];
            mma_tf32(d0, d1, d2, d3,
                     af[k8][0], af[k8][1], af[k8][2], af[k8][3],
                     bp[0], bp[4]);
        }
        int mm = mtile * 8 + 2 * tg;
        int dd = mm >> 2;
        int a  = (mm >> 1) & 1;
        float bud = __ldg(&bu[dd]);
        size_t base = ((size_t)(b * 64 + dd) * 64);
        float* r1p = &up[(base + 2 * i1 + a) * 64 + 2 * j1];
        float* r2p = &up[(base + 2 * i2 + a) * 64 + 2 * j2];
        *reinterpret_cast<float2*>(r1p) = make_float2(d0 + bud, d1 + bud);
        *reinterpret_cast<float2*>(r2p) = make_float2(d2 + bud, d3 + bud);
    }
}

// ---------------------------------------------------------------------------
extern "C" void kernel_launch(void* const* d_in, const int* in_sizes, int n_in,
                              void* d_out, int out_size) {
    const float* x     = (const float*)d_in[0];
    const float* v     = (const float*)d_in[1];
    const float* wq    = (const float*)d_in[2];
    const float* bq    = (const float*)d_in[3];
    const float* wk    = (const float*)d_in[4];
    const float* bk    = (const float*)d_in[5];
    const float* wv    = (const float*)d_in[6];
    const float* bv    = (const float*)d_in[7];
    const float* wu    = (const float*)d_in[8];
    const float* bu    = (const float*)d_in[9];
    const float* wproj = (const float*)d_in[10];
    const float* bproj = (const float*)d_in[11];

    float* up_out   = (float*)d_out;
    int has_attn    = (out_size > UP_ELEMS) ? 1 : 0;
    float* attn_out = up_out + UP_ELEMS;

    cudaFuncSetAttribute(conv_x_kernel,   cudaFuncAttributeMaxDynamicSharedMemorySize, 48384);
    cudaFuncSetAttribute(upsample_kernel, cudaFuncAttributeMaxDynamicSharedMemorySize, 105472);

    conv_v_kernel<<<dim3(42, 64), 256>>>(v, wk, bk);
    kproj_kernel<<<16, 256>>>(wproj, bproj);
    kstats_kernel<<<64, 256>>>();
    conv_x_kernel<<<dim3(4, 64), 256, 48384>>>(x, wq, bq, wv, bv);
    attn_kernel<<<dim3(4, 64), 256>>>(attn_out, has_attn);
    upsample_kernel<<<dim3(8, 64), 256, 105472>>>(wu, bu, up_out);
}

// round 7
// speedup vs baseline: 2.3676x; 1.0348x over previous
#include <cuda_runtime.h>
#include <cuda_bf16.h>
#include <cstdint>

// Problem constants
#define BATCH 64
#define CH    64
#define HH    64
#define WW    64
#define NPOS  1024        // 32*32
#define KPIN  1134        // 42*27
#define KPOUT 1024
#define UP_ELEMS (BATCH*CH*HH*WW)          // 16777216
#define ATTN_ELEMS (BATCH*NPOS*NPOS)       // 67108864

// Scratch (device globals; no allocation)
__device__ float    g_pv[BATCH * CH * NPOS];   // [b][c][n]
__device__ float    g_q[BATCH * NPOS];
__device__ float    g_k[BATCH * NPOS];
__device__ float    g_kc[BATCH * KPIN];
__device__ float    g_kmax[BATCH];
__device__ float    g_kmin[BATCH];
__device__ uint32_t g_wuT[256 * 64];           // tf32 bits, [dab][c]

typedef unsigned long long ull;

__device__ __forceinline__ float ex2f(float x) {
    float y;
    asm("ex2.approx.ftz.f32 %0, %1;" : "=f"(y) : "f"(x));
    return y;
}
__device__ __forceinline__ float lg2f(float x) {
    float y;
    asm("lg2.approx.ftz.f32 %0, %1;" : "=f"(y) : "f"(x));
    return y;
}
__device__ __forceinline__ uint32_t tf32r(float x) {
    uint32_t r;
    asm("cvt.rna.tf32.f32 %0, %1;" : "=r"(r) : "f"(x));
    return r;
}
__device__ __forceinline__ void mma_tf32(float& d0, float& d1, float& d2, float& d3,
                                         uint32_t a0, uint32_t a1, uint32_t a2, uint32_t a3,
                                         uint32_t b0, uint32_t b1) {
    asm("mma.sync.aligned.m16n8k8.row.col.f32.tf32.tf32.f32 "
        "{%0,%1,%2,%3}, {%4,%5,%6,%7}, {%8,%9}, {%0,%1,%2,%3};"
        : "+f"(d0), "+f"(d1), "+f"(d2), "+f"(d3)
        : "r"(a0), "r"(a1), "r"(a2), "r"(a3), "r"(b0), "r"(b1));
}

// ---------------------------------------------------------------------------
// Kernel 0: stage wu transposed as tf32 bits: g_wuT[dab][c] = tf32(wu[c][dab])
// ---------------------------------------------------------------------------
__global__ __launch_bounds__(256) void wuT_kernel(const float* __restrict__ wu) {
    int idx = blockIdx.x * 256 + threadIdx.x;   // 0..16383
    int dab = idx & 255;
    int c   = idx >> 8;
    g_wuT[dab * 64 + c] = tf32r(wu[c * 256 + dab]);
}

// ---------------------------------------------------------------------------
// Kernel 1: conv2x2(v, wk) -> g_kc[b][ii*27+jj]
// ---------------------------------------------------------------------------
__global__ __launch_bounds__(256) void conv_v_kernel(const float* __restrict__ v,
                                                     const float* __restrict__ wk,
                                                     const float* __restrict__ bk) {
    __shared__ float vs[64 * 2 * 54];
    __shared__ float wks[256];
    __shared__ float part[8][28];
    int ii = blockIdx.x;
    int b  = blockIdx.y;
    int t  = threadIdx.x;

    wks[t] = wk[t];
    for (int idx = t; idx < 64 * 2 * 54; idx += 256) {
        int c   = idx / 108;
        int rem = idx - c * 108;
        int a   = rem / 54;
        int col = rem - a * 54;
        vs[idx] = v[((b * 64 + c) * 84 + (2 * ii + a)) * 54 + col];
    }
    __syncthreads();

    if (t < 216) {
        int jj = t % 27;
        int cg = t / 27;
        float acc = 0.f;
        #pragma unroll
        for (int cc = 0; cc < 8; cc++) {
            int c = cg * 8 + cc;
            #pragma unroll
            for (int a = 0; a < 2; a++) {
                float x0 = vs[(c * 2 + a) * 54 + 2 * jj + 0];
                float x1 = vs[(c * 2 + a) * 54 + 2 * jj + 1];
                acc += x0 * wks[c * 4 + a * 2 + 0] + x1 * wks[c * 4 + a * 2 + 1];
            }
        }
        part[cg][jj] = acc;
    }
    __syncthreads();
    if (t < 27) {
        float s = bk[0];
        #pragma unroll
        for (int cg = 0; cg < 8; cg++) s += part[cg][t];
        g_kc[b * KPIN + ii * 27 + t] = s;
    }
}

// ---------------------------------------------------------------------------
// Kernel 2: k[b][m] = sum_j g_kc[b][j] * wproj[m][j] + bproj[m]
// ---------------------------------------------------------------------------
__global__ __launch_bounds__(256) void kproj_kernel(const float* __restrict__ wproj,
                                                    const float* __restrict__ bproj) {
    __shared__ float kcs[64 * 65];
    __shared__ float ws[64 * 65];
    int m0 = blockIdx.x * 64;
    int t  = threadIdx.x;
    int r  = t >> 4;
    int cc = t & 15;
    int b0 = r * 4;
    int mm0 = cc * 4;

    float acc[4][4];
    #pragma unroll
    for (int i = 0; i < 4; i++)
        #pragma unroll
        for (int j = 0; j < 4; j++) acc[i][j] = 0.f;

    for (int j0 = 0; j0 < KPIN; j0 += 64) {
        __syncthreads();
        for (int idx = t; idx < 4096; idx += 256) {
            int row = idx >> 6, jj = idx & 63;
            int j = j0 + jj;
            kcs[row * 65 + jj] = (j < KPIN) ? g_kc[row * KPIN + j] : 0.f;
            ws[row * 65 + jj]  = (j < KPIN) ? wproj[(m0 + row) * KPIN + j] : 0.f;
        }
        __syncthreads();
        #pragma unroll 4
        for (int jj = 0; jj < 64; jj++) {
            float kv[4], wv_[4];
            #pragma unroll
            for (int v_ = 0; v_ < 4; v_++) kv[v_] = kcs[(b0 + v_) * 65 + jj];
            #pragma unroll
            for (int u = 0; u < 4; u++) wv_[u] = ws[(mm0 + u) * 65 + jj];
            #pragma unroll
            for (int v_ = 0; v_ < 4; v_++)
                #pragma unroll
                for (int u = 0; u < 4; u++) acc[v_][u] += kv[v_] * wv_[u];
        }
    }
    #pragma unroll
    for (int v_ = 0; v_ < 4; v_++)
        #pragma unroll
        for (int u = 0; u < 4; u++) {
            int m = m0 + mm0 + u;
            g_k[(b0 + v_) * KPOUT + m] = acc[v_][u] + bproj[m];
        }
}

// ---------------------------------------------------------------------------
// Kernel 3: per-b max/min of k
// ---------------------------------------------------------------------------
__global__ __launch_bounds__(256) void kstats_kernel() {
    __shared__ float smax[256], smin[256];
    int b = blockIdx.x, t = threadIdx.x;
    float mx = -1e30f, mn = 1e30f;
    for (int n = t; n < NPOS; n += 256) {
        float kv = g_k[b * NPOS + n];
        mx = fmaxf(mx, kv);
        mn = fminf(mn, kv);
    }
    smax[t] = mx; smin[t] = mn;
    __syncthreads();
    for (int s = 128; s > 0; s >>= 1) {
        if (t < s) {
            smax[t] = fmaxf(smax[t], smax[t + s]);
            smin[t] = fminf(smin[t], smin[t + s]);
        }
        __syncthreads();
    }
    if (t == 0) { g_kmax[b] = smax[0]; g_kmin[b] = smin[0]; }
}

// ---------------------------------------------------------------------------
// Kernel 4: conv2x2 of x as tf32 MMA GEMM (im2col at staging).
// grid (4 ntile, 64 b), 256 threads. dyn smem = 48384 B.
// ---------------------------------------------------------------------------
__global__ __launch_bounds__(256, 2) void conv_x_kernel(const float* __restrict__ x,
                                                        const float* __restrict__ wq,
                                                        const float* __restrict__ bq,
                                                        const float* __restrict__ wv,
                                                        const float* __restrict__ bv) {
    extern __shared__ uint32_t cxs[];
    uint32_t* Pn  = cxs;                 // 256*38
    uint32_t* wvs = Pn + 9728;           // 64*36
    float*    wqc = reinterpret_cast<float*>(wvs + 2304);   // 32

    int ntile = blockIdx.x;
    int b     = blockIdx.y;
    int t     = threadIdx.x;
    int w     = t >> 5;
    int l     = t & 31;
    int g     = l >> 2;
    int tg    = l & 3;
    int mt    = w & 3;
    int half  = w >> 2;

    float acc[16][4];
    #pragma unroll
    for (int nt = 0; nt < 16; nt++)
        #pragma unroll
        for (int u = 0; u < 4; u++) acc[nt][u] = 0.f;
    float qacc = 0.f;

    for (int chunk = 0; chunk < 8; chunk++) {
        int k0  = chunk * 32;
        int ci0 = chunk * 8;
        __syncthreads();
        #pragma unroll
        for (int s = 0; s < 8; s++) {
            int idx = t + s * 256;
            int co = idx >> 5, kl = idx & 31;
            wvs[co * 36 + kl] = tf32r(wv[co * 256 + k0 + kl]);
        }
        if (t < 32) wqc[t] = wq[k0 + t];
        #pragma unroll
        for (int s = 0; s < 8; s++) {
            int idx = t + s * 256;
            int cl  = idx >> 8;
            int rem = idx & 255;
            int r   = rem >> 4;
            int c4  = rem & 15;
            float4 xv = *reinterpret_cast<const float4*>(
                &x[(((size_t)b * 64 + ci0 + cl) * 64 + ntile * 16 + r) * 64 + c4 * 4]);
            int n2 = (r >> 1) * 32 + c4 * 2;
            int kb = cl * 4 + (r & 1) * 2;
            uint2 p0 = make_uint2(tf32r(xv.x), tf32r(xv.y));
            uint2 p1 = make_uint2(tf32r(xv.z), tf32r(xv.w));
            *reinterpret_cast<uint2*>(&Pn[n2 * 38 + kb])       = p0;
            *reinterpret_cast<uint2*>(&Pn[(n2 + 1) * 38 + kb]) = p1;
        }
        __syncthreads();

        {
            const uint32_t* pr = &Pn[t * 38];
            #pragma unroll 8
            for (int k = 0; k < 32; k++)
                qacc = fmaf(wqc[k], __uint_as_float(pr[k]), qacc);
        }

        #pragma unroll
        for (int k8 = 0; k8 < 4; k8++) {
            int kk = k8 * 8 + tg;
            const uint32_t* ap = &wvs[(mt * 16 + g) * 36 + kk];
            uint32_t a0 = ap[0];
            uint32_t a1 = ap[8 * 36];
            uint32_t a2 = ap[4];
            uint32_t a3 = ap[8 * 36 + 4];
            #pragma unroll
            for (int nt = 0; nt < 16; nt++) {
                const uint32_t* bp = &Pn[(half * 128 + nt * 8 + g) * 38 + kk];
                mma_tf32(acc[nt][0], acc[nt][1], acc[nt][2], acc[nt][3],
                         a0, a1, a2, a3, bp[0], bp[4]);
            }
        }
    }

    int c0 = mt * 16 + g;
    float bv0 = bv[c0];
    float bv8 = bv[c0 + 8];
    int nb = ntile * 256 + half * 128;
    #pragma unroll
    for (int nt = 0; nt < 16; nt++) {
        int n = nb + nt * 8 + 2 * tg;
        *reinterpret_cast<float2*>(&g_pv[((size_t)b * 64 + c0) * NPOS + n]) =
            make_float2(acc[nt][0] + bv0, acc[nt][1] + bv0);
        *reinterpret_cast<float2*>(&g_pv[((size_t)b * 64 + c0 + 8) * NPOS + n]) =
            make_float2(acc[nt][2] + bv8, acc[nt][3] + bv8);
    }
    g_q[b * NPOS + ntile * 256 + t] = qacc + bq[0];
}

// ---------------------------------------------------------------------------
// Kernel 5: fused softmax + attn write + tf32 MMA GEMM + ConvTranspose2d.
// 256 m-rows/block, grid (4, 64), 256 threads.
// Epilogue: out D-frags -> smem (tf32) -> up-GEMM vs g_wuT -> up directly.
// dyn smem = 75776 B (ks | sLs | offs | pvs(aliased by outS)).
// ---------------------------------------------------------------------------
__global__ __launch_bounds__(256, 2) void attn_kernel(float* __restrict__ attn_out,
                                                      int has_attn,
                                                      const float* __restrict__ bu,
                                                      float* __restrict__ up) {
    extern __shared__ float dsm[];
    float*    ks   = dsm;                                      // [1024]
    float*    sLs  = dsm + 1024;                               // [256]
    float*    offs = dsm + 1280;                               // [256]
    uint32_t* pvs  = reinterpret_cast<uint32_t*>(dsm + 1536);  // [64*68]
    uint32_t* outS = pvs;                                      // alias: [256*68]

    const float L2E = 1.4426950408889634f;
    int mt = blockIdx.x;
    int b  = blockIdx.y;
    int m0 = mt * 256;
    int t  = threadIdx.x;
    int w  = t >> 5;
    int l  = t & 31;
    int g  = l >> 2;
    int tg = l & 3;

    for (int n = t; n < NPOS; n += 256) ks[n] = g_k[b * NPOS + n];
    __syncthreads();

    // Pass 1: fold softmax into (sL, off): attn = exp2(sL*k + off)
    {
        float s   = g_q[b * NPOS + m0 + t] * 0.03125f;   // 1/sqrt(1024)
        float rm  = (s >= 0.f) ? s * g_kmax[b] : s * g_kmin[b];
        float sL  = s * L2E;
        float rmL = rm * L2E;
        float p0 = 0.f, p1 = 0.f, p2 = 0.f, p3 = 0.f;
        #pragma unroll 4
        for (int n = 0; n < 1024; n += 4) {
            p0 += ex2f(fmaf(sL, ks[n + 0], -rmL));
            p1 += ex2f(fmaf(sL, ks[n + 1], -rmL));
            p2 += ex2f(fmaf(sL, ks[n + 2], -rmL));
            p3 += ex2f(fmaf(sL, ks[n + 3], -rmL));
        }
        float Z = (p0 + p1) + (p2 + p3);
        sLs[t]  = sL;
        offs[t] = -rmL - lg2f(Z);
    }
    __syncthreads();

    int mbase = w * 32;
    float sl[4], of[4];
    #pragma unroll
    for (int nt = 0; nt < 4; nt++) {
        int mm = mbase + nt * 8 + g;
        sl[nt] = sLs[mm];
        of[nt] = offs[mm];
    }

    float acc[4][4][4];
    #pragma unroll
    for (int ct = 0; ct < 4; ct++)
        #pragma unroll
        for (int nt = 0; nt < 4; nt++)
            #pragma unroll
            for (int u = 0; u < 4; u++) acc[ct][nt][u] = 0.f;

    for (int ch = 0; ch < 16; ch++) {
        int nn0 = ch * 64;
        __syncthreads();
        #pragma unroll
        for (int s = 0; s < 16; s++) {
            int idx = t + s * 256;
            int c = idx >> 6, nn = idx & 63;
            pvs[c * 68 + nn] = tf32r(g_pv[((size_t)b * 64 + c) * NPOS + nn0 + nn]);
        }
        __syncthreads();

        #pragma unroll
        for (int ks8 = 0; ks8 < 8; ks8++) {
            int kk = ks8 * 8 + tg;
            float k0v = ks[nn0 + kk];
            float k4v = ks[nn0 + kk + 4];

            uint32_t afr[4][4];
            #pragma unroll
            for (int ct = 0; ct < 4; ct++) {
                const uint32_t* ap = &pvs[(ct * 16 + g) * 68 + kk];
                afr[ct][0] = ap[0];
                afr[ct][1] = ap[8 * 68];
                afr[ct][2] = ap[4];
                afr[ct][3] = ap[8 * 68 + 4];
            }

            #pragma unroll
            for (int nt = 0; nt < 4; nt++) {
                float e0 = ex2f(fmaf(sl[nt], k0v, of[nt]));
                float e4 = ex2f(fmaf(sl[nt], k4v, of[nt]));
                if (has_attn) {
                    int mrow = m0 + mbase + nt * 8 + g;
                    size_t base = ((size_t)(b * 1024 + mrow)) * 1024 + nn0;
                    attn_out[base + kk]     = e0;
                    attn_out[base + kk + 4] = e4;
                }
                uint32_t b0 = tf32r(e0);
                uint32_t b1 = tf32r(e4);
                #pragma unroll
                for (int ct = 0; ct < 4; ct++)
                    mma_tf32(acc[ct][nt][0], acc[ct][nt][1], acc[ct][nt][2], acc[ct][nt][3],
                             afr[ct][0], afr[ct][1], afr[ct][2], afr[ct][3],
                             b0, b1);
            }
        }
    }

    // ---- Epilogue 1: out D-frags -> smem (tf32 bits), layout outS[m][c] ----
    __syncthreads();   // all warps done reading pvs/ks
    #pragma unroll
    for (int ct = 0; ct < 4; ct++) {
        #pragma unroll
        for (int nt = 0; nt < 4; nt++) {
            int ml = mbase + nt * 8 + 2 * tg;
            int c  = ct * 16 + g;
            outS[ml * 68 + c]           = tf32r(acc[ct][nt][0]);
            outS[(ml + 1) * 68 + c]     = tf32r(acc[ct][nt][1]);
            outS[ml * 68 + c + 8]       = tf32r(acc[ct][nt][2]);
            outS[(ml + 1) * 68 + c + 8] = tf32r(acc[ct][nt][3]);
        }
    }
    __syncthreads();

    // ---- Epilogue 2: up-GEMM: up[dab][m] = sum_c wuT[dab][c] * outS[m][c] ----
    #pragma unroll
    for (int dtl = 0; dtl < 2; dtl++) {
        int dt = w * 2 + dtl;
        uint32_t af[8][4];
        #pragma unroll
        for (int k8 = 0; k8 < 8; k8++) {
            const uint32_t* ap = &g_wuT[(dt * 16 + g) * 64 + k8 * 8 + tg];
            af[k8][0] = ap[0];
            af[k8][1] = ap[8 * 64];
            af[k8][2] = ap[4];
            af[k8][3] = ap[8 * 64 + 4];
        }
        int dab0 = dt * 16 + g;
        int dab1 = dab0 + 8;
        int dd0 = dab0 >> 2, aa0 = (dab0 >> 1) & 1, bb0 = dab0 & 1;
        int dd1 = dab1 >> 2, aa1 = (dab1 >> 1) & 1, bb1 = dab1 & 1;
        float bud0 = __ldg(&bu[dd0]);
        float bud1 = __ldg(&bu[dd1]);

        for (int mt2 = 0; mt2 < 32; mt2++) {
            float e0 = 0.f, e1 = 0.f, e2 = 0.f, e3 = 0.f;
            #pragma unroll
            for (int k8 = 0; k8 < 8; k8++) {
                const uint32_t* bp = &outS[(mt2 * 8 + g) * 68 + k8 * 8 + tg];
                mma_tf32(e0, e1, e2, e3,
                         af[k8][0], af[k8][1], af[k8][2], af[k8][3],
                         bp[0], bp[4]);
            }
            int mg = m0 + mt2 * 8 + 2 * tg;
            int i = mg >> 5, j = mg & 31;
            size_t a0 = (((size_t)(b * 64 + dd0)) * 64 + 2 * i + aa0) * 64 + 2 * j + bb0;
            size_t a1 = (((size_t)(b * 64 + dd1)) * 64 + 2 * i + aa1) * 64 + 2 * j + bb1;
            up[a0]     = e0 + bud0;
            up[a0 + 2] = e1 + bud0;
            up[a1]     = e2 + bud1;
            up[a1 + 2] = e3 + bud1;
        }
    }
}

// ---------------------------------------------------------------------------
extern "C" void kernel_launch(void* const* d_in, const int* in_sizes, int n_in,
                              void* d_out, int out_size) {
    const float* x     = (const float*)d_in[0];
    const float* v     = (const float*)d_in[1];
    const float* wq    = (const float*)d_in[2];
    const float* bq    = (const float*)d_in[3];
    const float* wk    = (const float*)d_in[4];
    const float* bk    = (const float*)d_in[5];
    const float* wv    = (const float*)d_in[6];
    const float* bv    = (const float*)d_in[7];
    const float* wu    = (const float*)d_in[8];
    const float* bu    = (const float*)d_in[9];
    const float* wproj = (const float*)d_in[10];
    const float* bproj = (const float*)d_in[11];

    float* up_out   = (float*)d_out;
    int has_attn    = (out_size > UP_ELEMS) ? 1 : 0;
    float* attn_out = up_out + UP_ELEMS;

    cudaFuncSetAttribute(conv_x_kernel, cudaFuncAttributeMaxDynamicSharedMemorySize, 48384);
    cudaFuncSetAttribute(attn_kernel,   cudaFuncAttributeMaxDynamicSharedMemorySize, 75776);

    wuT_kernel<<<64, 256>>>(wu);
    conv_v_kernel<<<dim3(42, 64), 256>>>(v, wk, bk);
    kproj_kernel<<<16, 256>>>(wproj, bproj);
    kstats_kernel<<<64, 256>>>();
    conv_x_kernel<<<dim3(4, 64), 256, 48384>>>(x, wq, bq, wv, bv);
    attn_kernel<<<dim3(4, 64), 256, 75776>>>(attn_out, has_attn, bu, up_out);
}

// round 8
// speedup vs baseline: 2.7467x; 1.1601x over previous
#include <cuda_runtime.h>
#include <cuda_bf16.h>
#include <cstdint>

// Problem constants
#define BATCH 64
#define CH    64
#define HH    64
#define WW    64
#define NPOS  1024        // 32*32
#define KPIN  1134        // 42*27
#define KPOUT 1024
#define UP_ELEMS (BATCH*CH*HH*WW)          // 16777216
#define ATTN_ELEMS (BATCH*NPOS*NPOS)       // 67108864

// Scratch (device globals; no allocation)
__device__ float    g_pv[BATCH * CH * NPOS];   // [b][c][n]
__device__ float    g_q[BATCH * NPOS];
__device__ float    g_k[BATCH * NPOS];
__device__ float    g_kc[BATCH * KPIN];
__device__ float    g_kmax[BATCH];
__device__ float    g_kmin[BATCH];
__device__ uint32_t g_wuT[256 * 64];           // tf32 bits, [dab][c]

typedef unsigned long long ull;

__device__ __forceinline__ float ex2f(float x) {
    float y;
    asm("ex2.approx.ftz.f32 %0, %1;" : "=f"(y) : "f"(x));
    return y;
}
__device__ __forceinline__ float lg2f(float x) {
    float y;
    asm("lg2.approx.ftz.f32 %0, %1;" : "=f"(y) : "f"(x));
    return y;
}
__device__ __forceinline__ uint32_t tf32r(float x) {
    uint32_t r;
    asm("cvt.rna.tf32.f32 %0, %1;" : "=r"(r) : "f"(x));
    return r;
}
__device__ __forceinline__ void mma_tf32(float& d0, float& d1, float& d2, float& d3,
                                         uint32_t a0, uint32_t a1, uint32_t a2, uint32_t a3,
                                         uint32_t b0, uint32_t b1) {
    asm("mma.sync.aligned.m16n8k8.row.col.f32.tf32.tf32.f32 "
        "{%0,%1,%2,%3}, {%4,%5,%6,%7}, {%8,%9}, {%0,%1,%2,%3};"
        : "+f"(d0), "+f"(d1), "+f"(d2), "+f"(d3)
        : "r"(a0), "r"(a1), "r"(a2), "r"(a3), "r"(b0), "r"(b1));
}
__device__ __forceinline__ void atomicMaxF(float* addr, float val) {
    if (val >= 0.f) atomicMax(reinterpret_cast<int*>(addr), __float_as_int(val));
    else atomicMin(reinterpret_cast<unsigned int*>(addr),
                   static_cast<unsigned int>(__float_as_int(val)));
}
__device__ __forceinline__ void atomicMinF(float* addr, float val) {
    if (val >= 0.f) atomicMin(reinterpret_cast<int*>(addr), __float_as_int(val));
    else atomicMax(reinterpret_cast<unsigned int*>(addr),
                   static_cast<unsigned int>(__float_as_int(val)));
}

// ---------------------------------------------------------------------------
// Kernel 0: stage wu transposed as tf32 bits + init k stats
// ---------------------------------------------------------------------------
__global__ __launch_bounds__(256) void wuT_kernel(const float* __restrict__ wu) {
    int idx = blockIdx.x * 256 + threadIdx.x;   // 0..16383
    int dab = idx & 255;
    int c   = idx >> 8;
    g_wuT[dab * 64 + c] = tf32r(wu[c * 256 + dab]);
    if (blockIdx.x == 0 && threadIdx.x < 64) {
        g_kmax[threadIdx.x] = __int_as_float(0xFF800000);   // -inf
        g_kmin[threadIdx.x] = __int_as_float(0x7F800000);   // +inf
    }
}

// ---------------------------------------------------------------------------
// Kernel 1: conv2x2(v, wk) -> g_kc[b][ii*27+jj]
// ---------------------------------------------------------------------------
__global__ __launch_bounds__(256) void conv_v_kernel(const float* __restrict__ v,
                                                     const float* __restrict__ wk,
                                                     const float* __restrict__ bk) {
    __shared__ float vs[64 * 2 * 54];
    __shared__ float wks[256];
    __shared__ float part[8][28];
    int ii = blockIdx.x;
    int b  = blockIdx.y;
    int t  = threadIdx.x;

    wks[t] = wk[t];
    for (int idx = t; idx < 64 * 2 * 54; idx += 256) {
        int c   = idx / 108;
        int rem = idx - c * 108;
        int a   = rem / 54;
        int col = rem - a * 54;
        vs[idx] = v[((b * 64 + c) * 84 + (2 * ii + a)) * 54 + col];
    }
    __syncthreads();

    if (t < 216) {
        int jj = t % 27;
        int cg = t / 27;
        float acc = 0.f;
        #pragma unroll
        for (int cc = 0; cc < 8; cc++) {
            int c = cg * 8 + cc;
            #pragma unroll
            for (int a = 0; a < 2; a++) {
                float x0 = vs[(c * 2 + a) * 54 + 2 * jj + 0];
                float x1 = vs[(c * 2 + a) * 54 + 2 * jj + 1];
                acc += x0 * wks[c * 4 + a * 2 + 0] + x1 * wks[c * 4 + a * 2 + 1];
            }
        }
        part[cg][jj] = acc;
    }
    __syncthreads();
    if (t < 27) {
        float s = bk[0];
        #pragma unroll
        for (int cg = 0; cg < 8; cg++) s += part[cg][t];
        g_kc[b * KPIN + ii * 27 + t] = s;
    }
}

// ---------------------------------------------------------------------------
// Kernel 2: k[b][m] = sum_j g_kc[b][j] * wproj[m][j] + bproj[m]
// Also accumulates per-b max/min into g_kmax/g_kmin via atomics.
// ---------------------------------------------------------------------------
__global__ __launch_bounds__(256) void kproj_kernel(const float* __restrict__ wproj,
                                                    const float* __restrict__ bproj) {
    __shared__ float kcs[64 * 65];
    __shared__ float ws[64 * 65];
    int m0 = blockIdx.x * 64;
    int t  = threadIdx.x;
    int r  = t >> 4;
    int cc = t & 15;
    int b0 = r * 4;
    int mm0 = cc * 4;

    float acc[4][4];
    #pragma unroll
    for (int i = 0; i < 4; i++)
        #pragma unroll
        for (int j = 0; j < 4; j++) acc[i][j] = 0.f;

    for (int j0 = 0; j0 < KPIN; j0 += 64) {
        __syncthreads();
        for (int idx = t; idx < 4096; idx += 256) {
            int row = idx >> 6, jj = idx & 63;
            int j = j0 + jj;
            kcs[row * 65 + jj] = (j < KPIN) ? g_kc[row * KPIN + j] : 0.f;
            ws[row * 65 + jj]  = (j < KPIN) ? wproj[(m0 + row) * KPIN + j] : 0.f;
        }
        __syncthreads();
        #pragma unroll 4
        for (int jj = 0; jj < 64; jj++) {
            float kv[4], wv_[4];
            #pragma unroll
            for (int v_ = 0; v_ < 4; v_++) kv[v_] = kcs[(b0 + v_) * 65 + jj];
            #pragma unroll
            for (int u = 0; u < 4; u++) wv_[u] = ws[(mm0 + u) * 65 + jj];
            #pragma unroll
            for (int v_ = 0; v_ < 4; v_++)
                #pragma unroll
                for (int u = 0; u < 4; u++) acc[v_][u] += kv[v_] * wv_[u];
        }
    }

    float lmax[4], lmin[4];
    #pragma unroll
    for (int v_ = 0; v_ < 4; v_++) {
        lmax[v_] = __int_as_float(0xFF800000);
        lmin[v_] = __int_as_float(0x7F800000);
    }
    #pragma unroll
    for (int v_ = 0; v_ < 4; v_++)
        #pragma unroll
        for (int u = 0; u < 4; u++) {
            int m = m0 + mm0 + u;
            float kv = acc[v_][u] + bproj[m];
            g_k[(b0 + v_) * KPOUT + m] = kv;
            lmax[v_] = fmaxf(lmax[v_], kv);
            lmin[v_] = fminf(lmin[v_], kv);
        }

    // block reduce per-b, then one atomic per b
    __syncthreads();
    #pragma unroll
    for (int v_ = 0; v_ < 4; v_++) {
        kcs[(b0 + v_) * 16 + cc] = lmax[v_];
        ws[(b0 + v_) * 16 + cc]  = lmin[v_];
    }
    __syncthreads();
    if (t < 64) {
        float mx = __int_as_float(0xFF800000);
        float mn = __int_as_float(0x7F800000);
        #pragma unroll
        for (int i = 0; i < 16; i++) {
            mx = fmaxf(mx, kcs[t * 16 + i]);
            mn = fminf(mn, ws[t * 16 + i]);
        }
        atomicMaxF(&g_kmax[t], mx);
        atomicMinF(&g_kmin[t], mn);
    }
}

// ---------------------------------------------------------------------------
// Kernel 4: conv2x2 of x as tf32 MMA GEMM (im2col at staging).
// grid (4 ntile, 64 b), 256 threads. dyn smem = 48384 B.
// ---------------------------------------------------------------------------
__global__ __launch_bounds__(256, 2) void conv_x_kernel(const float* __restrict__ x,
                                                        const float* __restrict__ wq,
                                                        const float* __restrict__ bq,
                                                        const float* __restrict__ wv,
                                                        const float* __restrict__ bv) {
    extern __shared__ uint32_t cxs[];
    uint32_t* Pn  = cxs;                 // 256*38
    uint32_t* wvs = Pn + 9728;           // 64*36
    float*    wqc = reinterpret_cast<float*>(wvs + 2304);   // 32

    int ntile = blockIdx.x;
    int b     = blockIdx.y;
    int t     = threadIdx.x;
    int w     = t >> 5;
    int l     = t & 31;
    int g     = l >> 2;
    int tg    = l & 3;
    int mt    = w & 3;
    int half  = w >> 2;

    float acc[16][4];
    #pragma unroll
    for (int nt = 0; nt < 16; nt++)
        #pragma unroll
        for (int u = 0; u < 4; u++) acc[nt][u] = 0.f;
    float qacc = 0.f;

    for (int chunk = 0; chunk < 8; chunk++) {
        int k0  = chunk * 32;
        int ci0 = chunk * 8;
        __syncthreads();
        #pragma unroll
        for (int s = 0; s < 8; s++) {
            int idx = t + s * 256;
            int co = idx >> 5, kl = idx & 31;
            wvs[co * 36 + kl] = tf32r(wv[co * 256 + k0 + kl]);
        }
        if (t < 32) wqc[t] = wq[k0 + t];
        #pragma unroll
        for (int s = 0; s < 8; s++) {
            int idx = t + s * 256;
            int cl  = idx >> 8;
            int rem = idx & 255;
            int r   = rem >> 4;
            int c4  = rem & 15;
            float4 xv = *reinterpret_cast<const float4*>(
                &x[(((size_t)b * 64 + ci0 + cl) * 64 + ntile * 16 + r) * 64 + c4 * 4]);
            int n2 = (r >> 1) * 32 + c4 * 2;
            int kb = cl * 4 + (r & 1) * 2;
            uint2 p0 = make_uint2(tf32r(xv.x), tf32r(xv.y));
            uint2 p1 = make_uint2(tf32r(xv.z), tf32r(xv.w));
            *reinterpret_cast<uint2*>(&Pn[n2 * 38 + kb])       = p0;
            *reinterpret_cast<uint2*>(&Pn[(n2 + 1) * 38 + kb]) = p1;
        }
        __syncthreads();

        {
            const uint32_t* pr = &Pn[t * 38];
            #pragma unroll 8
            for (int k = 0; k < 32; k++)
                qacc = fmaf(wqc[k], __uint_as_float(pr[k]), qacc);
        }

        #pragma unroll
        for (int k8 = 0; k8 < 4; k8++) {
            int kk = k8 * 8 + tg;
            const uint32_t* ap = &wvs[(mt * 16 + g) * 36 + kk];
            uint32_t a0 = ap[0];
            uint32_t a1 = ap[8 * 36];
            uint32_t a2 = ap[4];
            uint32_t a3 = ap[8 * 36 + 4];
            #pragma unroll
            for (int nt = 0; nt < 16; nt++) {
                const uint32_t* bp = &Pn[(half * 128 + nt * 8 + g) * 38 + kk];
                mma_tf32(acc[nt][0], acc[nt][1], acc[nt][2], acc[nt][3],
                         a0, a1, a2, a3, bp[0], bp[4]);
            }
        }
    }

    int c0 = mt * 16 + g;
    float bv0 = bv[c0];
    float bv8 = bv[c0 + 8];
    int nb = ntile * 256 + half * 128;
    #pragma unroll
    for (int nt = 0; nt < 16; nt++) {
        int n = nb + nt * 8 + 2 * tg;
        *reinterpret_cast<float2*>(&g_pv[((size_t)b * 64 + c0) * NPOS + n]) =
            make_float2(acc[nt][0] + bv0, acc[nt][1] + bv0);
        *reinterpret_cast<float2*>(&g_pv[((size_t)b * 64 + c0 + 8) * NPOS + n]) =
            make_float2(acc[nt][2] + bv8, acc[nt][3] + bv8);
    }
    g_q[b * NPOS + ntile * 256 + t] = qacc + bq[0];
}

// ---------------------------------------------------------------------------
// Kernel 5: fused softmax + attn write (smem-staged, coalesced) + tf32 MMA
// GEMM + ConvTranspose2d epilogue.
// grid (4, 64), 256 threads, dyn smem = 93184 B.
// Layout: ks[1024] | sLs[256] | offs[256] | pvs u32[64*68] | es f[256*68]
// (es aliased as outS u32[256*68] in the epilogue).
// ---------------------------------------------------------------------------
__global__ __launch_bounds__(256, 2) void attn_kernel(float* __restrict__ attn_out,
                                                      int has_attn,
                                                      const float* __restrict__ bu,
                                                      float* __restrict__ up) {
    extern __shared__ float dsm[];
    float*    ks   = dsm;                                      // [1024]
    float*    sLs  = dsm + 1024;                               // [256]
    float*    offs = dsm + 1280;                               // [256]
    uint32_t* pvs  = reinterpret_cast<uint32_t*>(dsm + 1536);  // [64*68]
    float*    es   = dsm + 1536 + 4352;                        // [256*68]
    uint32_t* outS = reinterpret_cast<uint32_t*>(es);          // alias

    const float L2E = 1.4426950408889634f;
    int mt = blockIdx.x;
    int b  = blockIdx.y;
    int m0 = mt * 256;
    int t  = threadIdx.x;
    int w  = t >> 5;
    int l  = t & 31;
    int g  = l >> 2;
    int tg = l & 3;

    for (int n = t; n < NPOS; n += 256) ks[n] = g_k[b * NPOS + n];
    __syncthreads();

    // Pass 1: fold softmax into (sL, off): attn = exp2(sL*k + off)
    {
        float s   = g_q[b * NPOS + m0 + t] * 0.03125f;   // 1/sqrt(1024)
        float rm  = (s >= 0.f) ? s * g_kmax[b] : s * g_kmin[b];
        float sL  = s * L2E;
        float rmL = rm * L2E;
        float p0 = 0.f, p1 = 0.f, p2 = 0.f, p3 = 0.f;
        #pragma unroll 4
        for (int n = 0; n < 1024; n += 4) {
            p0 += ex2f(fmaf(sL, ks[n + 0], -rmL));
            p1 += ex2f(fmaf(sL, ks[n + 1], -rmL));
            p2 += ex2f(fmaf(sL, ks[n + 2], -rmL));
            p3 += ex2f(fmaf(sL, ks[n + 3], -rmL));
        }
        float Z = (p0 + p1) + (p2 + p3);
        sLs[t]  = sL;
        offs[t] = -rmL - lg2f(Z);
    }
    __syncthreads();

    int mbase = w * 32;
    float sl[4], of[4];
    #pragma unroll
    for (int nt = 0; nt < 4; nt++) {
        int mm = mbase + nt * 8 + g;
        sl[nt] = sLs[mm];
        of[nt] = offs[mm];
    }

    float acc[4][4][4];
    #pragma unroll
    for (int ct = 0; ct < 4; ct++)
        #pragma unroll
        for (int nt = 0; nt < 4; nt++)
            #pragma unroll
            for (int u = 0; u < 4; u++) acc[ct][nt][u] = 0.f;

    const float* attn_base = 0;
    if (has_attn) attn_base = attn_out;   // silence unused warnings path

    for (int ch = 0; ch < 16; ch++) {
        int nn0 = ch * 64;
        __syncthreads();
        #pragma unroll
        for (int s = 0; s < 16; s++) {
            int idx = t + s * 256;
            int c = idx >> 6, nn = idx & 63;
            pvs[c * 68 + nn] = tf32r(g_pv[((size_t)b * 64 + c) * NPOS + nn0 + nn]);
        }
        __syncthreads();

        #pragma unroll
        for (int ks8 = 0; ks8 < 8; ks8++) {
            int kk = ks8 * 8 + tg;
            float k0v = ks[nn0 + kk];
            float k4v = ks[nn0 + kk + 4];

            uint32_t afr[4][4];
            #pragma unroll
            for (int ct = 0; ct < 4; ct++) {
                const uint32_t* ap = &pvs[(ct * 16 + g) * 68 + kk];
                afr[ct][0] = ap[0];
                afr[ct][1] = ap[8 * 68];
                afr[ct][2] = ap[4];
                afr[ct][3] = ap[8 * 68 + 4];
            }

            #pragma unroll
            for (int nt = 0; nt < 4; nt++) {
                float e0 = ex2f(fmaf(sl[nt], k0v, of[nt]));
                float e4 = ex2f(fmaf(sl[nt], k4v, of[nt]));
                int ml = mbase + nt * 8 + g;
                es[ml * 68 + kk]     = e0;
                es[ml * 68 + kk + 4] = e4;
                uint32_t b0 = tf32r(e0);
                uint32_t b1 = tf32r(e4);
                #pragma unroll
                for (int ct = 0; ct < 4; ct++)
                    mma_tf32(acc[ct][nt][0], acc[ct][nt][1], acc[ct][nt][2], acc[ct][nt][3],
                             afr[ct][0], afr[ct][1], afr[ct][2], afr[ct][3],
                             b0, b1);
            }
        }

        // coalesced attn write: warp w streams rows m = w + 8r (256 B each)
        if (has_attn) {
            __syncthreads();
            float* dst0 = attn_out + ((size_t)(b * 1024 + m0)) * 1024 + nn0 + 2 * l;
            #pragma unroll 8
            for (int r = 0; r < 32; r++) {
                int ml = w + 8 * r;
                float2 val = *reinterpret_cast<const float2*>(&es[ml * 68 + 2 * l]);
                *reinterpret_cast<float2*>(dst0 + (size_t)ml * 1024) = val;
            }
        }
    }

    // ---- Epilogue 1: out D-frags -> smem (tf32 bits), layout outS[m][c] ----
    __syncthreads();
    #pragma unroll
    for (int ct = 0; ct < 4; ct++) {
        #pragma unroll
        for (int nt = 0; nt < 4; nt++) {
            int ml = mbase + nt * 8 + 2 * tg;
            int c  = ct * 16 + g;
            outS[ml * 68 + c]           = tf32r(acc[ct][nt][0]);
            outS[(ml + 1) * 68 + c]     = tf32r(acc[ct][nt][1]);
            outS[ml * 68 + c + 8]       = tf32r(acc[ct][nt][2]);
            outS[(ml + 1) * 68 + c + 8] = tf32r(acc[ct][nt][3]);
        }
    }
    __syncthreads();

    // ---- Epilogue 2: up-GEMM: up[dab][m] = sum_c wuT[dab][c] * outS[m][c] ----
    #pragma unroll
    for (int dtl = 0; dtl < 2; dtl++) {
        int dt = w * 2 + dtl;
        uint32_t af[8][4];
        #pragma unroll
        for (int k8 = 0; k8 < 8; k8++) {
            const uint32_t* ap = &g_wuT[(dt * 16 + g) * 64 + k8 * 8 + tg];
            af[k8][0] = ap[0];
            af[k8][1] = ap[8 * 64];
            af[k8][2] = ap[4];
            af[k8][3] = ap[8 * 64 + 4];
        }
        int dab0 = dt * 16 + g;
        int dab1 = dab0 + 8;
        int dd0 = dab0 >> 2, aa0 = (dab0 >> 1) & 1, bb0 = dab0 & 1;
        int dd1 = dab1 >> 2, aa1 = (dab1 >> 1) & 1, bb1 = dab1 & 1;
        float bud0 = __ldg(&bu[dd0]);
        float bud1 = __ldg(&bu[dd1]);

        for (int mt2 = 0; mt2 < 32; mt2++) {
            float e0 = 0.f, e1 = 0.f, e2 = 0.f, e3 = 0.f;
            #pragma unroll
            for (int k8 = 0; k8 < 8; k8++) {
                const uint32_t* bp = &outS[(mt2 * 8 + g) * 68 + k8 * 8 + tg];
                mma_tf32(e0, e1, e2, e3,
                         af[k8][0], af[k8][1], af[k8][2], af[k8][3],
                         bp[0], bp[4]);
            }
            int mg = m0 + mt2 * 8 + 2 * tg;
            int i = mg >> 5, j = mg & 31;
            size_t a0 = (((size_t)(b * 64 + dd0)) * 64 + 2 * i + aa0) * 64 + 2 * j + bb0;
            size_t a1 = (((size_t)(b * 64 + dd1)) * 64 + 2 * i + aa1) * 64 + 2 * j + bb1;
            up[a0]     = e0 + bud0;
            up[a0 + 2] = e1 + bud0;
            up[a1]     = e2 + bud1;
            up[a1 + 2] = e3 + bud1;
        }
    }
}

// ---------------------------------------------------------------------------
extern "C" void kernel_launch(void* const* d_in, const int* in_sizes, int n_in,
                              void* d_out, int out_size) {
    const float* x     = (const float*)d_in[0];
    const float* v     = (const float*)d_in[1];
    const float* wq    = (const float*)d_in[2];
    const float* bq    = (const float*)d_in[3];
    const float* wk    = (const float*)d_in[4];
    const float* bk    = (const float*)d_in[5];
    const float* wv    = (const float*)d_in[6];
    const float* bv    = (const float*)d_in[7];
    const float* wu    = (const float*)d_in[8];
    const float* bu    = (const float*)d_in[9];
    const float* wproj = (const float*)d_in[10];
    const float* bproj = (const float*)d_in[11];

    float* up_out   = (float*)d_out;
    int has_attn    = (out_size > UP_ELEMS) ? 1 : 0;
    float* attn_out = up_out + UP_ELEMS;

    cudaFuncSetAttribute(conv_x_kernel, cudaFuncAttributeMaxDynamicSharedMemorySize, 48384);
    cudaFuncSetAttribute(attn_kernel,   cudaFuncAttributeMaxDynamicSharedMemorySize, 93184);

    wuT_kernel<<<64, 256>>>(wu);
    conv_v_kernel<<<dim3(42, 64), 256>>>(v, wk, bk);
    kproj_kernel<<<16, 256>>>(wproj, bproj);
    conv_x_kernel<<<dim3(4, 64), 256, 48384>>>(x, wq, bq, wv, bv);
    attn_kernel<<<dim3(4, 64), 256, 93184>>>(attn_out, has_attn, bu, up_out);
}

// round 9
// speedup vs baseline: 2.9117x; 1.0601x over previous
#include <cuda_runtime.h>
#include <cuda_bf16.h>
#include <cstdint>

// Problem constants
#define BATCH 64
#define CH    64
#define HH    64
#define WW    64
#define NPOS  1024        // 32*32
#define KPIN  1134        // 42*27
#define KPOUT 1024
#define UP_ELEMS (BATCH*CH*HH*WW)          // 16777216
#define ATTN_ELEMS (BATCH*NPOS*NPOS)       // 67108864

// Scratch (device globals; no allocation)
__device__ float    g_pv[BATCH * CH * NPOS];   // [b][c][n]
__device__ float    g_q[BATCH * NPOS];
__device__ float    g_k[BATCH * NPOS];
__device__ float    g_kc[BATCH * KPIN];
__device__ float    g_kmax[BATCH];
__device__ float    g_kmin[BATCH];
__device__ uint32_t g_wuT[256 * 64];           // tf32 bits, [dab][c]

typedef unsigned long long ull;

__device__ __forceinline__ float ex2f(float x) {
    float y;
    asm("ex2.approx.ftz.f32 %0, %1;" : "=f"(y) : "f"(x));
    return y;
}
__device__ __forceinline__ float lg2f(float x) {
    float y;
    asm("lg2.approx.ftz.f32 %0, %1;" : "=f"(y) : "f"(x));
    return y;
}
__device__ __forceinline__ uint32_t tf32r(float x) {
    uint32_t r;
    asm("cvt.rna.tf32.f32 %0, %1;" : "=r"(r) : "f"(x));
    return r;
}
__device__ __forceinline__ void mma_tf32(float& d0, float& d1, float& d2, float& d3,
                                         uint32_t a0, uint32_t a1, uint32_t a2, uint32_t a3,
                                         uint32_t b0, uint32_t b1) {
    asm("mma.sync.aligned.m16n8k8.row.col.f32.tf32.tf32.f32 "
        "{%0,%1,%2,%3}, {%4,%5,%6,%7}, {%8,%9}, {%0,%1,%2,%3};"
        : "+f"(d0), "+f"(d1), "+f"(d2), "+f"(d3)
        : "r"(a0), "r"(a1), "r"(a2), "r"(a3), "r"(b0), "r"(b1));
}
__device__ __forceinline__ void atomicMaxF(float* addr, float val) {
    if (val >= 0.f) atomicMax(reinterpret_cast<int*>(addr), __float_as_int(val));
    else atomicMin(reinterpret_cast<unsigned int*>(addr),
                   static_cast<unsigned int>(__float_as_int(val)));
}
__device__ __forceinline__ void atomicMinF(float* addr, float val) {
    if (val >= 0.f) atomicMin(reinterpret_cast<int*>(addr), __float_as_int(val));
    else atomicMax(reinterpret_cast<unsigned int*>(addr),
                   static_cast<unsigned int>(__float_as_int(val)));
}

// ---------------------------------------------------------------------------
// Kernel 1: conv2x2(v, wk) -> g_kc[b][ii*27+jj]
// Blocks with ii==0 also stage g_wuT (tf32 transpose of wu) and init kstats.
// ---------------------------------------------------------------------------
__global__ __launch_bounds__(256) void conv_v_kernel(const float* __restrict__ v,
                                                     const float* __restrict__ wk,
                                                     const float* __restrict__ bk,
                                                     const float* __restrict__ wu) {
    __shared__ float vs[64 * 2 * 54];
    __shared__ float wks[256];
    __shared__ float part[8][28];
    int ii = blockIdx.x;
    int b  = blockIdx.y;
    int t  = threadIdx.x;

    if (ii == 0) {
        int idx = b * 256 + t;          // 0..16383, each exactly once
        int dab = idx & 255;
        int c   = idx >> 8;
        g_wuT[dab * 64 + c] = tf32r(wu[c * 256 + dab]);
        if (b == 0 && t < 64) {
            g_kmax[t] = __int_as_float(0xFF800000);   // -inf
            g_kmin[t] = __int_as_float(0x7F800000);   // +inf
        }
    }

    wks[t] = wk[t];
    for (int idx = t; idx < 64 * 2 * 54; idx += 256) {
        int c   = idx / 108;
        int rem = idx - c * 108;
        int a   = rem / 54;
        int col = rem - a * 54;
        vs[idx] = v[((b * 64 + c) * 84 + (2 * ii + a)) * 54 + col];
    }
    __syncthreads();

    if (t < 216) {
        int jj = t % 27;
        int cg = t / 27;
        float acc = 0.f;
        #pragma unroll
        for (int cc = 0; cc < 8; cc++) {
            int c = cg * 8 + cc;
            #pragma unroll
            for (int a = 0; a < 2; a++) {
                float x0 = vs[(c * 2 + a) * 54 + 2 * jj + 0];
                float x1 = vs[(c * 2 + a) * 54 + 2 * jj + 1];
                acc += x0 * wks[c * 4 + a * 2 + 0] + x1 * wks[c * 4 + a * 2 + 1];
            }
        }
        part[cg][jj] = acc;
    }
    __syncthreads();
    if (t < 27) {
        float s = bk[0];
        #pragma unroll
        for (int cg = 0; cg < 8; cg++) s += part[cg][t];
        g_kc[b * KPIN + ii * 27 + t] = s;
    }
}

// ---------------------------------------------------------------------------
// Kernel 2: k[b][m] = sum_j g_kc[b][j] * wproj[m][j] + bproj[m]
// Also accumulates per-b max/min into g_kmax/g_kmin via atomics.
// ---------------------------------------------------------------------------
__global__ __launch_bounds__(256) void kproj_kernel(const float* __restrict__ wproj,
                                                    const float* __restrict__ bproj) {
    __shared__ float kcs[64 * 65];
    __shared__ float ws[64 * 65];
    int m0 = blockIdx.x * 64;
    int t  = threadIdx.x;
    int r  = t >> 4;
    int cc = t & 15;
    int b0 = r * 4;
    int mm0 = cc * 4;

    float acc[4][4];
    #pragma unroll
    for (int i = 0; i < 4; i++)
        #pragma unroll
        for (int j = 0; j < 4; j++) acc[i][j] = 0.f;

    for (int j0 = 0; j0 < KPIN; j0 += 64) {
        __syncthreads();
        for (int idx = t; idx < 4096; idx += 256) {
            int row = idx >> 6, jj = idx & 63;
            int j = j0 + jj;
            kcs[row * 65 + jj] = (j < KPIN) ? g_kc[row * KPIN + j] : 0.f;
            ws[row * 65 + jj]  = (j < KPIN) ? wproj[(m0 + row) * KPIN + j] : 0.f;
        }
        __syncthreads();
        #pragma unroll 4
        for (int jj = 0; jj < 64; jj++) {
            float kv[4], wv_[4];
            #pragma unroll
            for (int v_ = 0; v_ < 4; v_++) kv[v_] = kcs[(b0 + v_) * 65 + jj];
            #pragma unroll
            for (int u = 0; u < 4; u++) wv_[u] = ws[(mm0 + u) * 65 + jj];
            #pragma unroll
            for (int v_ = 0; v_ < 4; v_++)
                #pragma unroll
                for (int u = 0; u < 4; u++) acc[v_][u] += kv[v_] * wv_[u];
        }
    }

    float lmax[4], lmin[4];
    #pragma unroll
    for (int v_ = 0; v_ < 4; v_++) {
        lmax[v_] = __int_as_float(0xFF800000);
        lmin[v_] = __int_as_float(0x7F800000);
    }
    #pragma unroll
    for (int v_ = 0; v_ < 4; v_++)
        #pragma unroll
        for (int u = 0; u < 4; u++) {
            int m = m0 + mm0 + u;
            float kv = acc[v_][u] + bproj[m];
            g_k[(b0 + v_) * KPOUT + m] = kv;
            lmax[v_] = fmaxf(lmax[v_], kv);
            lmin[v_] = fminf(lmin[v_], kv);
        }

    __syncthreads();
    #pragma unroll
    for (int v_ = 0; v_ < 4; v_++) {
        kcs[(b0 + v_) * 16 + cc] = lmax[v_];
        ws[(b0 + v_) * 16 + cc]  = lmin[v_];
    }
    __syncthreads();
    if (t < 64) {
        float mx = __int_as_float(0xFF800000);
        float mn = __int_as_float(0x7F800000);
        #pragma unroll
        for (int i = 0; i < 16; i++) {
            mx = fmaxf(mx, kcs[t * 16 + i]);
            mn = fminf(mn, ws[t * 16 + i]);
        }
        atomicMaxF(&g_kmax[t], mx);
        atomicMinF(&g_kmin[t], mn);
    }
}

// ---------------------------------------------------------------------------
// Kernel 4: conv2x2 of x as tf32 MMA GEMM (im2col at staging).
// grid (4 ntile, 64 b), 256 threads. dyn smem = 48384 B.
// ---------------------------------------------------------------------------
__global__ __launch_bounds__(256, 2) void conv_x_kernel(const float* __restrict__ x,
                                                        const float* __restrict__ wq,
                                                        const float* __restrict__ bq,
                                                        const float* __restrict__ wv,
                                                        const float* __restrict__ bv) {
    extern __shared__ uint32_t cxs[];
    uint32_t* Pn  = cxs;                 // 256*38
    uint32_t* wvs = Pn + 9728;           // 64*36
    float*    wqc = reinterpret_cast<float*>(wvs + 2304);   // 32

    int ntile = blockIdx.x;
    int b     = blockIdx.y;
    int t     = threadIdx.x;
    int w     = t >> 5;
    int l     = t & 31;
    int g     = l >> 2;
    int tg    = l & 3;
    int mt    = w & 3;
    int half  = w >> 2;

    float acc[16][4];
    #pragma unroll
    for (int nt = 0; nt < 16; nt++)
        #pragma unroll
        for (int u = 0; u < 4; u++) acc[nt][u] = 0.f;
    float qacc = 0.f;

    for (int chunk = 0; chunk < 8; chunk++) {
        int k0  = chunk * 32;
        int ci0 = chunk * 8;
        __syncthreads();
        #pragma unroll
        for (int s = 0; s < 8; s++) {
            int idx = t + s * 256;
            int co = idx >> 5, kl = idx & 31;
            wvs[co * 36 + kl] = tf32r(wv[co * 256 + k0 + kl]);
        }
        if (t < 32) wqc[t] = wq[k0 + t];
        #pragma unroll
        for (int s = 0; s < 8; s++) {
            int idx = t + s * 256;
            int cl  = idx >> 8;
            int rem = idx & 255;
            int r   = rem >> 4;
            int c4  = rem & 15;
            float4 xv = *reinterpret_cast<const float4*>(
                &x[(((size_t)b * 64 + ci0 + cl) * 64 + ntile * 16 + r) * 64 + c4 * 4]);
            int n2 = (r >> 1) * 32 + c4 * 2;
            int kb = cl * 4 + (r & 1) * 2;
            uint2 p0 = make_uint2(tf32r(xv.x), tf32r(xv.y));
            uint2 p1 = make_uint2(tf32r(xv.z), tf32r(xv.w));
            *reinterpret_cast<uint2*>(&Pn[n2 * 38 + kb])       = p0;
            *reinterpret_cast<uint2*>(&Pn[(n2 + 1) * 38 + kb]) = p1;
        }
        __syncthreads();

        {
            const uint32_t* pr = &Pn[t * 38];
            #pragma unroll 8
            for (int k = 0; k < 32; k++)
                qacc = fmaf(wqc[k], __uint_as_float(pr[k]), qacc);
        }

        #pragma unroll
        for (int k8 = 0; k8 < 4; k8++) {
            int kk = k8 * 8 + tg;
            const uint32_t* ap = &wvs[(mt * 16 + g) * 36 + kk];
            uint32_t a0 = ap[0];
            uint32_t a1 = ap[8 * 36];
            uint32_t a2 = ap[4];
            uint32_t a3 = ap[8 * 36 + 4];
            #pragma unroll
            for (int nt = 0; nt < 16; nt++) {
                const uint32_t* bp = &Pn[(half * 128 + nt * 8 + g) * 38 + kk];
                mma_tf32(acc[nt][0], acc[nt][1], acc[nt][2], acc[nt][3],
                         a0, a1, a2, a3, bp[0], bp[4]);
            }
        }
    }

    int c0 = mt * 16 + g;
    float bv0 = bv[c0];
    float bv8 = bv[c0 + 8];
    int nb = ntile * 256 + half * 128;
    #pragma unroll
    for (int nt = 0; nt < 16; nt++) {
        int n = nb + nt * 8 + 2 * tg;
        *reinterpret_cast<float2*>(&g_pv[((size_t)b * 64 + c0) * NPOS + n]) =
            make_float2(acc[nt][0] + bv0, acc[nt][1] + bv0);
        *reinterpret_cast<float2*>(&g_pv[((size_t)b * 64 + c0 + 8) * NPOS + n]) =
            make_float2(acc[nt][2] + bv8, acc[nt][3] + bv8);
    }
    g_q[b * NPOS + ntile * 256 + t] = qacc + bq[0];
}

// ---------------------------------------------------------------------------
// Kernel 5: fused softmax + attn write + tf32 MMA GEMM + ConvTranspose2d.
// grid (4, 64), 256 threads, dyn smem = 93184 B.
// Pipelined pv staging (register prefetch) + warp-private attn copy-out.
// ---------------------------------------------------------------------------
__global__ __launch_bounds__(256, 2) void attn_kernel(float* __restrict__ attn_out,
                                                      int has_attn,
                                                      const float* __restrict__ bu,
                                                      float* __restrict__ up) {
    extern __shared__ float dsm[];
    float*    ks   = dsm;                                      // [1024]
    float*    sLs  = dsm + 1024;                               // [256]
    float*    offs = dsm + 1280;                               // [256]
    uint32_t* pvs  = reinterpret_cast<uint32_t*>(dsm + 1536);  // [64*68]
    float*    es   = dsm + 1536 + 4352;                        // [256*68]
    uint32_t* outS = reinterpret_cast<uint32_t*>(es);          // alias

    const float L2E = 1.4426950408889634f;
    int mt = blockIdx.x;
    int b  = blockIdx.y;
    int m0 = mt * 256;
    int t  = threadIdx.x;
    int w  = t >> 5;
    int l  = t & 31;
    int g  = l >> 2;
    int tg = l & 3;

    for (int n = t; n < NPOS; n += 256) ks[n] = g_k[b * NPOS + n];

    // issue first pv chunk prefetch now; latency hides behind pass-1
    int pv_c  = t >> 6;          // staging coords for this thread (s stride 4 c)
    int pv_nn = t & 63;
    float pvf[16];
    #pragma unroll
    for (int s = 0; s < 16; s++)
        pvf[s] = g_pv[((size_t)b * 64 + (pv_c + s * 4)) * NPOS + pv_nn];

    __syncthreads();

    // Pass 1: fold softmax into (sL, off): attn = exp2(sL*k + off)
    {
        float s   = g_q[b * NPOS + m0 + t] * 0.03125f;   // 1/sqrt(1024)
        float rm  = (s >= 0.f) ? s * g_kmax[b] : s * g_kmin[b];
        float sL  = s * L2E;
        float rmL = rm * L2E;
        float p0 = 0.f, p1 = 0.f, p2 = 0.f, p3 = 0.f;
        #pragma unroll 4
        for (int n = 0; n < 1024; n += 4) {
            p0 += ex2f(fmaf(sL, ks[n + 0], -rmL));
            p1 += ex2f(fmaf(sL, ks[n + 1], -rmL));
            p2 += ex2f(fmaf(sL, ks[n + 2], -rmL));
            p3 += ex2f(fmaf(sL, ks[n + 3], -rmL));
        }
        float Z = (p0 + p1) + (p2 + p3);
        sLs[t]  = sL;
        offs[t] = -rmL - lg2f(Z);
    }
    __syncthreads();

    int mbase = w * 32;
    float sl[4], of[4];
    #pragma unroll
    for (int nt = 0; nt < 4; nt++) {
        int mm = mbase + nt * 8 + g;
        sl[nt] = sLs[mm];
        of[nt] = offs[mm];
    }

    float acc[4][4][4];
    #pragma unroll
    for (int ct = 0; ct < 4; ct++)
        #pragma unroll
        for (int nt = 0; nt < 4; nt++)
            #pragma unroll
            for (int u = 0; u < 4; u++) acc[ct][nt][u] = 0.f;

    for (int ch = 0; ch < 16; ch++) {
        int nn0 = ch * 64;
        __syncthreads();   // prev chunk's pvs readers done
        #pragma unroll
        for (int s = 0; s < 16; s++)
            pvs[(pv_c + s * 4) * 68 + pv_nn] = tf32r(pvf[s]);
        // prefetch next chunk while this one computes
        if (ch < 15) {
            int nb2 = nn0 + 64;
            #pragma unroll
            for (int s = 0; s < 16; s++)
                pvf[s] = g_pv[((size_t)b * 64 + (pv_c + s * 4)) * NPOS + nb2 + pv_nn];
        }
        __syncthreads();   // pvs visible

        #pragma unroll
        for (int ks8 = 0; ks8 < 8; ks8++) {
            int kk = ks8 * 8 + tg;
            float k0v = ks[nn0 + kk];
            float k4v = ks[nn0 + kk + 4];

            uint32_t afr[4][4];
            #pragma unroll
            for (int ct = 0; ct < 4; ct++) {
                const uint32_t* ap = &pvs[(ct * 16 + g) * 68 + kk];
                afr[ct][0] = ap[0];
                afr[ct][1] = ap[8 * 68];
                afr[ct][2] = ap[4];
                afr[ct][3] = ap[8 * 68 + 4];
            }

            #pragma unroll
            for (int nt = 0; nt < 4; nt++) {
                float e0 = ex2f(fmaf(sl[nt], k0v, of[nt]));
                float e4 = ex2f(fmaf(sl[nt], k4v, of[nt]));
                int ml = mbase + nt * 8 + g;
                es[ml * 68 + kk]     = e0;
                es[ml * 68 + kk + 4] = e4;
                uint32_t b0 = tf32r(e0);
                uint32_t b1 = tf32r(e4);
                #pragma unroll
                for (int ct = 0; ct < 4; ct++)
                    mma_tf32(acc[ct][nt][0], acc[ct][nt][1], acc[ct][nt][2], acc[ct][nt][3],
                             afr[ct][0], afr[ct][1], afr[ct][2], afr[ct][3],
                             b0, b1);
            }
        }

        // warp-private coalesced attn write: own 32 rows, 256 B each
        if (has_attn) {
            __syncwarp();
            float* dst = attn_out + ((size_t)(b * 1024 + m0 + mbase)) * 1024 + nn0 + 2 * l;
            #pragma unroll 8
            for (int r2 = 0; r2 < 32; r2++) {
                float2 val = *reinterpret_cast<const float2*>(&es[(mbase + r2) * 68 + 2 * l]);
                *reinterpret_cast<float2*>(dst + (size_t)r2 * 1024) = val;
            }
        }
    }

    // ---- Epilogue 1: out D-frags -> smem (tf32 bits), layout outS[m][c] ----
    __syncwarp();   // own rows only; copy-out of last chunk already warp-ordered
    #pragma unroll
    for (int ct = 0; ct < 4; ct++) {
        #pragma unroll
        for (int nt = 0; nt < 4; nt++) {
            int ml = mbase + nt * 8 + 2 * tg;
            int c  = ct * 16 + g;
            outS[ml * 68 + c]           = tf32r(acc[ct][nt][0]);
            outS[(ml + 1) * 68 + c]     = tf32r(acc[ct][nt][1]);
            outS[ml * 68 + c + 8]       = tf32r(acc[ct][nt][2]);
            outS[(ml + 1) * 68 + c + 8] = tf32r(acc[ct][nt][3]);
        }
    }
    __syncthreads();

    // ---- Epilogue 2: up-GEMM: up[dab][m] = sum_c wuT[dab][c] * outS[m][c] ----
    #pragma unroll
    for (int dtl = 0; dtl < 2; dtl++) {
        int dt = w * 2 + dtl;
        uint32_t af[8][4];
        #pragma unroll
        for (int k8 = 0; k8 < 8; k8++) {
            const uint32_t* ap = &g_wuT[(dt * 16 + g) * 64 + k8 * 8 + tg];
            af[k8][0] = ap[0];
            af[k8][1] = ap[8 * 64];
            af[k8][2] = ap[4];
            af[k8][3] = ap[8 * 64 + 4];
        }
        int dab0 = dt * 16 + g;
        int dab1 = dab0 + 8;
        int dd0 = dab0 >> 2, aa0 = (dab0 >> 1) & 1, bb0 = dab0 & 1;
        int dd1 = dab1 >> 2, aa1 = (dab1 >> 1) & 1, bb1 = dab1 & 1;
        float bud0 = __ldg(&bu[dd0]);
        float bud1 = __ldg(&bu[dd1]);

        for (int mt2 = 0; mt2 < 32; mt2++) {
            float e0 = 0.f, e1 = 0.f, e2 = 0.f, e3 = 0.f;
            #pragma unroll
            for (int k8 = 0; k8 < 8; k8++) {
                const uint32_t* bp = &outS[(mt2 * 8 + g) * 68 + k8 * 8 + tg];
                mma_tf32(e0, e1, e2, e3,
                         af[k8][0], af[k8][1], af[k8][2], af[k8][3],
                         bp[0], bp[4]);
            }
            int mg = m0 + mt2 * 8 + 2 * tg;
            int i = mg >> 5, j = mg & 31;
            size_t a0 = (((size_t)(b * 64 + dd0)) * 64 + 2 * i + aa0) * 64 + 2 * j + bb0;
            size_t a1 = (((size_t)(b * 64 + dd1)) * 64 + 2 * i + aa1) * 64 + 2 * j + bb1;
            up[a0]     = e0 + bud0;
            up[a0 + 2] = e1 + bud0;
            up[a1]     = e2 + bud1;
            up[a1 + 2] = e3 + bud1;
        }
    }
}

// ---------------------------------------------------------------------------
extern "C" void kernel_launch(void* const* d_in, const int* in_sizes, int n_in,
                              void* d_out, int out_size) {
    const float* x     = (const float*)d_in[0];
    const float* v     = (const float*)d_in[1];
    const float* wq    = (const float*)d_in[2];
    const float* bq    = (const float*)d_in[3];
    const float* wk    = (const float*)d_in[4];
    const float* bk    = (const float*)d_in[5];
    const float* wv    = (const float*)d_in[6];
    const float* bv    = (const float*)d_in[7];
    const float* wu    = (const float*)d_in[8];
    const float* bu    = (const float*)d_in[9];
    const float* wproj = (const float*)d_in[10];
    const float* bproj = (const float*)d_in[11];

    float* up_out   = (float*)d_out;
    int has_attn    = (out_size > UP_ELEMS) ? 1 : 0;
    float* attn_out = up_out + UP_ELEMS;

    cudaFuncSetAttribute(conv_x_kernel, cudaFuncAttributeMaxDynamicSharedMemorySize, 48384);
    cudaFuncSetAttribute(attn_kernel,   cudaFuncAttributeMaxDynamicSharedMemorySize, 93184);

    conv_v_kernel<<<dim3(42, 64), 256>>>(v, wk, bk, wu);
    kproj_kernel<<<16, 256>>>(wproj, bproj);
    conv_x_kernel<<<dim3(4, 64), 256, 48384>>>(x, wq, bq, wv, bv);
    attn_kernel<<<dim3(4, 64), 256, 93184>>>(attn_out, has_attn, bu, up_out);
}

// round 10
// speedup vs baseline: 3.7508x; 1.2882x over previous
#include <cuda_runtime.h>
#include <cuda_bf16.h>
#include <cstdint>

// Problem constants
#define BATCH 64
#define CH    64
#define HH    64
#define WW    64
#define NPOS  1024        // 32*32
#define KPIN  1134        // 42*27 = 9*126
#define KPOUT 1024
#define UP_ELEMS (BATCH*CH*HH*WW)          // 16777216
#define ATTN_ELEMS (BATCH*NPOS*NPOS)       // 67108864

// Scratch (device globals; no allocation)
__device__ float    g_pv[BATCH * CH * NPOS];   // [b][c][n]
__device__ float    g_q[BATCH * NPOS];
__device__ float    g_k[BATCH * NPOS];
__device__ float    g_kc[BATCH * KPIN];
__device__ float    g_kpart[9 * BATCH * NPOS]; // split-K partials [ks][b][m]
__device__ float    g_kmax[BATCH];
__device__ float    g_kmin[BATCH];
__device__ uint32_t g_wuT[256 * 64];           // tf32 bits, [dab][c]

typedef unsigned long long ull;

__device__ __forceinline__ float ex2f(float x) {
    float y;
    asm("ex2.approx.ftz.f32 %0, %1;" : "=f"(y) : "f"(x));
    return y;
}
__device__ __forceinline__ float lg2f(float x) {
    float y;
    asm("lg2.approx.ftz.f32 %0, %1;" : "=f"(y) : "f"(x));
    return y;
}
__device__ __forceinline__ uint32_t tf32r(float x) {
    uint32_t r;
    asm("cvt.rna.tf32.f32 %0, %1;" : "=r"(r) : "f"(x));
    return r;
}
__device__ __forceinline__ void mma_tf32(float& d0, float& d1, float& d2, float& d3,
                                         uint32_t a0, uint32_t a1, uint32_t a2, uint32_t a3,
                                         uint32_t b0, uint32_t b1) {
    asm("mma.sync.aligned.m16n8k8.row.col.f32.tf32.tf32.f32 "
        "{%0,%1,%2,%3}, {%4,%5,%6,%7}, {%8,%9}, {%0,%1,%2,%3};"
        : "+f"(d0), "+f"(d1), "+f"(d2), "+f"(d3)
        : "r"(a0), "r"(a1), "r"(a2), "r"(a3), "r"(b0), "r"(b1));
}

// ---------------------------------------------------------------------------
// Kernel 1: conv2x2(v, wk) -> g_kc[b][ii*27+jj]
// Blocks with ii==0 also stage g_wuT (tf32 transpose of wu).
// ---------------------------------------------------------------------------
__global__ __launch_bounds__(256) void conv_v_kernel(const float* __restrict__ v,
                                                     const float* __restrict__ wk,
                                                     const float* __restrict__ bk,
                                                     const float* __restrict__ wu) {
    __shared__ float vs[64 * 2 * 54];
    __shared__ float wks[256];
    __shared__ float part[8][28];
    int ii = blockIdx.x;
    int b  = blockIdx.y;
    int t  = threadIdx.x;

    if (ii == 0) {
        int idx = b * 256 + t;          // 0..16383, each exactly once
        int dab = idx & 255;
        int c   = idx >> 8;
        g_wuT[dab * 64 + c] = tf32r(wu[c * 256 + dab]);
    }

    wks[t] = wk[t];
    for (int idx = t; idx < 64 * 2 * 54; idx += 256) {
        int c   = idx / 108;
        int rem = idx - c * 108;
        int a   = rem / 54;
        int col = rem - a * 54;
        vs[idx] = v[((b * 64 + c) * 84 + (2 * ii + a)) * 54 + col];
    }
    __syncthreads();

    if (t < 216) {
        int jj = t % 27;
        int cg = t / 27;
        float acc = 0.f;
        #pragma unroll
        for (int cc = 0; cc < 8; cc++) {
            int c = cg * 8 + cc;
            #pragma unroll
            for (int a = 0; a < 2; a++) {
                float x0 = vs[(c * 2 + a) * 54 + 2 * jj + 0];
                float x1 = vs[(c * 2 + a) * 54 + 2 * jj + 1];
                acc += x0 * wks[c * 4 + a * 2 + 0] + x1 * wks[c * 4 + a * 2 + 1];
            }
        }
        part[cg][jj] = acc;
    }
    __syncthreads();
    if (t < 27) {
        float s = bk[0];
        #pragma unroll
        for (int cg = 0; cg < 8; cg++) s += part[cg][t];
        g_kc[b * KPIN + ii * 27 + t] = s;
    }
}

// ---------------------------------------------------------------------------
// Kernel 2a: split-K partial GEMM.
// grid (16 m-tiles, 9 k-splits), 256 threads, dyn smem = 65024 B.
// g_kpart[ks][b][m] = sum_{k in split} g_kc[b][k] * wproj[m][k]
// ---------------------------------------------------------------------------
__global__ __launch_bounds__(256) void kproj_part_kernel(const float* __restrict__ wproj) {
    extern __shared__ float sm2[];
    float* kcs = sm2;               // [64][127]
    float* ws  = sm2 + 64 * 127;    // [64][127]
    int mt  = blockIdx.x;
    int ksp = blockIdx.y;
    int m0  = mt * 64;
    int k0  = ksp * 126;
    int t   = threadIdx.x;

    for (int idx = t; idx < 64 * 126; idx += 256) {
        int row = idx / 126;
        int jj  = idx - row * 126;
        kcs[row * 127 + jj] = g_kc[row * KPIN + k0 + jj];
        ws[row * 127 + jj]  = wproj[(size_t)(m0 + row) * KPIN + k0 + jj];
    }
    __syncthreads();

    int r  = t >> 4;       // b group
    int cc = t & 15;       // m group
    int b0 = r * 4;
    int mm0 = cc * 4;

    float acc[4][4];
    #pragma unroll
    for (int i = 0; i < 4; i++)
        #pragma unroll
        for (int j = 0; j < 4; j++) acc[i][j] = 0.f;

    #pragma unroll 3
    for (int jj = 0; jj < 126; jj++) {
        float kv[4], wv_[4];
        #pragma unroll
        for (int v_ = 0; v_ < 4; v_++) kv[v_] = kcs[(b0 + v_) * 127 + jj];
        #pragma unroll
        for (int u = 0; u < 4; u++) wv_[u] = ws[(mm0 + u) * 127 + jj];
        #pragma unroll
        for (int v_ = 0; v_ < 4; v_++)
            #pragma unroll
            for (int u = 0; u < 4; u++) acc[v_][u] += kv[v_] * wv_[u];
    }

    #pragma unroll
    for (int v_ = 0; v_ < 4; v_++)
        #pragma unroll
        for (int u = 0; u < 4; u++)
            g_kpart[((size_t)ksp * 64 + b0 + v_) * NPOS + m0 + mm0 + u] = acc[v_][u];
}

// ---------------------------------------------------------------------------
// Kernel 2b: reduce partials + bias -> g_k; per-b max/min (deterministic).
// grid 64 (b), 256 threads.
// ---------------------------------------------------------------------------
__global__ __launch_bounds__(256) void kreduce_kernel(const float* __restrict__ bproj) {
    __shared__ float smax[256], smin[256];
    int b = blockIdx.x, t = threadIdx.x;
    float mx = __int_as_float(0xFF800000);
    float mn = __int_as_float(0x7F800000);
    #pragma unroll
    for (int j = 0; j < 4; j++) {
        int m = t + j * 256;
        float s = bproj[m];
        #pragma unroll
        for (int ksp = 0; ksp < 9; ksp++)
            s += g_kpart[((size_t)ksp * 64 + b) * NPOS + m];
        g_k[b * NPOS + m] = s;
        mx = fmaxf(mx, s);
        mn = fminf(mn, s);
    }
    smax[t] = mx; smin[t] = mn;
    __syncthreads();
    for (int s2 = 128; s2 > 0; s2 >>= 1) {
        if (t < s2) {
            smax[t] = fmaxf(smax[t], smax[t + s2]);
            smin[t] = fminf(smin[t], smin[t + s2]);
        }
        __syncthreads();
    }
    if (t == 0) { g_kmax[b] = smax[0]; g_kmin[b] = smin[0]; }
}

// ---------------------------------------------------------------------------
// Kernel 4: conv2x2 of x as tf32 MMA GEMM (im2col at staging).
// grid (8 ntile of 128 n, 64 b), 256 threads, 3 blocks/SM.
// dyn smem = 28800 B: Pn u32[128][38] | wvs u32[64][36] | wqc f[32]
// ---------------------------------------------------------------------------
__global__ __launch_bounds__(256, 3) void conv_x_kernel(const float* __restrict__ x,
                                                        const float* __restrict__ wq,
                                                        const float* __restrict__ bq,
                                                        const float* __restrict__ wv,
                                                        const float* __restrict__ bv) {
    extern __shared__ uint32_t cxs[];
    uint32_t* Pn  = cxs;                 // 128*38 = 4864
    uint32_t* wvs = Pn + 4864;           // 64*36  = 2304
    float*    wqc = reinterpret_cast<float*>(wvs + 2304);   // 32

    int ntile = blockIdx.x;              // 0..7, n0 = ntile*128 (4 i-rows)
    int b     = blockIdx.y;
    int t     = threadIdx.x;
    int w     = t >> 5;
    int l     = t & 31;
    int g     = l >> 2;
    int tg    = l & 3;
    int mt    = w & 3;
    int half  = w >> 2;

    float acc[8][4];
    #pragma unroll
    for (int nt = 0; nt < 8; nt++)
        #pragma unroll
        for (int u = 0; u < 4; u++) acc[nt][u] = 0.f;
    float qacc = 0.f;

    for (int chunk = 0; chunk < 8; chunk++) {
        int k0  = chunk * 32;
        int ci0 = chunk * 8;
        __syncthreads();
        #pragma unroll
        for (int s = 0; s < 8; s++) {
            int idx = t + s * 256;
            int co = idx >> 5, kl = idx & 31;
            wvs[co * 36 + kl] = tf32r(wv[co * 256 + k0 + kl]);
        }
        if (t < 32) wqc[t] = wq[k0 + t];
        // 1024 float4 = 8 cl x 8 r x 16 c4
        #pragma unroll
        for (int s = 0; s < 4; s++) {
            int idx = t + s * 256;
            int cl  = idx >> 7;
            int rem = idx & 127;
            int r   = rem >> 4;            // 0..7 local x-row
            int c4  = rem & 15;
            float4 xv = *reinterpret_cast<const float4*>(
                &x[(((size_t)b * 64 + ci0 + cl) * 64 + ntile * 8 + r) * 64 + c4 * 4]);
            int n2 = (r >> 1) * 32 + c4 * 2;   // 0..127 (pairs)
            int kb = cl * 4 + (r & 1) * 2;
            uint2 p0 = make_uint2(tf32r(xv.x), tf32r(xv.y));
            uint2 p1 = make_uint2(tf32r(xv.z), tf32r(xv.w));
            *reinterpret_cast<uint2*>(&Pn[n2 * 38 + kb])       = p0;
            *reinterpret_cast<uint2*>(&Pn[(n2 + 1) * 38 + kb]) = p1;
        }
        __syncthreads();

        if (t < 128) {
            const uint32_t* pr = &Pn[t * 38];
            #pragma unroll 8
            for (int k = 0; k < 32; k++)
                qacc = fmaf(wqc[k], __uint_as_float(pr[k]), qacc);
        }

        #pragma unroll
        for (int k8 = 0; k8 < 4; k8++) {
            int kk = k8 * 8 + tg;
            const uint32_t* ap = &wvs[(mt * 16 + g) * 36 + kk];
            uint32_t a0 = ap[0];
            uint32_t a1 = ap[8 * 36];
            uint32_t a2 = ap[4];
            uint32_t a3 = ap[8 * 36 + 4];
            #pragma unroll
            for (int nt = 0; nt < 8; nt++) {
                const uint32_t* bp = &Pn[(half * 64 + nt * 8 + g) * 38 + kk];
                mma_tf32(acc[nt][0], acc[nt][1], acc[nt][2], acc[nt][3],
                         a0, a1, a2, a3, bp[0], bp[4]);
            }
        }
    }

    int c0 = mt * 16 + g;
    float bv0 = bv[c0];
    float bv8 = bv[c0 + 8];
    int nb = ntile * 128 + half * 64;
    #pragma unroll
    for (int nt = 0; nt < 8; nt++) {
        int n = nb + nt * 8 + 2 * tg;
        *reinterpret_cast<float2*>(&g_pv[((size_t)b * 64 + c0) * NPOS + n]) =
            make_float2(acc[nt][0] + bv0, acc[nt][1] + bv0);
        *reinterpret_cast<float2*>(&g_pv[((size_t)b * 64 + c0 + 8) * NPOS + n]) =
            make_float2(acc[nt][2] + bv8, acc[nt][3] + bv8);
    }
    if (t < 128) g_q[b * NPOS + ntile * 128 + t] = qacc + bq[0];
}

// ---------------------------------------------------------------------------
// Kernel 5: fused softmax + attn write + tf32 MMA GEMM + ConvTranspose2d.
// grid (4, 64), 256 threads, dyn smem = 93184 B.
// ---------------------------------------------------------------------------
__global__ __launch_bounds__(256, 2) void attn_kernel(float* __restrict__ attn_out,
                                                      int has_attn,
                                                      const float* __restrict__ bu,
                                                      float* __restrict__ up) {
    extern __shared__ float dsm[];
    float*    ks   = dsm;                                      // [1024]
    float*    sLs  = dsm + 1024;                               // [256]
    float*    offs = dsm + 1280;                               // [256]
    uint32_t* pvs  = reinterpret_cast<uint32_t*>(dsm + 1536);  // [64*68]
    float*    es   = dsm + 1536 + 4352;                        // [256*68]
    uint32_t* outS = reinterpret_cast<uint32_t*>(es);          // alias

    const float L2E = 1.4426950408889634f;
    int mt = blockIdx.x;
    int b  = blockIdx.y;
    int m0 = mt * 256;
    int t  = threadIdx.x;
    int w  = t >> 5;
    int l  = t & 31;
    int g  = l >> 2;
    int tg = l & 3;

    for (int n = t; n < NPOS; n += 256) ks[n] = g_k[b * NPOS + n];

    int pv_c  = t >> 6;
    int pv_nn = t & 63;
    float pvf[16];
    #pragma unroll
    for (int s = 0; s < 16; s++)
        pvf[s] = g_pv[((size_t)b * 64 + (pv_c + s * 4)) * NPOS + pv_nn];

    __syncthreads();

    {
        float s   = g_q[b * NPOS + m0 + t] * 0.03125f;   // 1/sqrt(1024)
        float rm  = (s >= 0.f) ? s * g_kmax[b] : s * g_kmin[b];
        float sL  = s * L2E;
        float rmL = rm * L2E;
        float p0 = 0.f, p1 = 0.f, p2 = 0.f, p3 = 0.f;
        #pragma unroll 4
        for (int n = 0; n < 1024; n += 4) {
            p0 += ex2f(fmaf(sL, ks[n + 0], -rmL));
            p1 += ex2f(fmaf(sL, ks[n + 1], -rmL));
            p2 += ex2f(fmaf(sL, ks[n + 2], -rmL));
            p3 += ex2f(fmaf(sL, ks[n + 3], -rmL));
        }
        float Z = (p0 + p1) + (p2 + p3);
        sLs[t]  = sL;
        offs[t] = -rmL - lg2f(Z);
    }
    __syncthreads();

    int mbase = w * 32;
    float sl[4], of[4];
    #pragma unroll
    for (int nt = 0; nt < 4; nt++) {
        int mm = mbase + nt * 8 + g;
        sl[nt] = sLs[mm];
        of[nt] = offs[mm];
    }

    float acc[4][4][4];
    #pragma unroll
    for (int ct = 0; ct < 4; ct++)
        #pragma unroll
        for (int nt = 0; nt < 4; nt++)
            #pragma unroll
            for (int u = 0; u < 4; u++) acc[ct][nt][u] = 0.f;

    for (int ch = 0; ch < 16; ch++) {
        int nn0 = ch * 64;
        __syncthreads();
        #pragma unroll
        for (int s = 0; s < 16; s++)
            pvs[(pv_c + s * 4) * 68 + pv_nn] = tf32r(pvf[s]);
        if (ch < 15) {
            int nb2 = nn0 + 64;
            #pragma unroll
            for (int s = 0; s < 16; s++)
                pvf[s] = g_pv[((size_t)b * 64 + (pv_c + s * 4)) * NPOS + nb2 + pv_nn];
        }
        __syncthreads();

        #pragma unroll
        for (int ks8 = 0; ks8 < 8; ks8++) {
            int kk = ks8 * 8 + tg;
            float k0v = ks[nn0 + kk];
            float k4v = ks[nn0 + kk + 4];

            uint32_t afr[4][4];
            #pragma unroll
            for (int ct = 0; ct < 4; ct++) {
                const uint32_t* ap = &pvs[(ct * 16 + g) * 68 + kk];
                afr[ct][0] = ap[0];
                afr[ct][1] = ap[8 * 68];
                afr[ct][2] = ap[4];
                afr[ct][3] = ap[8 * 68 + 4];
            }

            #pragma unroll
            for (int nt = 0; nt < 4; nt++) {
                float e0 = ex2f(fmaf(sl[nt], k0v, of[nt]));
                float e4 = ex2f(fmaf(sl[nt], k4v, of[nt]));
                int ml = mbase + nt * 8 + g;
                es[ml * 68 + kk]     = e0;
                es[ml * 68 + kk + 4] = e4;
                uint32_t b0 = tf32r(e0);
                uint32_t b1 = tf32r(e4);
                #pragma unroll
                for (int ct = 0; ct < 4; ct++)
                    mma_tf32(acc[ct][nt][0], acc[ct][nt][1], acc[ct][nt][2], acc[ct][nt][3],
                             afr[ct][0], afr[ct][1], afr[ct][2], afr[ct][3],
                             b0, b1);
            }
        }

        if (has_attn) {
            __syncwarp();
            float* dst = attn_out + ((size_t)(b * 1024 + m0 + mbase)) * 1024 + nn0 + 2 * l;
            #pragma unroll 8
            for (int r2 = 0; r2 < 32; r2++) {
                float2 val = *reinterpret_cast<const float2*>(&es[(mbase + r2) * 68 + 2 * l]);
                *reinterpret_cast<float2*>(dst + (size_t)r2 * 1024) = val;
            }
        }
    }

    // ---- Epilogue 1: out D-frags -> smem (tf32 bits), layout outS[m][c] ----
    __syncwarp();
    #pragma unroll
    for (int ct = 0; ct < 4; ct++) {
        #pragma unroll
        for (int nt = 0; nt < 4; nt++) {
            int ml = mbase + nt * 8 + 2 * tg;
            int c  = ct * 16 + g;
            outS[ml * 68 + c]           = tf32r(acc[ct][nt][0]);
            outS[(ml + 1) * 68 + c]     = tf32r(acc[ct][nt][1]);
            outS[ml * 68 + c + 8]       = tf32r(acc[ct][nt][2]);
            outS[(ml + 1) * 68 + c + 8] = tf32r(acc[ct][nt][3]);
        }
    }
    __syncthreads();

    // ---- Epilogue 2: up-GEMM ----
    #pragma unroll
    for (int dtl = 0; dtl < 2; dtl++) {
        int dt = w * 2 + dtl;
        uint32_t af[8][4];
        #pragma unroll
        for (int k8 = 0; k8 < 8; k8++) {
            const uint32_t* ap = &g_wuT[(dt * 16 + g) * 64 + k8 * 8 + tg];
            af[k8][0] = ap[0];
            af[k8][1] = ap[8 * 64];
            af[k8][2] = ap[4];
            af[k8][3] = ap[8 * 64 + 4];
        }
        int dab0 = dt * 16 + g;
        int dab1 = dab0 + 8;
        int dd0 = dab0 >> 2, aa0 = (dab0 >> 1) & 1, bb0 = dab0 & 1;
        int dd1 = dab1 >> 2, aa1 = (dab1 >> 1) & 1, bb1 = dab1 & 1;
        float bud0 = __ldg(&bu[dd0]);
        float bud1 = __ldg(&bu[dd1]);

        for (int mt2 = 0; mt2 < 32; mt2++) {
            float e0 = 0.f, e1 = 0.f, e2 = 0.f, e3 = 0.f;
            #pragma unroll
            for (int k8 = 0; k8 < 8; k8++) {
                const uint32_t* bp = &outS[(mt2 * 8 + g) * 68 + k8 * 8 + tg];
                mma_tf32(e0, e1, e2, e3,
                         af[k8][0], af[k8][1], af[k8][2], af[k8][3],
                         bp[0], bp[4]);
            }
            int mg = m0 + mt2 * 8 + 2 * tg;
            int i = mg >> 5, j = mg & 31;
            size_t a0 = (((size_t)(b * 64 + dd0)) * 64 + 2 * i + aa0) * 64 + 2 * j + bb0;
            size_t a1 = (((size_t)(b * 64 + dd1)) * 64 + 2 * i + aa1) * 64 + 2 * j + bb1;
            up[a0]     = e0 + bud0;
            up[a0 + 2] = e1 + bud0;
            up[a1]     = e2 + bud1;
            up[a1 + 2] = e3 + bud1;
        }
    }
}

// ---------------------------------------------------------------------------
extern "C" void kernel_launch(void* const* d_in, const int* in_sizes, int n_in,
                              void* d_out, int out_size) {
    const float* x     = (const float*)d_in[0];
    const float* v     = (const float*)d_in[1];
    const float* wq    = (const float*)d_in[2];
    const float* bq    = (const float*)d_in[3];
    const float* wk    = (const float*)d_in[4];
    const float* bk    = (const float*)d_in[5];
    const float* wv    = (const float*)d_in[6];
    const float* bv    = (const float*)d_in[7];
    const float* wu    = (const float*)d_in[8];
    const float* bu    = (const float*)d_in[9];
    const float* wproj = (const float*)d_in[10];
    const float* bproj = (const float*)d_in[11];

    float* up_out   = (float*)d_out;
    int has_attn    = (out_size > UP_ELEMS) ? 1 : 0;
    float* attn_out = up_out + UP_ELEMS;

    cudaFuncSetAttribute(kproj_part_kernel, cudaFuncAttributeMaxDynamicSharedMemorySize, 65024);
    cudaFuncSetAttribute(conv_x_kernel,     cudaFuncAttributeMaxDynamicSharedMemorySize, 28800);
    cudaFuncSetAttribute(attn_kernel,       cudaFuncAttributeMaxDynamicSharedMemorySize, 93184);

    conv_v_kernel<<<dim3(42, 64), 256>>>(v, wk, bk, wu);
    kproj_part_kernel<<<dim3(16, 9), 256, 65024>>>(wproj);
    kreduce_kernel<<<64, 256>>>(bproj);
    conv_x_kernel<<<dim3(8, 64), 256, 28800>>>(x, wq, bq, wv, bv);
    attn_kernel<<<dim3(4, 64), 256, 93184>>>(attn_out, has_attn, bu, up_out);
}